// round 5
// baseline (speedup 1.0000x reference)
#include <cuda_runtime.h>
#include <cstdint>

#define L_SEQ 2048
#define BATCH 2
#define DMODEL 1024
#define NHEAD 16
#define DHEAD 64
#define DFF 3072
#define MTOT (BATCH * L_SEQ) /* 4096 */

// -------- scratch (device globals: allocation-free rule) --------
__device__ float g_xn[MTOT * DMODEL];
__device__ float g_qkv[MTOT * 3 * DMODEL];
__device__ float g_o[MTOT * DMODEL];
__device__ float g_u[MTOT * 2 * DFF];

__device__ __forceinline__ unsigned f2tf32(float f) {
    unsigned r;
    asm("cvt.rna.tf32.f32 %0, %1;" : "=r"(r) : "f"(f));
    return r;
}

// FFMA-only 2^y (no MUFU).
__device__ __forceinline__ float fexp2(float y) {
    y = fmaxf(fminf(y, 120.f), -120.f);
    float z = y + 12582912.f;                 // 1.5*2^23
    int n = __float_as_int(z) - 0x4B400000;   // round(y)
    float f = y - (z - 12582912.f);           // y - n in [-0.5, 0.5]
    float p = 0.0013333558f;
    p = fmaf(p, f, 0.0096181291f);
    p = fmaf(p, f, 0.0555041087f);
    p = fmaf(p, f, 0.2402265070f);
    p = fmaf(p, f, 0.6931471806f);
    p = fmaf(p, f, 1.0f);
    return __int_as_float((n + 127) << 23) * p;
}
#define L2E 1.4426950408889634f

__device__ __forceinline__ float fsilu(float g) {
    return g / (1.f + fexp2(-g * L2E));
}

// ---------------- RMSNorm ----------------
__global__ void __launch_bounds__(256) rmsnorm_kernel(const float* __restrict__ x,
                                                      const float* __restrict__ scale,
                                                      float* __restrict__ out)
{
    int row = blockIdx.x;
    int t = threadIdx.x;
    const float4* xr = reinterpret_cast<const float4*>(x) + (size_t)row * (DMODEL / 4);
    float4 v = xr[t];
    float ss = v.x * v.x + v.y * v.y + v.z * v.z + v.w * v.w;
#pragma unroll
    for (int o = 16; o; o >>= 1) ss += __shfl_xor_sync(0xffffffffu, ss, o);
    __shared__ float ws[8];
    if ((t & 31) == 0) ws[t >> 5] = ss;
    __syncthreads();
    float tot = 0.f;
#pragma unroll
    for (int i = 0; i < 8; i++) tot += ws[i];
    float inv = rsqrtf(tot * (1.0f / DMODEL) + 1e-6f);
    float4 s = reinterpret_cast<const float4*>(scale)[t];
    float4 r;
    r.x = v.x * s.x * inv;
    r.y = v.y * s.y * inv;
    r.z = v.z * s.z * inv;
    r.w = v.w * s.w * inv;
    (reinterpret_cast<float4*>(out) + (size_t)row * (DMODEL / 4))[t] = r;
}

// ---------------- TF32 tensor-core GEMM NT, templated N-tile ----------------
// C[m,n] = sum_k A'[m,k]*B[n,k] (+resid), A' = silu-fused u if FUSE.
// Block 128 x BN, 8 warps (2x4), warp tile 64 x (BN/4), BK=16, m16n8k8 tf32.
#define BKK 16
template<int BN, bool FUSE>
__global__ void __launch_bounds__(256, (BN == 128) ? 2 : 1)
gemm_tf32_kernel(const float* __restrict__ A,
                 const float* __restrict__ B,
                 const float* resid,
                 float* __restrict__ C,
                 int N, int K)
{
    constexpr int WN = BN / 4;     // warp n width: 32 or 64
    constexpr int NI = WN / 8;     // 4 or 8
    constexpr int LDB = BN + 8;    // 136 or 264; %32==8 -> conflict-free frag reads
    __shared__ unsigned As[BKK][136];
    __shared__ unsigned Bs[BKK][LDB];
    int tid = threadIdx.x;
    int warp = tid >> 5, lane = tid & 31;
    int g = lane >> 2, t = lane & 3;
    int m0 = blockIdx.y * 128, n0 = blockIdx.x * BN;
    int wm = (warp >> 2) * 64;
    int wn = (warp & 3) * WN;

    // A loader: row lm = tid>>1, k offset lk = (tid&1)*8, 2 float4
    int lm = tid >> 1;
    int lk = (tid & 1) * 8;
    const size_t astr = FUSE ? (size_t)(2 * DFF) : (size_t)K;
    const float* Ap = A + (size_t)(m0 + lm) * astr + lk;

    float acc[4][NI][4] = {};

    float4 a0, a1, ga0, ga1;
    float4 b0, b1, b2, b3;

    // initial prefetch
    a0 = *reinterpret_cast<const float4*>(Ap);
    a1 = *reinterpret_cast<const float4*>(Ap + 4);
    if (FUSE) {
        ga0 = *reinterpret_cast<const float4*>(Ap + DFF);
        ga1 = *reinterpret_cast<const float4*>(Ap + DFF + 4);
    }
    if (BN == 128) {
        const float* Bp = B + (size_t)(n0 + lm) * K + lk;
        b0 = *reinterpret_cast<const float4*>(Bp);
        b1 = *reinterpret_cast<const float4*>(Bp + 4);
    } else {
        const float* Bp = B + (size_t)(n0 + tid) * K;
        b0 = *reinterpret_cast<const float4*>(Bp);
        b1 = *reinterpret_cast<const float4*>(Bp + 4);
        b2 = *reinterpret_cast<const float4*>(Bp + 8);
        b3 = *reinterpret_cast<const float4*>(Bp + 12);
    }

    for (int kt = 0; kt < K; kt += BKK) {
        // ---- store staged tiles to smem ----
        {
            float av[8] = {a0.x, a0.y, a0.z, a0.w, a1.x, a1.y, a1.z, a1.w};
            if (FUSE) {
                float gv[8] = {ga0.x, ga0.y, ga0.z, ga0.w, ga1.x, ga1.y, ga1.z, ga1.w};
#pragma unroll
                for (int i = 0; i < 8; i++) av[i] *= fsilu(gv[i]);
            }
#pragma unroll
            for (int i = 0; i < 8; i++) As[lk + i][lm] = f2tf32(av[i]);
        }
        if (BN == 128) {
            float bv[8] = {b0.x, b0.y, b0.z, b0.w, b1.x, b1.y, b1.z, b1.w};
#pragma unroll
            for (int i = 0; i < 8; i++) Bs[lk + i][lm] = f2tf32(bv[i]);
        } else {
            float bv[16] = {b0.x, b0.y, b0.z, b0.w, b1.x, b1.y, b1.z, b1.w,
                            b2.x, b2.y, b2.z, b2.w, b3.x, b3.y, b3.z, b3.w};
#pragma unroll
            for (int i = 0; i < 16; i++) Bs[i][tid] = f2tf32(bv[i]);
        }
        __syncthreads();

        // ---- prefetch next tile into registers ----
        if (kt + BKK < K) {
            a0 = *reinterpret_cast<const float4*>(Ap + kt + BKK);
            a1 = *reinterpret_cast<const float4*>(Ap + kt + BKK + 4);
            if (FUSE) {
                ga0 = *reinterpret_cast<const float4*>(Ap + DFF + kt + BKK);
                ga1 = *reinterpret_cast<const float4*>(Ap + DFF + kt + BKK + 4);
            }
            if (BN == 128) {
                const float* Bp = B + (size_t)(n0 + lm) * K + lk + kt + BKK;
                b0 = *reinterpret_cast<const float4*>(Bp);
                b1 = *reinterpret_cast<const float4*>(Bp + 4);
            } else {
                const float* Bp = B + (size_t)(n0 + tid) * K + kt + BKK;
                b0 = *reinterpret_cast<const float4*>(Bp);
                b1 = *reinterpret_cast<const float4*>(Bp + 4);
                b2 = *reinterpret_cast<const float4*>(Bp + 8);
                b3 = *reinterpret_cast<const float4*>(Bp + 12);
            }
        }

        // ---- compute ----
#pragma unroll
        for (int ks = 0; ks < BKK; ks += 8) {
            unsigned af[4][4], bf[NI][2];
#pragma unroll
            for (int mi = 0; mi < 4; mi++) {
                int mr = wm + mi * 16 + g;
                af[mi][0] = As[ks + t][mr];
                af[mi][1] = As[ks + t][mr + 8];
                af[mi][2] = As[ks + t + 4][mr];
                af[mi][3] = As[ks + t + 4][mr + 8];
            }
#pragma unroll
            for (int ni = 0; ni < NI; ni++) {
                int nc = wn + ni * 8 + g;
                bf[ni][0] = Bs[ks + t][nc];
                bf[ni][1] = Bs[ks + t + 4][nc];
            }
#pragma unroll
            for (int mi = 0; mi < 4; mi++)
#pragma unroll
                for (int ni = 0; ni < NI; ni++) {
                    asm volatile(
                        "mma.sync.aligned.m16n8k8.row.col.f32.tf32.tf32.f32 "
                        "{%0,%1,%2,%3}, {%4,%5,%6,%7}, {%8,%9}, {%0,%1,%2,%3};"
                        : "+f"(acc[mi][ni][0]), "+f"(acc[mi][ni][1]),
                          "+f"(acc[mi][ni][2]), "+f"(acc[mi][ni][3])
                        : "r"(af[mi][0]), "r"(af[mi][1]), "r"(af[mi][2]), "r"(af[mi][3]),
                          "r"(bf[ni][0]), "r"(bf[ni][1]));
                }
        }
        __syncthreads();
    }

#pragma unroll
    for (int mi = 0; mi < 4; mi++) {
#pragma unroll
        for (int ni = 0; ni < NI; ni++) {
            int row0 = m0 + wm + mi * 16 + g;
            int col = n0 + wn + ni * 8 + 2 * t;
            size_t i0 = (size_t)row0 * N + col;
            size_t i1 = (size_t)(row0 + 8) * N + col;
            float2 v01 = make_float2(acc[mi][ni][0], acc[mi][ni][1]);
            float2 v23 = make_float2(acc[mi][ni][2], acc[mi][ni][3]);
            if (resid) {
                float2 r0 = *reinterpret_cast<const float2*>(resid + i0);
                float2 r1 = *reinterpret_cast<const float2*>(resid + i1);
                v01.x += r0.x; v01.y += r0.y;
                v23.x += r1.x; v23.y += r1.y;
            }
            *reinterpret_cast<float2*>(C + i0) = v01;
            *reinterpret_cast<float2*>(C + i1) = v23;
        }
    }
}

// ---------------- QK cosine norm ----------------
__global__ void __launch_bounds__(256) qknorm_kernel(float* __restrict__ qkv,
                                                     const float* __restrict__ attn_scale)
{
    int warp = blockIdx.x * (blockDim.x >> 5) + (threadIdx.x >> 5);
    int lane = threadIdx.x & 31;
    int m = warp >> 5;
    int rest = warp & 31;
    int part = rest >> 4;
    int h = rest & 15;
    size_t base = (size_t)m * 3072 + part * 1024 + h * 64;
    float2 v = *reinterpret_cast<float2*>(qkv + base + lane * 2);
    float ss = v.x * v.x + v.y * v.y;
#pragma unroll
    for (int o = 16; o; o >>= 1) ss += __shfl_xor_sync(0xffffffffu, ss, o);
    float f = sqrtf(attn_scale[h]) * rsqrtf(ss + 1e-6f);
    v.x *= f;
    v.y *= f;
    *reinterpret_cast<float2*>(qkv + base + lane * 2) = v;
}

// ---------------- Tensor-core flash attention (unchanged from R3) ----------------
__global__ void __launch_bounds__(128) attention_tc_kernel(const float* __restrict__ qkv,
                                                           float* __restrict__ o)
{
    __shared__ __align__(16) char qk_raw[64 * 68 * 4];
    float (*Qs)[68] = reinterpret_cast<float(*)[68]>(qk_raw);
    unsigned (*KsB)[68] = reinterpret_cast<unsigned(*)[68]>(qk_raw);
    unsigned (*KsS)[68] = reinterpret_cast<unsigned(*)[68]>(qk_raw + 32 * 68 * 4);
    __shared__ unsigned Vs[32][72];
    __shared__ unsigned Ps[64][36];

    int tid = threadIdx.x;
    int warp = tid >> 5, lane = tid & 31;
    int g = lane >> 2, t = lane & 3;
    int wm = warp * 16;
    int q0 = blockIdx.x * 64;
    int h = blockIdx.y, b = blockIdx.z;
    const float* qbase = qkv + (size_t)b * L_SEQ * 3072 + h * 64;
    const float* kbase = qbase + 1024;
    const float* vbase = qbase + 2048;

#pragma unroll
    for (int j = 0; j < 8; j++) {
        int idx = tid + 128 * j;
        int r = idx >> 4, seg = idx & 15;
        float4 v = *reinterpret_cast<const float4*>(qbase + (size_t)(q0 + r) * 3072 + seg * 4);
        *reinterpret_cast<float4*>(&Qs[r][seg * 4]) = v;
    }
    __syncthreads();

    unsigned qb[32], qs[32];
#pragma unroll
    for (int k0 = 0; k0 < 8; k0++) {
        float qa[4];
        qa[0] = Qs[wm + g][k0 * 8 + t];
        qa[1] = Qs[wm + g + 8][k0 * 8 + t];
        qa[2] = Qs[wm + g][k0 * 8 + t + 4];
        qa[3] = Qs[wm + g + 8][k0 * 8 + t + 4];
#pragma unroll
        for (int i = 0; i < 4; i++) {
            unsigned big = f2tf32(qa[i]);
            qb[k0 * 4 + i] = big;
            qs[k0 * 4 + i] = f2tf32(qa[i] - __uint_as_float(big));
        }
    }

    float oacc[8][4] = {};
    float mrow[2] = {-1e30f, -1e30f};
    float lrow[2] = {0.f, 0.f};

    for (int kb = 0; kb < L_SEQ / 32; kb++) {
        __syncthreads();
#pragma unroll
        for (int j = 0; j < 4; j++) {
            int idx = tid + 128 * j;
            int r = idx >> 4, seg = idx & 15;
            size_t moff = (size_t)(kb * 32 + r) * 3072 + seg * 4;
            float4 k4 = *reinterpret_cast<const float4*>(kbase + moff);
            unsigned b0 = f2tf32(k4.x), b1 = f2tf32(k4.y);
            unsigned b2 = f2tf32(k4.z), b3 = f2tf32(k4.w);
            KsB[r][seg * 4 + 0] = b0; KsB[r][seg * 4 + 1] = b1;
            KsB[r][seg * 4 + 2] = b2; KsB[r][seg * 4 + 3] = b3;
            KsS[r][seg * 4 + 0] = f2tf32(k4.x - __uint_as_float(b0));
            KsS[r][seg * 4 + 1] = f2tf32(k4.y - __uint_as_float(b1));
            KsS[r][seg * 4 + 2] = f2tf32(k4.z - __uint_as_float(b2));
            KsS[r][seg * 4 + 3] = f2tf32(k4.w - __uint_as_float(b3));
            float4 v4 = *reinterpret_cast<const float4*>(vbase + moff);
            uint4 u;
            u.x = f2tf32(v4.x); u.y = f2tf32(v4.y);
            u.z = f2tf32(v4.z); u.w = f2tf32(v4.w);
            *reinterpret_cast<uint4*>(&Vs[r][seg * 4]) = u;
        }
        __syncthreads();

        float sacc[4][4] = {};
#pragma unroll
        for (int k0 = 0; k0 < 8; k0++) {
            const unsigned* qbp = qb + k0 * 4;
            const unsigned* qsp = qs + k0 * 4;
#pragma unroll
            for (int ni = 0; ni < 4; ni++) {
                unsigned kb0 = KsB[ni * 8 + g][k0 * 8 + t];
                unsigned kb1 = KsB[ni * 8 + g][k0 * 8 + t + 4];
                unsigned ks0 = KsS[ni * 8 + g][k0 * 8 + t];
                unsigned ks1 = KsS[ni * 8 + g][k0 * 8 + t + 4];
#define MMA_S(A0,A1,A2,A3,B0,B1) \
                asm volatile("mma.sync.aligned.m16n8k8.row.col.f32.tf32.tf32.f32 " \
                    "{%0,%1,%2,%3}, {%4,%5,%6,%7}, {%8,%9}, {%0,%1,%2,%3};" \
                    : "+f"(sacc[ni][0]), "+f"(sacc[ni][1]), "+f"(sacc[ni][2]), "+f"(sacc[ni][3]) \
                    : "r"(A0), "r"(A1), "r"(A2), "r"(A3), "r"(B0), "r"(B1))
                MMA_S(qbp[0], qbp[1], qbp[2], qbp[3], kb0, kb1);
                MMA_S(qbp[0], qbp[1], qbp[2], qbp[3], ks0, ks1);
                MMA_S(qsp[0], qsp[1], qsp[2], qsp[3], kb0, kb1);
#undef MMA_S
            }
        }

        float ml0 = -1e30f, ml1 = -1e30f;
#pragma unroll
        for (int ni = 0; ni < 4; ni++) {
            ml0 = fmaxf(ml0, fmaxf(sacc[ni][0], sacc[ni][1]));
            ml1 = fmaxf(ml1, fmaxf(sacc[ni][2], sacc[ni][3]));
        }
#pragma unroll
        for (int off = 1; off < 4; off <<= 1) {
            ml0 = fmaxf(ml0, __shfl_xor_sync(0xffffffffu, ml0, off));
            ml1 = fmaxf(ml1, __shfl_xor_sync(0xffffffffu, ml1, off));
        }
        float mn0 = fmaxf(mrow[0], ml0);
        float mn1 = fmaxf(mrow[1], ml1);
        float corr0 = fexp2((mrow[0] - mn0) * L2E);
        float corr1 = fexp2((mrow[1] - mn1) * L2E);
        mrow[0] = mn0; mrow[1] = mn1;

        float rs0 = 0.f, rs1 = 0.f;
#pragma unroll
        for (int ni = 0; ni < 4; ni++) {
            float p0 = fexp2((sacc[ni][0] - mn0) * L2E);
            float p1 = fexp2((sacc[ni][1] - mn0) * L2E);
            float p2 = fexp2((sacc[ni][2] - mn1) * L2E);
            float p3 = fexp2((sacc[ni][3] - mn1) * L2E);
            rs0 += p0 + p1;
            rs1 += p2 + p3;
            Ps[wm + g][ni * 8 + 2 * t] = f2tf32(p0);
            Ps[wm + g][ni * 8 + 2 * t + 1] = f2tf32(p1);
            Ps[wm + g + 8][ni * 8 + 2 * t] = f2tf32(p2);
            Ps[wm + g + 8][ni * 8 + 2 * t + 1] = f2tf32(p3);
        }
#pragma unroll
        for (int off = 1; off < 4; off <<= 1) {
            rs0 += __shfl_xor_sync(0xffffffffu, rs0, off);
            rs1 += __shfl_xor_sync(0xffffffffu, rs1, off);
        }
        lrow[0] = lrow[0] * corr0 + rs0;
        lrow[1] = lrow[1] * corr1 + rs1;
#pragma unroll
        for (int ni = 0; ni < 8; ni++) {
            oacc[ni][0] *= corr0; oacc[ni][1] *= corr0;
            oacc[ni][2] *= corr1; oacc[ni][3] *= corr1;
        }
        __syncwarp();

#pragma unroll
        for (int k0 = 0; k0 < 32; k0 += 8) {
            unsigned pa0 = Ps[wm + g][k0 + t];
            unsigned pa1 = Ps[wm + g + 8][k0 + t];
            unsigned pa2 = Ps[wm + g][k0 + t + 4];
            unsigned pa3 = Ps[wm + g + 8][k0 + t + 4];
#pragma unroll
            for (int ni = 0; ni < 8; ni++) {
                unsigned vb0 = Vs[k0 + t][ni * 8 + g];
                unsigned vb1 = Vs[k0 + t + 4][ni * 8 + g];
                asm volatile("mma.sync.aligned.m16n8k8.row.col.f32.tf32.tf32.f32 "
                    "{%0,%1,%2,%3}, {%4,%5,%6,%7}, {%8,%9}, {%0,%1,%2,%3};"
                    : "+f"(oacc[ni][0]), "+f"(oacc[ni][1]), "+f"(oacc[ni][2]), "+f"(oacc[ni][3])
                    : "r"(pa0), "r"(pa1), "r"(pa2), "r"(pa3), "r"(vb0), "r"(vb1));
            }
        }
        __syncwarp();
    }

    float inv0 = 1.0f / lrow[0];
    float inv1 = 1.0f / lrow[1];
    int row0 = b * L_SEQ + q0 + wm + g;
    int row1 = row0 + 8;
#pragma unroll
    for (int ni = 0; ni < 8; ni++) {
        int col = h * 64 + ni * 8 + 2 * t;
        float2 r0 = make_float2(oacc[ni][0] * inv0, oacc[ni][1] * inv0);
        float2 r1 = make_float2(oacc[ni][2] * inv1, oacc[ni][3] * inv1);
        *reinterpret_cast<float2*>(o + (size_t)row0 * DMODEL + col) = r0;
        *reinterpret_cast<float2*>(o + (size_t)row1 * DMODEL + col) = r1;
    }
}

extern "C" void kernel_launch(void* const* d_in, const int* in_sizes, int n_in,
                              void* d_out, int out_size)
{
    const float* x          = (const float*)d_in[0];
    const float* norm_scale = (const float*)d_in[2];
    const float* w_qkv      = (const float*)d_in[3];
    const float* attn_scale = (const float*)d_in[4];
    const float* w_out      = (const float*)d_in[5];
    const float* ff_scale   = (const float*)d_in[6];
    const float* w_up       = (const float*)d_in[7];
    const float* w_down     = (const float*)d_in[8];
    float* out = (float*)d_out;

    float *xn, *qkvp, *op, *up;
    cudaGetSymbolAddress((void**)&xn, g_xn);
    cudaGetSymbolAddress((void**)&qkvp, g_qkv);
    cudaGetSymbolAddress((void**)&op, g_o);
    cudaGetSymbolAddress((void**)&up, g_u);

    // 1) xn = rmsnorm(x)
    rmsnorm_kernel<<<MTOT, 256>>>(x, norm_scale, xn);
    // 2) qkv = xn @ w_qkv^T  [4096 x 3072], 128x256 tiles
    gemm_tf32_kernel<256, false><<<dim3(3 * DMODEL / 256, MTOT / 128), 256>>>(
        xn, w_qkv, nullptr, qkvp, 3 * DMODEL, DMODEL);
    // 3) q,k cosine norm
    qknorm_kernel<<<MTOT * 32 / 8, 256>>>(qkvp, attn_scale);
    // 4) attention -> o
    attention_tc_kernel<<<dim3(L_SEQ / 64, NHEAD, BATCH), 128>>>(qkvp, op);
    // 5) x1 = o @ w_out^T + x  [4096 x 1024], 128x128 tiles
    gemm_tf32_kernel<128, false><<<dim3(DMODEL / 128, MTOT / 128), 256>>>(
        op, w_out, x, out, DMODEL, DMODEL);
    // 6) xn = rmsnorm(x1)
    rmsnorm_kernel<<<MTOT, 256>>>(out, ff_scale, xn);
    // 7) u = xn @ w_up^T  [4096 x 6144], 128x256 tiles
    gemm_tf32_kernel<256, false><<<dim3(2 * DFF / 256, MTOT / 128), 256>>>(
        xn, w_up, nullptr, up, 2 * DFF, DMODEL);
    // 8+9) out = swiglu(u) @ w_down^T + x1  (silu fused into A-loader)
    gemm_tf32_kernel<128, true><<<dim3(DMODEL / 128, MTOT / 128), 256>>>(
        up, w_down, out, out, DMODEL, DFF);
}

// round 6
// speedup vs baseline: 1.0682x; 1.0682x over previous
#include <cuda_runtime.h>
#include <cstdint>

#define L_SEQ 2048
#define BATCH 2
#define DMODEL 1024
#define NHEAD 16
#define DHEAD 64
#define DFF 3072
#define MTOT (BATCH * L_SEQ) /* 4096 */

// -------- scratch (device globals: allocation-free rule) --------
__device__ float g_xn[MTOT * DMODEL];
__device__ float g_qkv[MTOT * 3 * DMODEL];
__device__ float g_o[MTOT * DMODEL];
__device__ float g_u[MTOT * 2 * DFF];

__device__ __forceinline__ unsigned f2tf32(float f) {
    unsigned r;
    asm("cvt.rna.tf32.f32 %0, %1;" : "=r"(r) : "f"(f));
    return r;
}

// FFMA-only 2^y (no MUFU).
__device__ __forceinline__ float fexp2(float y) {
    y = fmaxf(fminf(y, 120.f), -120.f);
    float z = y + 12582912.f;                 // 1.5*2^23
    int n = __float_as_int(z) - 0x4B400000;   // round(y)
    float f = y - (z - 12582912.f);           // y - n in [-0.5, 0.5]
    float p = 0.0013333558f;
    p = fmaf(p, f, 0.0096181291f);
    p = fmaf(p, f, 0.0555041087f);
    p = fmaf(p, f, 0.2402265070f);
    p = fmaf(p, f, 0.6931471806f);
    p = fmaf(p, f, 1.0f);
    return __int_as_float((n + 127) << 23) * p;
}
#define L2E 1.4426950408889634f

__device__ __forceinline__ float fsilu(float g) {
    return g / (1.f + fexp2(-g * L2E));
}

// ---------------- RMSNorm ----------------
__global__ void __launch_bounds__(256) rmsnorm_kernel(const float* __restrict__ x,
                                                      const float* __restrict__ scale,
                                                      float* __restrict__ out)
{
    int row = blockIdx.x;
    int t = threadIdx.x;
    const float4* xr = reinterpret_cast<const float4*>(x) + (size_t)row * (DMODEL / 4);
    float4 v = xr[t];
    float ss = v.x * v.x + v.y * v.y + v.z * v.z + v.w * v.w;
#pragma unroll
    for (int o = 16; o; o >>= 1) ss += __shfl_xor_sync(0xffffffffu, ss, o);
    __shared__ float ws[8];
    if ((t & 31) == 0) ws[t >> 5] = ss;
    __syncthreads();
    float tot = 0.f;
#pragma unroll
    for (int i = 0; i < 8; i++) tot += ws[i];
    float inv = rsqrtf(tot * (1.0f / DMODEL) + 1e-6f);
    float4 s = reinterpret_cast<const float4*>(scale)[t];
    float4 r;
    r.x = v.x * s.x * inv;
    r.y = v.y * s.y * inv;
    r.z = v.z * s.z * inv;
    r.w = v.w * s.w * inv;
    (reinterpret_cast<float4*>(out) + (size_t)row * (DMODEL / 4))[t] = r;
}

// ---------------- TF32 tensor-core GEMM NT (R3-proven 128x128 shape) ----------------
// C[m,n] = sum_k A'[m,k]*B[n,k] (+resid); A' = u_a * silu(u_g) if FUSE.
#define BKK 16
#define LDP 136
template<bool FUSE>
__global__ void __launch_bounds__(256, 2) gemm_tf32_kernel(const float* __restrict__ A,
                                                           const float* __restrict__ B,
                                                           const float* resid,
                                                           float* __restrict__ C,
                                                           int N, int K)
{
    __shared__ unsigned As[BKK][LDP];
    __shared__ unsigned Bs[BKK][LDP];
    int tid = threadIdx.x;
    int warp = tid >> 5, lane = tid & 31;
    int g = lane >> 2, t = lane & 3;
    int m0 = blockIdx.y * 128, n0 = blockIdx.x * 128;
    int wm = (warp >> 2) * 64;
    int wn = (warp & 3) * 32;

    int lm = tid >> 1;
    int lk = (tid & 1) * 8;
    const size_t astr = FUSE ? (size_t)(2 * DFF) : (size_t)K;
    const float* Ap = A + (size_t)(m0 + lm) * astr + lk;
    const float* Bp = B + (size_t)(n0 + lm) * K + lk;

    float acc[4][4][4] = {};

    float4 a0 = *reinterpret_cast<const float4*>(Ap);
    float4 a1 = *reinterpret_cast<const float4*>(Ap + 4);
    float4 ga0, ga1;
    if (FUSE) {
        ga0 = *reinterpret_cast<const float4*>(Ap + DFF);
        ga1 = *reinterpret_cast<const float4*>(Ap + DFF + 4);
    }
    float4 b0 = *reinterpret_cast<const float4*>(Bp);
    float4 b1 = *reinterpret_cast<const float4*>(Bp + 4);

    for (int kt = 0; kt < K; kt += BKK) {
        {
            float av[8] = {a0.x, a0.y, a0.z, a0.w, a1.x, a1.y, a1.z, a1.w};
            if (FUSE) {
                float gv[8] = {ga0.x, ga0.y, ga0.z, ga0.w, ga1.x, ga1.y, ga1.z, ga1.w};
#pragma unroll
                for (int i = 0; i < 8; i++) av[i] *= fsilu(gv[i]);
            }
#pragma unroll
            for (int i = 0; i < 8; i++) As[lk + i][lm] = f2tf32(av[i]);
        }
        Bs[lk + 0][lm] = f2tf32(b0.x); Bs[lk + 1][lm] = f2tf32(b0.y);
        Bs[lk + 2][lm] = f2tf32(b0.z); Bs[lk + 3][lm] = f2tf32(b0.w);
        Bs[lk + 4][lm] = f2tf32(b1.x); Bs[lk + 5][lm] = f2tf32(b1.y);
        Bs[lk + 6][lm] = f2tf32(b1.z); Bs[lk + 7][lm] = f2tf32(b1.w);
        __syncthreads();
        if (kt + BKK < K) {
            a0 = *reinterpret_cast<const float4*>(Ap + kt + BKK);
            a1 = *reinterpret_cast<const float4*>(Ap + kt + BKK + 4);
            if (FUSE) {
                ga0 = *reinterpret_cast<const float4*>(Ap + DFF + kt + BKK);
                ga1 = *reinterpret_cast<const float4*>(Ap + DFF + kt + BKK + 4);
            }
            b0 = *reinterpret_cast<const float4*>(Bp + kt + BKK);
            b1 = *reinterpret_cast<const float4*>(Bp + kt + BKK + 4);
        }
#pragma unroll
        for (int ks = 0; ks < BKK; ks += 8) {
            unsigned af[4][4], bf[4][2];
#pragma unroll
            for (int mi = 0; mi < 4; mi++) {
                int mr = wm + mi * 16 + g;
                af[mi][0] = As[ks + t][mr];
                af[mi][1] = As[ks + t][mr + 8];
                af[mi][2] = As[ks + t + 4][mr];
                af[mi][3] = As[ks + t + 4][mr + 8];
            }
#pragma unroll
            for (int ni = 0; ni < 4; ni++) {
                int nc = wn + ni * 8 + g;
                bf[ni][0] = Bs[ks + t][nc];
                bf[ni][1] = Bs[ks + t + 4][nc];
            }
#pragma unroll
            for (int mi = 0; mi < 4; mi++)
#pragma unroll
                for (int ni = 0; ni < 4; ni++) {
                    asm volatile(
                        "mma.sync.aligned.m16n8k8.row.col.f32.tf32.tf32.f32 "
                        "{%0,%1,%2,%3}, {%4,%5,%6,%7}, {%8,%9}, {%0,%1,%2,%3};"
                        : "+f"(acc[mi][ni][0]), "+f"(acc[mi][ni][1]),
                          "+f"(acc[mi][ni][2]), "+f"(acc[mi][ni][3])
                        : "r"(af[mi][0]), "r"(af[mi][1]), "r"(af[mi][2]), "r"(af[mi][3]),
                          "r"(bf[ni][0]), "r"(bf[ni][1]));
                }
        }
        __syncthreads();
    }

#pragma unroll
    for (int mi = 0; mi < 4; mi++) {
#pragma unroll
        for (int ni = 0; ni < 4; ni++) {
            int row0 = m0 + wm + mi * 16 + g;
            int col = n0 + wn + ni * 8 + 2 * t;
            size_t i0 = (size_t)row0 * N + col;
            size_t i1 = (size_t)(row0 + 8) * N + col;
            float2 v01 = make_float2(acc[mi][ni][0], acc[mi][ni][1]);
            float2 v23 = make_float2(acc[mi][ni][2], acc[mi][ni][3]);
            if (resid) {
                float2 r0 = *reinterpret_cast<const float2*>(resid + i0);
                float2 r1 = *reinterpret_cast<const float2*>(resid + i1);
                v01.x += r0.x; v01.y += r0.y;
                v23.x += r1.x; v23.y += r1.y;
            }
            *reinterpret_cast<float2*>(C + i0) = v01;
            *reinterpret_cast<float2*>(C + i1) = v23;
        }
    }
}

// ---------------- QK cosine norm ----------------
__global__ void __launch_bounds__(256) qknorm_kernel(float* __restrict__ qkv,
                                                     const float* __restrict__ attn_scale)
{
    int warp = blockIdx.x * (blockDim.x >> 5) + (threadIdx.x >> 5);
    int lane = threadIdx.x & 31;
    int m = warp >> 5;
    int rest = warp & 31;
    int part = rest >> 4;
    int h = rest & 15;
    size_t base = (size_t)m * 3072 + part * 1024 + h * 64;
    float2 v = *reinterpret_cast<float2*>(qkv + base + lane * 2);
    float ss = v.x * v.x + v.y * v.y;
#pragma unroll
    for (int o = 16; o; o >>= 1) ss += __shfl_xor_sync(0xffffffffu, ss, o);
    float f = sqrtf(attn_scale[h]) * rsqrtf(ss + 1e-6f);
    v.x *= f;
    v.y *= f;
    *reinterpret_cast<float2*>(qkv + base + lane * 2) = v;
}

// ---------------- Tensor-core flash attention v3 ----------------
// Ps smem eliminated: P converted accumulator-layout -> A-fragment-layout via
// intra-quad shuffles. smem 36KB -> 26KB, 3 CTAs/SM target.
__global__ void __launch_bounds__(128, 3) attention_tc_kernel(const float* __restrict__ qkv,
                                                              float* __restrict__ o)
{
    __shared__ __align__(16) char qk_raw[64 * 68 * 4];
    float (*Qs)[68] = reinterpret_cast<float(*)[68]>(qk_raw);
    unsigned (*KsB)[68] = reinterpret_cast<unsigned(*)[68]>(qk_raw);
    unsigned (*KsS)[68] = reinterpret_cast<unsigned(*)[68]>(qk_raw + 32 * 68 * 4);
    __shared__ unsigned Vs[32][72];

    int tid = threadIdx.x;
    int warp = tid >> 5, lane = tid & 31;
    int g = lane >> 2, t = lane & 3;
    int wm = warp * 16;
    int q0 = blockIdx.x * 64;
    int h = blockIdx.y, b = blockIdx.z;
    const float* qbase = qkv + (size_t)b * L_SEQ * 3072 + h * 64;
    const float* kbase = qbase + 1024;
    const float* vbase = qbase + 2048;

    // P layout-conversion shuffle sources (within quad): holder of (row, c) is
    // lane 4g + c/2; needer (g,t) wants c = t (srcA) and c = t+4 (srcB).
    int srcA = (lane & 28) | (t >> 1);
    int srcB = srcA + 2;
    bool odd = (t & 1);

    // stage Q tile 64x64
#pragma unroll
    for (int j = 0; j < 8; j++) {
        int idx = tid + 128 * j;
        int r = idx >> 4, seg = idx & 15;
        float4 v = *reinterpret_cast<const float4*>(qbase + (size_t)(q0 + r) * 3072 + seg * 4);
        *reinterpret_cast<float4*>(&Qs[r][seg * 4]) = v;
    }
    __syncthreads();

    // hoist Q fragments (big/small tf32 split, once)
    unsigned qb[32], qs[32];
#pragma unroll
    for (int k0 = 0; k0 < 8; k0++) {
        float qa[4];
        qa[0] = Qs[wm + g][k0 * 8 + t];
        qa[1] = Qs[wm + g + 8][k0 * 8 + t];
        qa[2] = Qs[wm + g][k0 * 8 + t + 4];
        qa[3] = Qs[wm + g + 8][k0 * 8 + t + 4];
#pragma unroll
        for (int i = 0; i < 4; i++) {
            unsigned big = f2tf32(qa[i]);
            qb[k0 * 4 + i] = big;
            qs[k0 * 4 + i] = f2tf32(qa[i] - __uint_as_float(big));
        }
    }

    float oacc[8][4] = {};
    float mrow[2] = {-1e30f, -1e30f};
    float lrow[2] = {0.f, 0.f};

    for (int kb = 0; kb < L_SEQ / 32; kb++) {
        __syncthreads();  // prev PV reads of Vs done; guards Q-extract on iter 0
#pragma unroll
        for (int j = 0; j < 4; j++) {
            int idx = tid + 128 * j;
            int r = idx >> 4, seg = idx & 15;
            size_t moff = (size_t)(kb * 32 + r) * 3072 + seg * 4;
            float4 k4 = *reinterpret_cast<const float4*>(kbase + moff);
            unsigned b0 = f2tf32(k4.x), b1 = f2tf32(k4.y);
            unsigned b2 = f2tf32(k4.z), b3 = f2tf32(k4.w);
            KsB[r][seg * 4 + 0] = b0; KsB[r][seg * 4 + 1] = b1;
            KsB[r][seg * 4 + 2] = b2; KsB[r][seg * 4 + 3] = b3;
            KsS[r][seg * 4 + 0] = f2tf32(k4.x - __uint_as_float(b0));
            KsS[r][seg * 4 + 1] = f2tf32(k4.y - __uint_as_float(b1));
            KsS[r][seg * 4 + 2] = f2tf32(k4.z - __uint_as_float(b2));
            KsS[r][seg * 4 + 3] = f2tf32(k4.w - __uint_as_float(b3));
            float4 v4 = *reinterpret_cast<const float4*>(vbase + moff);
            uint4 u;
            u.x = f2tf32(v4.x); u.y = f2tf32(v4.y);
            u.z = f2tf32(v4.z); u.w = f2tf32(v4.w);
            *reinterpret_cast<uint4*>(&Vs[r][seg * 4]) = u;
        }
        __syncthreads();

        // ---- S = Q K^T (compensated tf32) ----
        float sacc[4][4] = {};
#pragma unroll
        for (int k0 = 0; k0 < 8; k0++) {
            const unsigned* qbp = qb + k0 * 4;
            const unsigned* qsp = qs + k0 * 4;
#pragma unroll
            for (int ni = 0; ni < 4; ni++) {
                unsigned kb0 = KsB[ni * 8 + g][k0 * 8 + t];
                unsigned kb1 = KsB[ni * 8 + g][k0 * 8 + t + 4];
                unsigned ks0 = KsS[ni * 8 + g][k0 * 8 + t];
                unsigned ks1 = KsS[ni * 8 + g][k0 * 8 + t + 4];
#define MMA_S(A0,A1,A2,A3,B0,B1) \
                asm volatile("mma.sync.aligned.m16n8k8.row.col.f32.tf32.tf32.f32 " \
                    "{%0,%1,%2,%3}, {%4,%5,%6,%7}, {%8,%9}, {%0,%1,%2,%3};" \
                    : "+f"(sacc[ni][0]), "+f"(sacc[ni][1]), "+f"(sacc[ni][2]), "+f"(sacc[ni][3]) \
                    : "r"(A0), "r"(A1), "r"(A2), "r"(A3), "r"(B0), "r"(B1))
                MMA_S(qbp[0], qbp[1], qbp[2], qbp[3], kb0, kb1);
                MMA_S(qbp[0], qbp[1], qbp[2], qbp[3], ks0, ks1);
                MMA_S(qsp[0], qsp[1], qsp[2], qsp[3], kb0, kb1);
#undef MMA_S
            }
        }

        // ---- online softmax (row max over quad) ----
        float ml0 = -1e30f, ml1 = -1e30f;
#pragma unroll
        for (int ni = 0; ni < 4; ni++) {
            ml0 = fmaxf(ml0, fmaxf(sacc[ni][0], sacc[ni][1]));
            ml1 = fmaxf(ml1, fmaxf(sacc[ni][2], sacc[ni][3]));
        }
#pragma unroll
        for (int off = 1; off < 4; off <<= 1) {
            ml0 = fmaxf(ml0, __shfl_xor_sync(0xffffffffu, ml0, off));
            ml1 = fmaxf(ml1, __shfl_xor_sync(0xffffffffu, ml1, off));
        }
        float mn0 = fmaxf(mrow[0], ml0);
        float mn1 = fmaxf(mrow[1], ml1);
        float corr0 = fexp2((mrow[0] - mn0) * L2E);
        float corr1 = fexp2((mrow[1] - mn1) * L2E);
        mrow[0] = mn0; mrow[1] = mn1;
#pragma unroll
        for (int ni = 0; ni < 8; ni++) {
            oacc[ni][0] *= corr0; oacc[ni][1] *= corr0;
            oacc[ni][2] *= corr1; oacc[ni][3] *= corr1;
        }

        // ---- exp + in-register layout conversion + PV, per 8-key slice ----
        float rs0 = 0.f, rs1 = 0.f;
#pragma unroll
        for (int ni = 0; ni < 4; ni++) {
            float p0 = fexp2((sacc[ni][0] - mn0) * L2E);
            float p1 = fexp2((sacc[ni][1] - mn0) * L2E);
            float p2 = fexp2((sacc[ni][2] - mn1) * L2E);
            float p3 = fexp2((sacc[ni][3] - mn1) * L2E);
            rs0 += p0 + p1;
            rs1 += p2 + p3;
            unsigned x0 = f2tf32(p0), x1 = f2tf32(p1);
            unsigned x2 = f2tf32(p2), x3 = f2tf32(p3);
            // accumulator layout -> A-fragment layout (intra-quad shuffles)
            unsigned e0 = __shfl_sync(0xffffffffu, x0, srcA);
            unsigned o0 = __shfl_sync(0xffffffffu, x1, srcA);
            unsigned e1 = __shfl_sync(0xffffffffu, x2, srcA);
            unsigned o1 = __shfl_sync(0xffffffffu, x3, srcA);
            unsigned e2 = __shfl_sync(0xffffffffu, x0, srcB);
            unsigned o2 = __shfl_sync(0xffffffffu, x1, srcB);
            unsigned e3 = __shfl_sync(0xffffffffu, x2, srcB);
            unsigned o3 = __shfl_sync(0xffffffffu, x3, srcB);
            unsigned pa0 = odd ? o0 : e0;   // (row_lo, k0+t)
            unsigned pa1 = odd ? o1 : e1;   // (row_hi, k0+t)
            unsigned pa2 = odd ? o2 : e2;   // (row_lo, k0+t+4)
            unsigned pa3 = odd ? o3 : e3;   // (row_hi, k0+t+4)
            int k0 = ni * 8;
#pragma unroll
            for (int no = 0; no < 8; no++) {
                unsigned vb0 = Vs[k0 + t][no * 8 + g];
                unsigned vb1 = Vs[k0 + t + 4][no * 8 + g];
                asm volatile("mma.sync.aligned.m16n8k8.row.col.f32.tf32.tf32.f32 "
                    "{%0,%1,%2,%3}, {%4,%5,%6,%7}, {%8,%9}, {%0,%1,%2,%3};"
                    : "+f"(oacc[no][0]), "+f"(oacc[no][1]), "+f"(oacc[no][2]), "+f"(oacc[no][3])
                    : "r"(pa0), "r"(pa1), "r"(pa2), "r"(pa3), "r"(vb0), "r"(vb1));
            }
        }
#pragma unroll
        for (int off = 1; off < 4; off <<= 1) {
            rs0 += __shfl_xor_sync(0xffffffffu, rs0, off);
            rs1 += __shfl_xor_sync(0xffffffffu, rs1, off);
        }
        lrow[0] = lrow[0] * corr0 + rs0;
        lrow[1] = lrow[1] * corr1 + rs1;
    }

    float inv0 = 1.0f / lrow[0];
    float inv1 = 1.0f / lrow[1];
    int row0 = b * L_SEQ + q0 + wm + g;
    int row1 = row0 + 8;
#pragma unroll
    for (int ni = 0; ni < 8; ni++) {
        int col = h * 64 + ni * 8 + 2 * t;
        float2 r0 = make_float2(oacc[ni][0] * inv0, oacc[ni][1] * inv0);
        float2 r1 = make_float2(oacc[ni][2] * inv1, oacc[ni][3] * inv1);
        *reinterpret_cast<float2*>(o + (size_t)row0 * DMODEL + col) = r0;
        *reinterpret_cast<float2*>(o + (size_t)row1 * DMODEL + col) = r1;
    }
}

extern "C" void kernel_launch(void* const* d_in, const int* in_sizes, int n_in,
                              void* d_out, int out_size)
{
    const float* x          = (const float*)d_in[0];
    const float* norm_scale = (const float*)d_in[2];
    const float* w_qkv      = (const float*)d_in[3];
    const float* attn_scale = (const float*)d_in[4];
    const float* w_out      = (const float*)d_in[5];
    const float* ff_scale   = (const float*)d_in[6];
    const float* w_up       = (const float*)d_in[7];
    const float* w_down     = (const float*)d_in[8];
    float* out = (float*)d_out;

    float *xn, *qkvp, *op, *up;
    cudaGetSymbolAddress((void**)&xn, g_xn);
    cudaGetSymbolAddress((void**)&qkvp, g_qkv);
    cudaGetSymbolAddress((void**)&op, g_o);
    cudaGetSymbolAddress((void**)&up, g_u);

    // 1) xn = rmsnorm(x)
    rmsnorm_kernel<<<MTOT, 256>>>(x, norm_scale, xn);
    // 2) qkv = xn @ w_qkv^T  [4096 x 3072]
    gemm_tf32_kernel<false><<<dim3(3 * DMODEL / 128, MTOT / 128), 256>>>(
        xn, w_qkv, nullptr, qkvp, 3 * DMODEL, DMODEL);
    // 3) q,k cosine norm
    qknorm_kernel<<<MTOT * 32 / 8, 256>>>(qkvp, attn_scale);
    // 4) attention -> o
    attention_tc_kernel<<<dim3(L_SEQ / 64, NHEAD, BATCH), 128>>>(qkvp, op);
    // 5) x1 = o @ w_out^T + x
    gemm_tf32_kernel<false><<<dim3(DMODEL / 128, MTOT / 128), 256>>>(
        op, w_out, x, out, DMODEL, DMODEL);
    // 6) xn = rmsnorm(x1)
    rmsnorm_kernel<<<MTOT, 256>>>(out, ff_scale, xn);
    // 7) u = xn @ w_up^T  [4096 x 6144]
    gemm_tf32_kernel<false><<<dim3(2 * DFF / 128, MTOT / 128), 256>>>(
        xn, w_up, nullptr, up, 2 * DFF, DMODEL);
    // 8+9) out = swiglu(u) @ w_down^T + x1  (silu fused into A loader)
    gemm_tf32_kernel<true><<<dim3(DMODEL / 128, MTOT / 128), 256>>>(
        up, w_down, out, out, DMODEL, DFF);
}

// round 7
// speedup vs baseline: 1.1459x; 1.0728x over previous
#include <cuda_runtime.h>
#include <cstdint>

#define L_SEQ 2048
#define BATCH 2
#define DMODEL 1024
#define NHEAD 16
#define DHEAD 64
#define DFF 3072
#define MTOT (BATCH * L_SEQ) /* 4096 */

// -------- scratch (device globals: allocation-free rule) --------
__device__ float g_xn[MTOT * DMODEL];
__device__ float g_qkv[MTOT * 3 * DMODEL];
__device__ float g_o[MTOT * DMODEL];
__device__ float g_u[MTOT * 2 * DFF];
__device__ float g_h[MTOT * DFF];

__device__ __forceinline__ unsigned f2tf32(float f) {
    unsigned r;
    asm("cvt.rna.tf32.f32 %0, %1;" : "=r"(r) : "f"(f));
    return r;
}

// FFMA-only 2^y (no MUFU).
__device__ __forceinline__ float fexp2(float y) {
    y = fmaxf(fminf(y, 120.f), -120.f);
    float z = y + 12582912.f;                 // 1.5*2^23
    int n = __float_as_int(z) - 0x4B400000;   // round(y)
    float f = y - (z - 12582912.f);           // y - n in [-0.5, 0.5]
    float p = 0.0013333558f;
    p = fmaf(p, f, 0.0096181291f);
    p = fmaf(p, f, 0.0555041087f);
    p = fmaf(p, f, 0.2402265070f);
    p = fmaf(p, f, 0.6931471806f);
    p = fmaf(p, f, 1.0f);
    return __int_as_float((n + 127) << 23) * p;
}
#define L2E 1.4426950408889634f

// ---------------- RMSNorm ----------------
__global__ void __launch_bounds__(256) rmsnorm_kernel(const float* __restrict__ x,
                                                      const float* __restrict__ scale,
                                                      float* __restrict__ out)
{
    int row = blockIdx.x;
    int t = threadIdx.x;
    const float4* xr = reinterpret_cast<const float4*>(x) + (size_t)row * (DMODEL / 4);
    float4 v = xr[t];
    float ss = v.x * v.x + v.y * v.y + v.z * v.z + v.w * v.w;
#pragma unroll
    for (int o = 16; o; o >>= 1) ss += __shfl_xor_sync(0xffffffffu, ss, o);
    __shared__ float ws[8];
    if ((t & 31) == 0) ws[t >> 5] = ss;
    __syncthreads();
    float tot = 0.f;
#pragma unroll
    for (int i = 0; i < 8; i++) tot += ws[i];
    float inv = rsqrtf(tot * (1.0f / DMODEL) + 1e-6f);
    float4 s = reinterpret_cast<const float4*>(scale)[t];
    float4 r;
    r.x = v.x * s.x * inv;
    r.y = v.y * s.y * inv;
    r.z = v.z * s.z * inv;
    r.w = v.w * s.w * inv;
    (reinterpret_cast<float4*>(out) + (size_t)row * (DMODEL / 4))[t] = r;
}

// ---------------- TF32 tensor-core GEMM NT, double-buffered smem ----------------
// C[m,n] = sum_k A[m,k]*B[n,k] (+resid). 128x128 tile, BK=16, 8 warps, 64x32 warp tile.
#define BKK 16
#define LDP 136
__global__ void __launch_bounds__(256, 2) gemm_tf32_kernel(const float* __restrict__ A,
                                                           const float* __restrict__ B,
                                                           const float* resid,
                                                           float* __restrict__ C,
                                                           int N, int K)
{
    __shared__ unsigned As[2][BKK][LDP];
    __shared__ unsigned Bs[2][BKK][LDP];
    int tid = threadIdx.x;
    int warp = tid >> 5, lane = tid & 31;
    int g = lane >> 2, t = lane & 3;
    int m0 = blockIdx.y * 128, n0 = blockIdx.x * 128;
    int wm = (warp >> 2) * 64;
    int wn = (warp & 3) * 32;

    int lm = tid >> 1;
    int lk = (tid & 1) * 8;
    const float* Ap = A + (size_t)(m0 + lm) * K + lk;
    const float* Bp = B + (size_t)(n0 + lm) * K + lk;

    float acc[4][4][4] = {};

    // prologue: load tile 0, store to buffer 0
    {
        float4 a0 = *reinterpret_cast<const float4*>(Ap);
        float4 a1 = *reinterpret_cast<const float4*>(Ap + 4);
        float4 b0 = *reinterpret_cast<const float4*>(Bp);
        float4 b1 = *reinterpret_cast<const float4*>(Bp + 4);
        As[0][lk + 0][lm] = f2tf32(a0.x); As[0][lk + 1][lm] = f2tf32(a0.y);
        As[0][lk + 2][lm] = f2tf32(a0.z); As[0][lk + 3][lm] = f2tf32(a0.w);
        As[0][lk + 4][lm] = f2tf32(a1.x); As[0][lk + 5][lm] = f2tf32(a1.y);
        As[0][lk + 6][lm] = f2tf32(a1.z); As[0][lk + 7][lm] = f2tf32(a1.w);
        Bs[0][lk + 0][lm] = f2tf32(b0.x); Bs[0][lk + 1][lm] = f2tf32(b0.y);
        Bs[0][lk + 2][lm] = f2tf32(b0.z); Bs[0][lk + 3][lm] = f2tf32(b0.w);
        Bs[0][lk + 4][lm] = f2tf32(b1.x); Bs[0][lk + 5][lm] = f2tf32(b1.y);
        Bs[0][lk + 6][lm] = f2tf32(b1.z); Bs[0][lk + 7][lm] = f2tf32(b1.w);
    }
    __syncthreads();

    int cur = 0;
    for (int kt = 0; kt < K; kt += BKK) {
        bool has_next = (kt + BKK < K);
        float4 a0, a1, b0, b1;
        if (has_next) {  // prefetch next tile into registers
            a0 = *reinterpret_cast<const float4*>(Ap + kt + BKK);
            a1 = *reinterpret_cast<const float4*>(Ap + kt + BKK + 4);
            b0 = *reinterpret_cast<const float4*>(Bp + kt + BKK);
            b1 = *reinterpret_cast<const float4*>(Bp + kt + BKK + 4);
        }

        // compute from buffer `cur`
#pragma unroll
        for (int ks = 0; ks < BKK; ks += 8) {
            unsigned af[4][4], bf[4][2];
#pragma unroll
            for (int mi = 0; mi < 4; mi++) {
                int mr = wm + mi * 16 + g;
                af[mi][0] = As[cur][ks + t][mr];
                af[mi][1] = As[cur][ks + t][mr + 8];
                af[mi][2] = As[cur][ks + t + 4][mr];
                af[mi][3] = As[cur][ks + t + 4][mr + 8];
            }
#pragma unroll
            for (int ni = 0; ni < 4; ni++) {
                int nc = wn + ni * 8 + g;
                bf[ni][0] = Bs[cur][ks + t][nc];
                bf[ni][1] = Bs[cur][ks + t + 4][nc];
            }
#pragma unroll
            for (int mi = 0; mi < 4; mi++)
#pragma unroll
                for (int ni = 0; ni < 4; ni++) {
                    asm volatile(
                        "mma.sync.aligned.m16n8k8.row.col.f32.tf32.tf32.f32 "
                        "{%0,%1,%2,%3}, {%4,%5,%6,%7}, {%8,%9}, {%0,%1,%2,%3};"
                        : "+f"(acc[mi][ni][0]), "+f"(acc[mi][ni][1]),
                          "+f"(acc[mi][ni][2]), "+f"(acc[mi][ni][3])
                        : "r"(af[mi][0]), "r"(af[mi][1]), "r"(af[mi][2]), "r"(af[mi][3]),
                          "r"(bf[ni][0]), "r"(bf[ni][1]));
                }
        }

        if (has_next) {  // store prefetched tile into the other buffer
            int nxt = cur ^ 1;
            As[nxt][lk + 0][lm] = f2tf32(a0.x); As[nxt][lk + 1][lm] = f2tf32(a0.y);
            As[nxt][lk + 2][lm] = f2tf32(a0.z); As[nxt][lk + 3][lm] = f2tf32(a0.w);
            As[nxt][lk + 4][lm] = f2tf32(a1.x); As[nxt][lk + 5][lm] = f2tf32(a1.y);
            As[nxt][lk + 6][lm] = f2tf32(a1.z); As[nxt][lk + 7][lm] = f2tf32(a1.w);
            Bs[nxt][lk + 0][lm] = f2tf32(b0.x); Bs[nxt][lk + 1][lm] = f2tf32(b0.y);
            Bs[nxt][lk + 2][lm] = f2tf32(b0.z); Bs[nxt][lk + 3][lm] = f2tf32(b0.w);
            Bs[nxt][lk + 4][lm] = f2tf32(b1.x); Bs[nxt][lk + 5][lm] = f2tf32(b1.y);
            Bs[nxt][lk + 6][lm] = f2tf32(b1.z); Bs[nxt][lk + 7][lm] = f2tf32(b1.w);
            __syncthreads();
            cur = nxt;
        }
    }

#pragma unroll
    for (int mi = 0; mi < 4; mi++) {
#pragma unroll
        for (int ni = 0; ni < 4; ni++) {
            int row0 = m0 + wm + mi * 16 + g;
            int col = n0 + wn + ni * 8 + 2 * t;
            size_t i0 = (size_t)row0 * N + col;
            size_t i1 = (size_t)(row0 + 8) * N + col;
            float2 v01 = make_float2(acc[mi][ni][0], acc[mi][ni][1]);
            float2 v23 = make_float2(acc[mi][ni][2], acc[mi][ni][3]);
            if (resid) {
                float2 r0 = *reinterpret_cast<const float2*>(resid + i0);
                float2 r1 = *reinterpret_cast<const float2*>(resid + i1);
                v01.x += r0.x; v01.y += r0.y;
                v23.x += r1.x; v23.y += r1.y;
            }
            *reinterpret_cast<float2*>(C + i0) = v01;
            *reinterpret_cast<float2*>(C + i1) = v23;
        }
    }
}

// ---------------- QK cosine norm ----------------
__global__ void __launch_bounds__(256) qknorm_kernel(float* __restrict__ qkv,
                                                     const float* __restrict__ attn_scale)
{
    int warp = blockIdx.x * (blockDim.x >> 5) + (threadIdx.x >> 5);
    int lane = threadIdx.x & 31;
    int m = warp >> 5;
    int rest = warp & 31;
    int part = rest >> 4;
    int h = rest & 15;
    size_t base = (size_t)m * 3072 + part * 1024 + h * 64;
    float2 v = *reinterpret_cast<float2*>(qkv + base + lane * 2);
    float ss = v.x * v.x + v.y * v.y;
#pragma unroll
    for (int o = 16; o; o >>= 1) ss += __shfl_xor_sync(0xffffffffu, ss, o);
    float f = sqrtf(attn_scale[h]) * rsqrtf(ss + 1e-6f);
    v.x *= f;
    v.y *= f;
    *reinterpret_cast<float2*>(qkv + base + lane * 2) = v;
}

// ---------------- Tensor-core flash attention (R3-proven version) ----------------
__global__ void __launch_bounds__(128) attention_tc_kernel(const float* __restrict__ qkv,
                                                           float* __restrict__ o)
{
    __shared__ __align__(16) char qk_raw[64 * 68 * 4];
    float (*Qs)[68] = reinterpret_cast<float(*)[68]>(qk_raw);
    unsigned (*KsB)[68] = reinterpret_cast<unsigned(*)[68]>(qk_raw);
    unsigned (*KsS)[68] = reinterpret_cast<unsigned(*)[68]>(qk_raw + 32 * 68 * 4);
    __shared__ unsigned Vs[32][72];
    __shared__ unsigned Ps[64][36];

    int tid = threadIdx.x;
    int warp = tid >> 5, lane = tid & 31;
    int g = lane >> 2, t = lane & 3;
    int wm = warp * 16;
    int q0 = blockIdx.x * 64;
    int h = blockIdx.y, b = blockIdx.z;
    const float* qbase = qkv + (size_t)b * L_SEQ * 3072 + h * 64;
    const float* kbase = qbase + 1024;
    const float* vbase = qbase + 2048;

#pragma unroll
    for (int j = 0; j < 8; j++) {
        int idx = tid + 128 * j;
        int r = idx >> 4, seg = idx & 15;
        float4 v = *reinterpret_cast<const float4*>(qbase + (size_t)(q0 + r) * 3072 + seg * 4);
        *reinterpret_cast<float4*>(&Qs[r][seg * 4]) = v;
    }
    __syncthreads();

    unsigned qb[32], qs[32];
#pragma unroll
    for (int k0 = 0; k0 < 8; k0++) {
        float qa[4];
        qa[0] = Qs[wm + g][k0 * 8 + t];
        qa[1] = Qs[wm + g + 8][k0 * 8 + t];
        qa[2] = Qs[wm + g][k0 * 8 + t + 4];
        qa[3] = Qs[wm + g + 8][k0 * 8 + t + 4];
#pragma unroll
        for (int i = 0; i < 4; i++) {
            unsigned big = f2tf32(qa[i]);
            qb[k0 * 4 + i] = big;
            qs[k0 * 4 + i] = f2tf32(qa[i] - __uint_as_float(big));
        }
    }

    float oacc[8][4] = {};
    float mrow[2] = {-1e30f, -1e30f};
    float lrow[2] = {0.f, 0.f};

    for (int kb = 0; kb < L_SEQ / 32; kb++) {
        __syncthreads();
#pragma unroll
        for (int j = 0; j < 4; j++) {
            int idx = tid + 128 * j;
            int r = idx >> 4, seg = idx & 15;
            size_t moff = (size_t)(kb * 32 + r) * 3072 + seg * 4;
            float4 k4 = *reinterpret_cast<const float4*>(kbase + moff);
            unsigned b0 = f2tf32(k4.x), b1 = f2tf32(k4.y);
            unsigned b2 = f2tf32(k4.z), b3 = f2tf32(k4.w);
            KsB[r][seg * 4 + 0] = b0; KsB[r][seg * 4 + 1] = b1;
            KsB[r][seg * 4 + 2] = b2; KsB[r][seg * 4 + 3] = b3;
            KsS[r][seg * 4 + 0] = f2tf32(k4.x - __uint_as_float(b0));
            KsS[r][seg * 4 + 1] = f2tf32(k4.y - __uint_as_float(b1));
            KsS[r][seg * 4 + 2] = f2tf32(k4.z - __uint_as_float(b2));
            KsS[r][seg * 4 + 3] = f2tf32(k4.w - __uint_as_float(b3));
            float4 v4 = *reinterpret_cast<const float4*>(vbase + moff);
            uint4 u;
            u.x = f2tf32(v4.x); u.y = f2tf32(v4.y);
            u.z = f2tf32(v4.z); u.w = f2tf32(v4.w);
            *reinterpret_cast<uint4*>(&Vs[r][seg * 4]) = u;
        }
        __syncthreads();

        float sacc[4][4] = {};
#pragma unroll
        for (int k0 = 0; k0 < 8; k0++) {
            const unsigned* qbp = qb + k0 * 4;
            const unsigned* qsp = qs + k0 * 4;
#pragma unroll
            for (int ni = 0; ni < 4; ni++) {
                unsigned kb0 = KsB[ni * 8 + g][k0 * 8 + t];
                unsigned kb1 = KsB[ni * 8 + g][k0 * 8 + t + 4];
                unsigned ks0 = KsS[ni * 8 + g][k0 * 8 + t];
                unsigned ks1 = KsS[ni * 8 + g][k0 * 8 + t + 4];
#define MMA_S(A0,A1,A2,A3,B0,B1) \
                asm volatile("mma.sync.aligned.m16n8k8.row.col.f32.tf32.tf32.f32 " \
                    "{%0,%1,%2,%3}, {%4,%5,%6,%7}, {%8,%9}, {%0,%1,%2,%3};" \
                    : "+f"(sacc[ni][0]), "+f"(sacc[ni][1]), "+f"(sacc[ni][2]), "+f"(sacc[ni][3]) \
                    : "r"(A0), "r"(A1), "r"(A2), "r"(A3), "r"(B0), "r"(B1))
                MMA_S(qbp[0], qbp[1], qbp[2], qbp[3], kb0, kb1);
                MMA_S(qbp[0], qbp[1], qbp[2], qbp[3], ks0, ks1);
                MMA_S(qsp[0], qsp[1], qsp[2], qsp[3], kb0, kb1);
#undef MMA_S
            }
        }

        float ml0 = -1e30f, ml1 = -1e30f;
#pragma unroll
        for (int ni = 0; ni < 4; ni++) {
            ml0 = fmaxf(ml0, fmaxf(sacc[ni][0], sacc[ni][1]));
            ml1 = fmaxf(ml1, fmaxf(sacc[ni][2], sacc[ni][3]));
        }
#pragma unroll
        for (int off = 1; off < 4; off <<= 1) {
            ml0 = fmaxf(ml0, __shfl_xor_sync(0xffffffffu, ml0, off));
            ml1 = fmaxf(ml1, __shfl_xor_sync(0xffffffffu, ml1, off));
        }
        float mn0 = fmaxf(mrow[0], ml0);
        float mn1 = fmaxf(mrow[1], ml1);
        float corr0 = fexp2((mrow[0] - mn0) * L2E);
        float corr1 = fexp2((mrow[1] - mn1) * L2E);
        mrow[0] = mn0; mrow[1] = mn1;

        float rs0 = 0.f, rs1 = 0.f;
#pragma unroll
        for (int ni = 0; ni < 4; ni++) {
            float p0 = fexp2((sacc[ni][0] - mn0) * L2E);
            float p1 = fexp2((sacc[ni][1] - mn0) * L2E);
            float p2 = fexp2((sacc[ni][2] - mn1) * L2E);
            float p3 = fexp2((sacc[ni][3] - mn1) * L2E);
            rs0 += p0 + p1;
            rs1 += p2 + p3;
            Ps[wm + g][ni * 8 + 2 * t] = f2tf32(p0);
            Ps[wm + g][ni * 8 + 2 * t + 1] = f2tf32(p1);
            Ps[wm + g + 8][ni * 8 + 2 * t] = f2tf32(p2);
            Ps[wm + g + 8][ni * 8 + 2 * t + 1] = f2tf32(p3);
        }
#pragma unroll
        for (int off = 1; off < 4; off <<= 1) {
            rs0 += __shfl_xor_sync(0xffffffffu, rs0, off);
            rs1 += __shfl_xor_sync(0xffffffffu, rs1, off);
        }
        lrow[0] = lrow[0] * corr0 + rs0;
        lrow[1] = lrow[1] * corr1 + rs1;
#pragma unroll
        for (int ni = 0; ni < 8; ni++) {
            oacc[ni][0] *= corr0; oacc[ni][1] *= corr0;
            oacc[ni][2] *= corr1; oacc[ni][3] *= corr1;
        }
        __syncwarp();

#pragma unroll
        for (int k0 = 0; k0 < 32; k0 += 8) {
            unsigned pa0 = Ps[wm + g][k0 + t];
            unsigned pa1 = Ps[wm + g + 8][k0 + t];
            unsigned pa2 = Ps[wm + g][k0 + t + 4];
            unsigned pa3 = Ps[wm + g + 8][k0 + t + 4];
#pragma unroll
            for (int ni = 0; ni < 8; ni++) {
                unsigned vb0 = Vs[k0 + t][ni * 8 + g];
                unsigned vb1 = Vs[k0 + t + 4][ni * 8 + g];
                asm volatile("mma.sync.aligned.m16n8k8.row.col.f32.tf32.tf32.f32 "
                    "{%0,%1,%2,%3}, {%4,%5,%6,%7}, {%8,%9}, {%0,%1,%2,%3};"
                    : "+f"(oacc[ni][0]), "+f"(oacc[ni][1]), "+f"(oacc[ni][2]), "+f"(oacc[ni][3])
                    : "r"(pa0), "r"(pa1), "r"(pa2), "r"(pa3), "r"(vb0), "r"(vb1));
            }
        }
        __syncwarp();
    }

    float inv0 = 1.0f / lrow[0];
    float inv1 = 1.0f / lrow[1];
    int row0 = b * L_SEQ + q0 + wm + g;
    int row1 = row0 + 8;
#pragma unroll
    for (int ni = 0; ni < 8; ni++) {
        int col = h * 64 + ni * 8 + 2 * t;
        float2 r0 = make_float2(oacc[ni][0] * inv0, oacc[ni][1] * inv0);
        float2 r1 = make_float2(oacc[ni][2] * inv1, oacc[ni][3] * inv1);
        *reinterpret_cast<float2*>(o + (size_t)row0 * DMODEL + col) = r0;
        *reinterpret_cast<float2*>(o + (size_t)row1 * DMODEL + col) = r1;
    }
}

// ---------------- SwiGLU ----------------
__global__ void __launch_bounds__(256) swiglu_kernel(const float* __restrict__ u,
                                                     float* __restrict__ h)
{
    int idx = blockIdx.x * blockDim.x + threadIdx.x;
    int m = idx / (DFF / 4);
    int j = idx % (DFF / 4);
    const float4* ur = reinterpret_cast<const float4*>(u) + (size_t)m * (2 * DFF / 4);
    float4 a = ur[j];
    float4 g = ur[DFF / 4 + j];
    float4 r;
    r.x = a.x * g.x / (1.f + fexp2(-g.x * L2E));
    r.y = a.y * g.y / (1.f + fexp2(-g.y * L2E));
    r.z = a.z * g.z / (1.f + fexp2(-g.z * L2E));
    r.w = a.w * g.w / (1.f + fexp2(-g.w * L2E));
    reinterpret_cast<float4*>(h)[idx] = r;
}

extern "C" void kernel_launch(void* const* d_in, const int* in_sizes, int n_in,
                              void* d_out, int out_size)
{
    const float* x          = (const float*)d_in[0];
    const float* norm_scale = (const float*)d_in[2];
    const float* w_qkv      = (const float*)d_in[3];
    const float* attn_scale = (const float*)d_in[4];
    const float* w_out      = (const float*)d_in[5];
    const float* ff_scale   = (const float*)d_in[6];
    const float* w_up       = (const float*)d_in[7];
    const float* w_down     = (const float*)d_in[8];
    float* out = (float*)d_out;

    float *xn, *qkvp, *op, *up, *hp;
    cudaGetSymbolAddress((void**)&xn, g_xn);
    cudaGetSymbolAddress((void**)&qkvp, g_qkv);
    cudaGetSymbolAddress((void**)&op, g_o);
    cudaGetSymbolAddress((void**)&up, g_u);
    cudaGetSymbolAddress((void**)&hp, g_h);

    rmsnorm_kernel<<<MTOT, 256>>>(x, norm_scale, xn);
    gemm_tf32_kernel<<<dim3(3 * DMODEL / 128, MTOT / 128), 256>>>(xn, w_qkv, nullptr, qkvp, 3 * DMODEL, DMODEL);
    qknorm_kernel<<<MTOT * 32 / 8, 256>>>(qkvp, attn_scale);
    attention_tc_kernel<<<dim3(L_SEQ / 64, NHEAD, BATCH), 128>>>(qkvp, op);
    gemm_tf32_kernel<<<dim3(DMODEL / 128, MTOT / 128), 256>>>(op, w_out, x, out, DMODEL, DMODEL);
    rmsnorm_kernel<<<MTOT, 256>>>(out, ff_scale, xn);
    gemm_tf32_kernel<<<dim3(2 * DFF / 128, MTOT / 128), 256>>>(xn, w_up, nullptr, up, 2 * DFF, DMODEL);
    swiglu_kernel<<<MTOT * DFF / 4 / 256, 256>>>(up, hp);
    gemm_tf32_kernel<<<dim3(DMODEL / 128, MTOT / 128), 256>>>(hp, w_down, out, out, DMODEL, DFF);
}

// round 9
// speedup vs baseline: 1.3027x; 1.1368x over previous
#include <cuda_runtime.h>
#include <cstdint>

#define L_SEQ 2048
#define BATCH 2
#define DMODEL 1024
#define NHEAD 16
#define DHEAD 64
#define DFF 3072
#define MTOT (BATCH * L_SEQ) /* 4096 */

// -------- scratch (device globals: allocation-free rule) --------
__device__ float g_xn[MTOT * DMODEL];
__device__ float g_qkv[MTOT * 3 * DMODEL];
__device__ float g_o[MTOT * DMODEL];
__device__ float g_u[MTOT * 2 * DFF];
__device__ float g_h[MTOT * DFF];

__device__ __forceinline__ unsigned f2tf32(float f) {
    unsigned r;
    asm("cvt.rna.tf32.f32 %0, %1;" : "=r"(r) : "f"(f));
    return r;
}

// FFMA-only 2^y (no MUFU).
__device__ __forceinline__ float fexp2(float y) {
    y = fmaxf(fminf(y, 120.f), -120.f);
    float z = y + 12582912.f;                 // 1.5*2^23
    int n = __float_as_int(z) - 0x4B400000;   // round(y)
    float f = y - (z - 12582912.f);           // y - n in [-0.5, 0.5]
    float p = 0.0013333558f;
    p = fmaf(p, f, 0.0096181291f);
    p = fmaf(p, f, 0.0555041087f);
    p = fmaf(p, f, 0.2402265070f);
    p = fmaf(p, f, 0.6931471806f);
    p = fmaf(p, f, 1.0f);
    return __int_as_float((n + 127) << 23) * p;
}
#define L2E 1.4426950408889634f

__device__ __forceinline__ void ldsm4(unsigned& r0, unsigned& r1, unsigned& r2, unsigned& r3,
                                      const void* p)
{
    unsigned a = (unsigned)__cvta_generic_to_shared(p);
    asm volatile("ldmatrix.sync.aligned.m8n8.x4.shared.b16 {%0,%1,%2,%3}, [%4];"
                 : "=r"(r0), "=r"(r1), "=r"(r2), "=r"(r3) : "r"(a));
}
__device__ __forceinline__ void ldsm2(unsigned& r0, unsigned& r1, const void* p)
{
    unsigned a = (unsigned)__cvta_generic_to_shared(p);
    asm volatile("ldmatrix.sync.aligned.m8n8.x2.shared.b16 {%0,%1}, [%2];"
                 : "=r"(r0), "=r"(r1) : "r"(a));
}

// ---------------- RMSNorm ----------------
__global__ void __launch_bounds__(256) rmsnorm_kernel(const float* __restrict__ x,
                                                      const float* __restrict__ scale,
                                                      float* __restrict__ out)
{
    int row = blockIdx.x;
    int t = threadIdx.x;
    const float4* xr = reinterpret_cast<const float4*>(x) + (size_t)row * (DMODEL / 4);
    float4 v = xr[t];
    float ss = v.x * v.x + v.y * v.y + v.z * v.z + v.w * v.w;
#pragma unroll
    for (int o = 16; o; o >>= 1) ss += __shfl_xor_sync(0xffffffffu, ss, o);
    __shared__ float ws[8];
    if ((t & 31) == 0) ws[t >> 5] = ss;
    __syncthreads();
    float tot = 0.f;
#pragma unroll
    for (int i = 0; i < 8; i++) tot += ws[i];
    float inv = rsqrtf(tot * (1.0f / DMODEL) + 1e-6f);
    float4 s = reinterpret_cast<const float4*>(scale)[t];
    float4 r;
    r.x = v.x * s.x * inv;
    r.y = v.y * s.y * inv;
    r.z = v.z * s.z * inv;
    r.w = v.w * s.w * inv;
    (reinterpret_cast<float4*>(out) + (size_t)row * (DMODEL / 4))[t] = r;
}

// ---------------- TF32 GEMM NT: ldmatrix fragments + double-buffered smem ----------------
// C[m,n] = sum_k A[m,k]*B[n,k] (+resid). 128x128 tile, BK=16, 8 warps, 64x32 warp tile.
// Smem row-major [row][k], stride 20 words: LDSM 8-row phases are bank-disjoint.
#define BKK 16
#define LDA 20
__global__ void __launch_bounds__(256, 2) gemm_tf32_kernel(const float* __restrict__ A,
                                                           const float* __restrict__ B,
                                                           const float* resid,
                                                           float* __restrict__ C,
                                                           int N, int K)
{
    __shared__ unsigned As[2][128][LDA];
    __shared__ unsigned Bs[2][128][LDA];
    int tid = threadIdx.x;
    int warp = tid >> 5, lane = tid & 31;
    int g = lane >> 2, t = lane & 3;
    int m0 = blockIdx.y * 128, n0 = blockIdx.x * 128;
    int wm = (warp >> 2) * 64;
    int wn = (warp & 3) * 32;

    // ldmatrix per-lane source coords
    int arow = wm + (lane & 15);            // + mi*16
    int acol = (lane >> 4) * 4;             // + ks
    int brow = wn + (lane & 7);             // + ni*8
    int bcol = ((lane >> 3) & 1) * 4;       // + ks

    int lm = tid >> 1;
    int lk = (tid & 1) * 8;
    const float* Ap = A + (size_t)(m0 + lm) * K + lk;
    const float* Bp = B + (size_t)(n0 + lm) * K + lk;

    float acc[4][4][4] = {};

    // prologue: tile 0 -> buffer 0
    {
        float4 a0 = *reinterpret_cast<const float4*>(Ap);
        float4 a1 = *reinterpret_cast<const float4*>(Ap + 4);
        float4 b0 = *reinterpret_cast<const float4*>(Bp);
        float4 b1 = *reinterpret_cast<const float4*>(Bp + 4);
        uint4 ua0 = make_uint4(f2tf32(a0.x), f2tf32(a0.y), f2tf32(a0.z), f2tf32(a0.w));
        uint4 ua1 = make_uint4(f2tf32(a1.x), f2tf32(a1.y), f2tf32(a1.z), f2tf32(a1.w));
        uint4 ub0 = make_uint4(f2tf32(b0.x), f2tf32(b0.y), f2tf32(b0.z), f2tf32(b0.w));
        uint4 ub1 = make_uint4(f2tf32(b1.x), f2tf32(b1.y), f2tf32(b1.z), f2tf32(b1.w));
        *reinterpret_cast<uint4*>(&As[0][lm][lk]) = ua0;
        *reinterpret_cast<uint4*>(&As[0][lm][lk + 4]) = ua1;
        *reinterpret_cast<uint4*>(&Bs[0][lm][lk]) = ub0;
        *reinterpret_cast<uint4*>(&Bs[0][lm][lk + 4]) = ub1;
    }
    __syncthreads();

    int cur = 0;
    for (int kt = 0; kt < K; kt += BKK) {
        bool has_next = (kt + BKK < K);
        float4 a0, a1, b0, b1;
        if (has_next) {
            a0 = *reinterpret_cast<const float4*>(Ap + kt + BKK);
            a1 = *reinterpret_cast<const float4*>(Ap + kt + BKK + 4);
            b0 = *reinterpret_cast<const float4*>(Bp + kt + BKK);
            b1 = *reinterpret_cast<const float4*>(Bp + kt + BKK + 4);
        }

        // compute from buffer `cur` with ldmatrix fragment loads
#pragma unroll
        for (int ks = 0; ks < BKK; ks += 8) {
            unsigned af[4][4], bf[4][2];
#pragma unroll
            for (int mi = 0; mi < 4; mi++)
                ldsm4(af[mi][0], af[mi][1], af[mi][2], af[mi][3],
                      &As[cur][arow + mi * 16][ks + acol]);
#pragma unroll
            for (int ni = 0; ni < 4; ni++)
                ldsm2(bf[ni][0], bf[ni][1], &Bs[cur][brow + ni * 8][ks + bcol]);
#pragma unroll
            for (int mi = 0; mi < 4; mi++)
#pragma unroll
                for (int ni = 0; ni < 4; ni++) {
                    asm volatile(
                        "mma.sync.aligned.m16n8k8.row.col.f32.tf32.tf32.f32 "
                        "{%0,%1,%2,%3}, {%4,%5,%6,%7}, {%8,%9}, {%0,%1,%2,%3};"
                        : "+f"(acc[mi][ni][0]), "+f"(acc[mi][ni][1]),
                          "+f"(acc[mi][ni][2]), "+f"(acc[mi][ni][3])
                        : "r"(af[mi][0]), "r"(af[mi][1]), "r"(af[mi][2]), "r"(af[mi][3]),
                          "r"(bf[ni][0]), "r"(bf[ni][1]));
                }
        }

        if (has_next) {
            int nxt = cur ^ 1;
            uint4 ua0 = make_uint4(f2tf32(a0.x), f2tf32(a0.y), f2tf32(a0.z), f2tf32(a0.w));
            uint4 ua1 = make_uint4(f2tf32(a1.x), f2tf32(a1.y), f2tf32(a1.z), f2tf32(a1.w));
            uint4 ub0 = make_uint4(f2tf32(b0.x), f2tf32(b0.y), f2tf32(b0.z), f2tf32(b0.w));
            uint4 ub1 = make_uint4(f2tf32(b1.x), f2tf32(b1.y), f2tf32(b1.z), f2tf32(b1.w));
            *reinterpret_cast<uint4*>(&As[nxt][lm][lk]) = ua0;
            *reinterpret_cast<uint4*>(&As[nxt][lm][lk + 4]) = ua1;
            *reinterpret_cast<uint4*>(&Bs[nxt][lm][lk]) = ub0;
            *reinterpret_cast<uint4*>(&Bs[nxt][lm][lk + 4]) = ub1;
            __syncthreads();
            cur = nxt;
        }
    }

#pragma unroll
    for (int mi = 0; mi < 4; mi++) {
#pragma unroll
        for (int ni = 0; ni < 4; ni++) {
            int row0 = m0 + wm + mi * 16 + g;
            int col = n0 + wn + ni * 8 + 2 * t;
            size_t i0 = (size_t)row0 * N + col;
            size_t i1 = (size_t)(row0 + 8) * N + col;
            float2 v01 = make_float2(acc[mi][ni][0], acc[mi][ni][1]);
            float2 v23 = make_float2(acc[mi][ni][2], acc[mi][ni][3]);
            if (resid) {
                float2 r0 = *reinterpret_cast<const float2*>(resid + i0);
                float2 r1 = *reinterpret_cast<const float2*>(resid + i1);
                v01.x += r0.x; v01.y += r0.y;
                v23.x += r1.x; v23.y += r1.y;
            }
            *reinterpret_cast<float2*>(C + i0) = v01;
            *reinterpret_cast<float2*>(C + i1) = v23;
        }
    }
}

// ---------------- QK cosine norm ----------------
__global__ void __launch_bounds__(256) qknorm_kernel(float* __restrict__ qkv,
                                                     const float* __restrict__ attn_scale)
{
    int warp = blockIdx.x * (blockDim.x >> 5) + (threadIdx.x >> 5);
    int lane = threadIdx.x & 31;
    int m = warp >> 5;
    int rest = warp & 31;
    int part = rest >> 4;
    int h = rest & 15;
    size_t base = (size_t)m * 3072 + part * 1024 + h * 64;
    float2 v = *reinterpret_cast<float2*>(qkv + base + lane * 2);
    float ss = v.x * v.x + v.y * v.y;
#pragma unroll
    for (int o = 16; o; o >>= 1) ss += __shfl_xor_sync(0xffffffffu, ss, o);
    float f = sqrtf(attn_scale[h]) * rsqrtf(ss + 1e-6f);
    v.x *= f;
    v.y *= f;
    *reinterpret_cast<float2*>(qkv + base + lane * 2) = v;
}

// ---------------- Tensor-core flash attention (R3-proven version) ----------------
__global__ void __launch_bounds__(128) attention_tc_kernel(const float* __restrict__ qkv,
                                                           float* __restrict__ o)
{
    __shared__ __align__(16) char qk_raw[64 * 68 * 4];
    float (*Qs)[68] = reinterpret_cast<float(*)[68]>(qk_raw);
    unsigned (*KsB)[68] = reinterpret_cast<unsigned(*)[68]>(qk_raw);
    unsigned (*KsS)[68] = reinterpret_cast<unsigned(*)[68]>(qk_raw + 32 * 68 * 4);
    __shared__ unsigned Vs[32][72];
    __shared__ unsigned Ps[64][36];

    int tid = threadIdx.x;
    int warp = tid >> 5, lane = tid & 31;
    int g = lane >> 2, t = lane & 3;
    int wm = warp * 16;
    int q0 = blockIdx.x * 64;
    int h = blockIdx.y, b = blockIdx.z;
    const float* qbase = qkv + (size_t)b * L_SEQ * 3072 + h * 64;
    const float* kbase = qbase + 1024;
    const float* vbase = qbase + 2048;

#pragma unroll
    for (int j = 0; j < 8; j++) {
        int idx = tid + 128 * j;
        int r = idx >> 4, seg = idx & 15;
        float4 v = *reinterpret_cast<const float4*>(qbase + (size_t)(q0 + r) * 3072 + seg * 4);
        *reinterpret_cast<float4*>(&Qs[r][seg * 4]) = v;
    }
    __syncthreads();

    unsigned qb[32], qs[32];
#pragma unroll
    for (int k0 = 0; k0 < 8; k0++) {
        float qa[4];
        qa[0] = Qs[wm + g][k0 * 8 + t];
        qa[1] = Qs[wm + g + 8][k0 * 8 + t];
        qa[2] = Qs[wm + g][k0 * 8 + t + 4];
        qa[3] = Qs[wm + g + 8][k0 * 8 + t + 4];
#pragma unroll
        for (int i = 0; i < 4; i++) {
            unsigned big = f2tf32(qa[i]);
            qb[k0 * 4 + i] = big;
            qs[k0 * 4 + i] = f2tf32(qa[i] - __uint_as_float(big));
        }
    }

    float oacc[8][4] = {};
    float mrow[2] = {-1e30f, -1e30f};
    float lrow[2] = {0.f, 0.f};

    for (int kb = 0; kb < L_SEQ / 32; kb++) {
        __syncthreads();
#pragma unroll
        for (int j = 0; j < 4; j++) {
            int idx = tid + 128 * j;
            int r = idx >> 4, seg = idx & 15;
            size_t moff = (size_t)(kb * 32 + r) * 3072 + seg * 4;
            float4 k4 = *reinterpret_cast<const float4*>(kbase + moff);
            unsigned b0 = f2tf32(k4.x), b1 = f2tf32(k4.y);
            unsigned b2 = f2tf32(k4.z), b3 = f2tf32(k4.w);
            KsB[r][seg * 4 + 0] = b0; KsB[r][seg * 4 + 1] = b1;
            KsB[r][seg * 4 + 2] = b2; KsB[r][seg * 4 + 3] = b3;
            KsS[r][seg * 4 + 0] = f2tf32(k4.x - __uint_as_float(b0));
            KsS[r][seg * 4 + 1] = f2tf32(k4.y - __uint_as_float(b1));
            KsS[r][seg * 4 + 2] = f2tf32(k4.z - __uint_as_float(b2));
            KsS[r][seg * 4 + 3] = f2tf32(k4.w - __uint_as_float(b3));
            float4 v4 = *reinterpret_cast<const float4*>(vbase + moff);
            uint4 u;
            u.x = f2tf32(v4.x); u.y = f2tf32(v4.y);
            u.z = f2tf32(v4.z); u.w = f2tf32(v4.w);
            *reinterpret_cast<uint4*>(&Vs[r][seg * 4]) = u;
        }
        __syncthreads();

        float sacc[4][4] = {};
#pragma unroll
        for (int k0 = 0; k0 < 8; k0++) {
            const unsigned* qbp = qb + k0 * 4;
            const unsigned* qsp = qs + k0 * 4;
#pragma unroll
            for (int ni = 0; ni < 4; ni++) {
                unsigned kb0 = KsB[ni * 8 + g][k0 * 8 + t];
                unsigned kb1 = KsB[ni * 8 + g][k0 * 8 + t + 4];
                unsigned ks0 = KsS[ni * 8 + g][k0 * 8 + t];
                unsigned ks1 = KsS[ni * 8 + g][k0 * 8 + t + 4];
#define MMA_S(A0,A1,A2,A3,B0,B1) \
                asm volatile("mma.sync.aligned.m16n8k8.row.col.f32.tf32.tf32.f32 " \
                    "{%0,%1,%2,%3}, {%4,%5,%6,%7}, {%8,%9}, {%0,%1,%2,%3};" \
                    : "+f"(sacc[ni][0]), "+f"(sacc[ni][1]), "+f"(sacc[ni][2]), "+f"(sacc[ni][3]) \
                    : "r"(A0), "r"(A1), "r"(A2), "r"(A3), "r"(B0), "r"(B1))
                MMA_S(qbp[0], qbp[1], qbp[2], qbp[3], kb0, kb1);
                MMA_S(qbp[0], qbp[1], qbp[2], qbp[3], ks0, ks1);
                MMA_S(qsp[0], qsp[1], qsp[2], qsp[3], kb0, kb1);
#undef MMA_S
            }
        }

        float ml0 = -1e30f, ml1 = -1e30f;
#pragma unroll
        for (int ni = 0; ni < 4; ni++) {
            ml0 = fmaxf(ml0, fmaxf(sacc[ni][0], sacc[ni][1]));
            ml1 = fmaxf(ml1, fmaxf(sacc[ni][2], sacc[ni][3]));
        }
#pragma unroll
        for (int off = 1; off < 4; off <<= 1) {
            ml0 = fmaxf(ml0, __shfl_xor_sync(0xffffffffu, ml0, off));
            ml1 = fmaxf(ml1, __shfl_xor_sync(0xffffffffu, ml1, off));
        }
        float mn0 = fmaxf(mrow[0], ml0);
        float mn1 = fmaxf(mrow[1], ml1);
        float corr0 = fexp2((mrow[0] - mn0) * L2E);
        float corr1 = fexp2((mrow[1] - mn1) * L2E);
        mrow[0] = mn0; mrow[1] = mn1;

        float rs0 = 0.f, rs1 = 0.f;
#pragma unroll
        for (int ni = 0; ni < 4; ni++) {
            float p0 = fexp2((sacc[ni][0] - mn0) * L2E);
            float p1 = fexp2((sacc[ni][1] - mn0) * L2E);
            float p2 = fexp2((sacc[ni][2] - mn1) * L2E);
            float p3 = fexp2((sacc[ni][3] - mn1) * L2E);
            rs0 += p0 + p1;
            rs1 += p2 + p3;
            Ps[wm + g][ni * 8 + 2 * t] = f2tf32(p0);
            Ps[wm + g][ni * 8 + 2 * t + 1] = f2tf32(p1);
            Ps[wm + g + 8][ni * 8 + 2 * t] = f2tf32(p2);
            Ps[wm + g + 8][ni * 8 + 2 * t + 1] = f2tf32(p3);
        }
#pragma unroll
        for (int off = 1; off < 4; off <<= 1) {
            rs0 += __shfl_xor_sync(0xffffffffu, rs0, off);
            rs1 += __shfl_xor_sync(0xffffffffu, rs1, off);
        }
        lrow[0] = lrow[0] * corr0 + rs0;
        lrow[1] = lrow[1] * corr1 + rs1;
#pragma unroll
        for (int ni = 0; ni < 8; ni++) {
            oacc[ni][0] *= corr0; oacc[ni][1] *= corr0;
            oacc[ni][2] *= corr1; oacc[ni][3] *= corr1;
        }
        __syncwarp();

#pragma unroll
        for (int k0 = 0; k0 < 32; k0 += 8) {
            unsigned pa0 = Ps[wm + g][k0 + t];
            unsigned pa1 = Ps[wm + g + 8][k0 + t];
            unsigned pa2 = Ps[wm + g][k0 + t + 4];
            unsigned pa3 = Ps[wm + g + 8][k0 + t + 4];
#pragma unroll
            for (int ni = 0; ni < 8; ni++) {
                unsigned vb0 = Vs[k0 + t][ni * 8 + g];
                unsigned vb1 = Vs[k0 + t + 4][ni * 8 + g];
                asm volatile("mma.sync.aligned.m16n8k8.row.col.f32.tf32.tf32.f32 "
                    "{%0,%1,%2,%3}, {%4,%5,%6,%7}, {%8,%9}, {%0,%1,%2,%3};"
                    : "+f"(oacc[ni][0]), "+f"(oacc[ni][1]), "+f"(oacc[ni][2]), "+f"(oacc[ni][3])
                    : "r"(pa0), "r"(pa1), "r"(pa2), "r"(pa3), "r"(vb0), "r"(vb1));
            }
        }
        __syncwarp();
    }

    float inv0 = 1.0f / lrow[0];
    float inv1 = 1.0f / lrow[1];
    int row0 = b * L_SEQ + q0 + wm + g;
    int row1 = row0 + 8;
#pragma unroll
    for (int ni = 0; ni < 8; ni++) {
        int col = h * 64 + ni * 8 + 2 * t;
        float2 r0 = make_float2(oacc[ni][0] * inv0, oacc[ni][1] * inv0);
        float2 r1 = make_float2(oacc[ni][2] * inv1, oacc[ni][3] * inv1);
        *reinterpret_cast<float2*>(o + (size_t)row0 * DMODEL + col) = r0;
        *reinterpret_cast<float2*>(o + (size_t)row1 * DMODEL + col) = r1;
    }
}

// ---------------- SwiGLU ----------------
__global__ void __launch_bounds__(256) swiglu_kernel(const float* __restrict__ u,
                                                     float* __restrict__ h)
{
    int idx = blockIdx.x * blockDim.x + threadIdx.x;
    int m = idx / (DFF / 4);
    int j = idx % (DFF / 4);
    const float4* ur = reinterpret_cast<const float4*>(u) + (size_t)m * (2 * DFF / 4);
    float4 a = ur[j];
    float4 g = ur[DFF / 4 + j];
    float4 r;
    r.x = a.x * g.x / (1.f + fexp2(-g.x * L2E));
    r.y = a.y * g.y / (1.f + fexp2(-g.y * L2E));
    r.z = a.z * g.z / (1.f + fexp2(-g.z * L2E));
    r.w = a.w * g.w / (1.f + fexp2(-g.w * L2E));
    reinterpret_cast<float4*>(h)[idx] = r;
}

extern "C" void kernel_launch(void* const* d_in, const int* in_sizes, int n_in,
                              void* d_out, int out_size)
{
    const float* x          = (const float*)d_in[0];
    const float* norm_scale = (const float*)d_in[2];
    const float* w_qkv      = (const float*)d_in[3];
    const float* attn_scale = (const float*)d_in[4];
    const float* w_out      = (const float*)d_in[5];
    const float* ff_scale   = (const float*)d_in[6];
    const float* w_up       = (const float*)d_in[7];
    const float* w_down     = (const float*)d_in[8];
    float* out = (float*)d_out;

    float *xn, *qkvp, *op, *up, *hp;
    cudaGetSymbolAddress((void**)&xn, g_xn);
    cudaGetSymbolAddress((void**)&qkvp, g_qkv);
    cudaGetSymbolAddress((void**)&op, g_o);
    cudaGetSymbolAddress((void**)&up, g_u);
    cudaGetSymbolAddress((void**)&hp, g_h);

    rmsnorm_kernel<<<MTOT, 256>>>(x, norm_scale, xn);
    gemm_tf32_kernel<<<dim3(3 * DMODEL / 128, MTOT / 128), 256>>>(xn, w_qkv, nullptr, qkvp, 3 * DMODEL, DMODEL);
    qknorm_kernel<<<MTOT * 32 / 8, 256>>>(qkvp, attn_scale);
    attention_tc_kernel<<<dim3(L_SEQ / 64, NHEAD, BATCH), 128>>>(qkvp, op);
    gemm_tf32_kernel<<<dim3(DMODEL / 128, MTOT / 128), 256>>>(op, w_out, x, out, DMODEL, DMODEL);
    rmsnorm_kernel<<<MTOT, 256>>>(out, ff_scale, xn);
    gemm_tf32_kernel<<<dim3(2 * DFF / 128, MTOT / 128), 256>>>(xn, w_up, nullptr, up, 2 * DFF, DMODEL);
    swiglu_kernel<<<MTOT * DFF / 4 / 256, 256>>>(up, hp);
    gemm_tf32_kernel<<<dim3(DMODEL / 128, MTOT / 128), 256>>>(hp, w_down, out, out, DMODEL, DFF);
}

// round 10
// speedup vs baseline: 1.3505x; 1.0367x over previous
#include <cuda_runtime.h>
#include <cstdint>

#define L_SEQ 2048
#define BATCH 2
#define DMODEL 1024
#define NHEAD 16
#define DHEAD 64
#define DFF 3072
#define MTOT (BATCH * L_SEQ) /* 4096 */

// -------- scratch (device globals: allocation-free rule) --------
__device__ float g_xn[MTOT * DMODEL];
__device__ float g_qkv[MTOT * 3 * DMODEL];
__device__ float g_o[MTOT * DMODEL];
__device__ float g_u[MTOT * 2 * DFF];
__device__ float g_h[MTOT * DFF];

__device__ __forceinline__ unsigned f2tf32(float f) {
    unsigned r;
    asm("cvt.rna.tf32.f32 %0, %1;" : "=r"(r) : "f"(f));
    return r;
}

// FFMA-only 2^y (no MUFU).
__device__ __forceinline__ float fexp2(float y) {
    y = fmaxf(fminf(y, 120.f), -120.f);
    float z = y + 12582912.f;                 // 1.5*2^23
    int n = __float_as_int(z) - 0x4B400000;   // round(y)
    float f = y - (z - 12582912.f);           // y - n in [-0.5, 0.5]
    float p = 0.0013333558f;
    p = fmaf(p, f, 0.0096181291f);
    p = fmaf(p, f, 0.0555041087f);
    p = fmaf(p, f, 0.2402265070f);
    p = fmaf(p, f, 0.6931471806f);
    p = fmaf(p, f, 1.0f);
    return __int_as_float((n + 127) << 23) * p;
}
#define L2E 1.4426950408889634f

__device__ __forceinline__ void ldsm4(unsigned& r0, unsigned& r1, unsigned& r2, unsigned& r3,
                                      const void* p)
{
    unsigned a = (unsigned)__cvta_generic_to_shared(p);
    asm volatile("ldmatrix.sync.aligned.m8n8.x4.shared.b16 {%0,%1,%2,%3}, [%4];"
                 : "=r"(r0), "=r"(r1), "=r"(r2), "=r"(r3) : "r"(a));
}
__device__ __forceinline__ void ldsm2(unsigned& r0, unsigned& r1, const void* p)
{
    unsigned a = (unsigned)__cvta_generic_to_shared(p);
    asm volatile("ldmatrix.sync.aligned.m8n8.x2.shared.b16 {%0,%1}, [%2];"
                 : "=r"(r0), "=r"(r1) : "r"(a));
}

// ---------------- RMSNorm ----------------
__global__ void __launch_bounds__(256) rmsnorm_kernel(const float* __restrict__ x,
                                                      const float* __restrict__ scale,
                                                      float* __restrict__ out)
{
    int row = blockIdx.x;
    int t = threadIdx.x;
    const float4* xr = reinterpret_cast<const float4*>(x) + (size_t)row * (DMODEL / 4);
    float4 v = xr[t];
    float ss = v.x * v.x + v.y * v.y + v.z * v.z + v.w * v.w;
#pragma unroll
    for (int o = 16; o; o >>= 1) ss += __shfl_xor_sync(0xffffffffu, ss, o);
    __shared__ float ws[8];
    if ((t & 31) == 0) ws[t >> 5] = ss;
    __syncthreads();
    float tot = 0.f;
#pragma unroll
    for (int i = 0; i < 8; i++) tot += ws[i];
    float inv = rsqrtf(tot * (1.0f / DMODEL) + 1e-6f);
    float4 s = reinterpret_cast<const float4*>(scale)[t];
    float4 r;
    r.x = v.x * s.x * inv;
    r.y = v.y * s.y * inv;
    r.z = v.z * s.z * inv;
    r.w = v.w * s.w * inv;
    (reinterpret_cast<float4*>(out) + (size_t)row * (DMODEL / 4))[t] = r;
}

// ---------------- TF32 GEMM NT: ldmatrix fragments + double-buffered smem ----------------
#define BKK 16
#define LDA 20
__global__ void __launch_bounds__(256, 2) gemm_tf32_kernel(const float* __restrict__ A,
                                                           const float* __restrict__ B,
                                                           const float* resid,
                                                           float* __restrict__ C,
                                                           int N, int K)
{
    __shared__ unsigned As[2][128][LDA];
    __shared__ unsigned Bs[2][128][LDA];
    int tid = threadIdx.x;
    int warp = tid >> 5, lane = tid & 31;
    int g = lane >> 2, t = lane & 3;
    int m0 = blockIdx.y * 128, n0 = blockIdx.x * 128;
    int wm = (warp >> 2) * 64;
    int wn = (warp & 3) * 32;

    int arow = wm + (lane & 15);
    int acol = (lane >> 4) * 4;
    int brow = wn + (lane & 7);
    int bcol = ((lane >> 3) & 1) * 4;

    int lm = tid >> 1;
    int lk = (tid & 1) * 8;
    const float* Ap = A + (size_t)(m0 + lm) * K + lk;
    const float* Bp = B + (size_t)(n0 + lm) * K + lk;

    float acc[4][4][4] = {};

    {
        float4 a0 = *reinterpret_cast<const float4*>(Ap);
        float4 a1 = *reinterpret_cast<const float4*>(Ap + 4);
        float4 b0 = *reinterpret_cast<const float4*>(Bp);
        float4 b1 = *reinterpret_cast<const float4*>(Bp + 4);
        uint4 ua0 = make_uint4(f2tf32(a0.x), f2tf32(a0.y), f2tf32(a0.z), f2tf32(a0.w));
        uint4 ua1 = make_uint4(f2tf32(a1.x), f2tf32(a1.y), f2tf32(a1.z), f2tf32(a1.w));
        uint4 ub0 = make_uint4(f2tf32(b0.x), f2tf32(b0.y), f2tf32(b0.z), f2tf32(b0.w));
        uint4 ub1 = make_uint4(f2tf32(b1.x), f2tf32(b1.y), f2tf32(b1.z), f2tf32(b1.w));
        *reinterpret_cast<uint4*>(&As[0][lm][lk]) = ua0;
        *reinterpret_cast<uint4*>(&As[0][lm][lk + 4]) = ua1;
        *reinterpret_cast<uint4*>(&Bs[0][lm][lk]) = ub0;
        *reinterpret_cast<uint4*>(&Bs[0][lm][lk + 4]) = ub1;
    }
    __syncthreads();

    int cur = 0;
    for (int kt = 0; kt < K; kt += BKK) {
        bool has_next = (kt + BKK < K);
        float4 a0, a1, b0, b1;
        if (has_next) {
            a0 = *reinterpret_cast<const float4*>(Ap + kt + BKK);
            a1 = *reinterpret_cast<const float4*>(Ap + kt + BKK + 4);
            b0 = *reinterpret_cast<const float4*>(Bp + kt + BKK);
            b1 = *reinterpret_cast<const float4*>(Bp + kt + BKK + 4);
        }

#pragma unroll
        for (int ks = 0; ks < BKK; ks += 8) {
            unsigned af[4][4], bf[4][2];
#pragma unroll
            for (int mi = 0; mi < 4; mi++)
                ldsm4(af[mi][0], af[mi][1], af[mi][2], af[mi][3],
                      &As[cur][arow + mi * 16][ks + acol]);
#pragma unroll
            for (int ni = 0; ni < 4; ni++)
                ldsm2(bf[ni][0], bf[ni][1], &Bs[cur][brow + ni * 8][ks + bcol]);
#pragma unroll
            for (int mi = 0; mi < 4; mi++)
#pragma unroll
                for (int ni = 0; ni < 4; ni++) {
                    asm volatile(
                        "mma.sync.aligned.m16n8k8.row.col.f32.tf32.tf32.f32 "
                        "{%0,%1,%2,%3}, {%4,%5,%6,%7}, {%8,%9}, {%0,%1,%2,%3};"
                        : "+f"(acc[mi][ni][0]), "+f"(acc[mi][ni][1]),
                          "+f"(acc[mi][ni][2]), "+f"(acc[mi][ni][3])
                        : "r"(af[mi][0]), "r"(af[mi][1]), "r"(af[mi][2]), "r"(af[mi][3]),
                          "r"(bf[ni][0]), "r"(bf[ni][1]));
                }
        }

        if (has_next) {
            int nxt = cur ^ 1;
            uint4 ua0 = make_uint4(f2tf32(a0.x), f2tf32(a0.y), f2tf32(a0.z), f2tf32(a0.w));
            uint4 ua1 = make_uint4(f2tf32(a1.x), f2tf32(a1.y), f2tf32(a1.z), f2tf32(a1.w));
            uint4 ub0 = make_uint4(f2tf32(b0.x), f2tf32(b0.y), f2tf32(b0.z), f2tf32(b0.w));
            uint4 ub1 = make_uint4(f2tf32(b1.x), f2tf32(b1.y), f2tf32(b1.z), f2tf32(b1.w));
            *reinterpret_cast<uint4*>(&As[nxt][lm][lk]) = ua0;
            *reinterpret_cast<uint4*>(&As[nxt][lm][lk + 4]) = ua1;
            *reinterpret_cast<uint4*>(&Bs[nxt][lm][lk]) = ub0;
            *reinterpret_cast<uint4*>(&Bs[nxt][lm][lk + 4]) = ub1;
            __syncthreads();
            cur = nxt;
        }
    }

#pragma unroll
    for (int mi = 0; mi < 4; mi++) {
#pragma unroll
        for (int ni = 0; ni < 4; ni++) {
            int row0 = m0 + wm + mi * 16 + g;
            int col = n0 + wn + ni * 8 + 2 * t;
            size_t i0 = (size_t)row0 * N + col;
            size_t i1 = (size_t)(row0 + 8) * N + col;
            float2 v01 = make_float2(acc[mi][ni][0], acc[mi][ni][1]);
            float2 v23 = make_float2(acc[mi][ni][2], acc[mi][ni][3]);
            if (resid) {
                float2 r0 = *reinterpret_cast<const float2*>(resid + i0);
                float2 r1 = *reinterpret_cast<const float2*>(resid + i1);
                v01.x += r0.x; v01.y += r0.y;
                v23.x += r1.x; v23.y += r1.y;
            }
            *reinterpret_cast<float2*>(C + i0) = v01;
            *reinterpret_cast<float2*>(C + i1) = v23;
        }
    }
}

// ---------------- QK cosine norm ----------------
__global__ void __launch_bounds__(256) qknorm_kernel(float* __restrict__ qkv,
                                                     const float* __restrict__ attn_scale)
{
    int warp = blockIdx.x * (blockDim.x >> 5) + (threadIdx.x >> 5);
    int lane = threadIdx.x & 31;
    int m = warp >> 5;
    int rest = warp & 31;
    int part = rest >> 4;
    int h = rest & 15;
    size_t base = (size_t)m * 3072 + part * 1024 + h * 64;
    float2 v = *reinterpret_cast<float2*>(qkv + base + lane * 2);
    float ss = v.x * v.x + v.y * v.y;
#pragma unroll
    for (int o = 16; o; o >>= 1) ss += __shfl_xor_sync(0xffffffffu, ss, o);
    float f = sqrtf(attn_scale[h]) * rsqrtf(ss + 1e-6f);
    v.x *= f;
    v.y *= f;
    *reinterpret_cast<float2*>(qkv + base + lane * 2) = v;
}

// ---------------- Tensor-core flash attention v4 ----------------
// 2-mma K-split compensation (s = qb·kb + qb·ks = qb·k; error = qs·k ~ 3.5e-4):
// qs registers eliminated -> ~134 regs -> 3 CTAs/SM. ldmatrix K fragment loads.
__global__ void __launch_bounds__(128, 3) attention_tc_kernel(const float* __restrict__ qkv,
                                                              float* __restrict__ o)
{
    __shared__ __align__(16) char qk_raw[64 * 68 * 4];
    float (*Qs)[68] = reinterpret_cast<float(*)[68]>(qk_raw);
    unsigned (*KsB)[68] = reinterpret_cast<unsigned(*)[68]>(qk_raw);
    unsigned (*KsS)[68] = reinterpret_cast<unsigned(*)[68]>(qk_raw + 32 * 68 * 4);
    __shared__ unsigned Vs[32][72];
    __shared__ unsigned Ps[64][36];

    int tid = threadIdx.x;
    int warp = tid >> 5, lane = tid & 31;
    int g = lane >> 2, t = lane & 3;
    int wm = warp * 16;
    int q0 = blockIdx.x * 64;
    int h = blockIdx.y, b = blockIdx.z;
    const float* qbase = qkv + (size_t)b * L_SEQ * 3072 + h * 64;
    const float* kbase = qbase + 1024;
    const float* vbase = qbase + 2048;

    // ldmatrix coords for K fragments (B-fragment pattern, verified in GEMM)
    int krow = lane & 7;
    int kcol = ((lane >> 3) & 1) * 4;

    // stage Q tile 64x64
#pragma unroll
    for (int j = 0; j < 8; j++) {
        int idx = tid + 128 * j;
        int r = idx >> 4, seg = idx & 15;
        float4 v = *reinterpret_cast<const float4*>(qbase + (size_t)(q0 + r) * 3072 + seg * 4);
        *reinterpret_cast<float4*>(&Qs[r][seg * 4]) = v;
    }
    __syncthreads();

    // hoist Q fragments, single tf32 conversion (no small part needed)
    unsigned qb[32];
#pragma unroll
    for (int k0 = 0; k0 < 8; k0++) {
        qb[k0 * 4 + 0] = f2tf32(Qs[wm + g][k0 * 8 + t]);
        qb[k0 * 4 + 1] = f2tf32(Qs[wm + g + 8][k0 * 8 + t]);
        qb[k0 * 4 + 2] = f2tf32(Qs[wm + g][k0 * 8 + t + 4]);
        qb[k0 * 4 + 3] = f2tf32(Qs[wm + g + 8][k0 * 8 + t + 4]);
    }

    float oacc[8][4] = {};
    float mrow[2] = {-1e30f, -1e30f};
    float lrow[2] = {0.f, 0.f};

    for (int kb = 0; kb < L_SEQ / 32; kb++) {
        __syncthreads();  // prev PV done; guards Q-extract on iter 0
#pragma unroll
        for (int j = 0; j < 4; j++) {
            int idx = tid + 128 * j;
            int r = idx >> 4, seg = idx & 15;
            size_t moff = (size_t)(kb * 32 + r) * 3072 + seg * 4;
            float4 k4 = *reinterpret_cast<const float4*>(kbase + moff);
            uint4 ukb = make_uint4(f2tf32(k4.x), f2tf32(k4.y), f2tf32(k4.z), f2tf32(k4.w));
            uint4 uks = make_uint4(f2tf32(k4.x - __uint_as_float(ukb.x)),
                                   f2tf32(k4.y - __uint_as_float(ukb.y)),
                                   f2tf32(k4.z - __uint_as_float(ukb.z)),
                                   f2tf32(k4.w - __uint_as_float(ukb.w)));
            *reinterpret_cast<uint4*>(&KsB[r][seg * 4]) = ukb;
            *reinterpret_cast<uint4*>(&KsS[r][seg * 4]) = uks;
            float4 v4 = *reinterpret_cast<const float4*>(vbase + moff);
            uint4 uv = make_uint4(f2tf32(v4.x), f2tf32(v4.y), f2tf32(v4.z), f2tf32(v4.w));
            *reinterpret_cast<uint4*>(&Vs[r][seg * 4]) = uv;
        }
        __syncthreads();

        // ---- S = qb·(kb + ks) = qb·k  (2 mmas, K-split compensation) ----
        float sacc[4][4] = {};
#pragma unroll
        for (int k0 = 0; k0 < 8; k0++) {
            const unsigned* qbp = qb + k0 * 4;
#pragma unroll
            for (int ni = 0; ni < 4; ni++) {
                unsigned kb0, kb1, ks0, ks1;
                ldsm2(kb0, kb1, &KsB[ni * 8 + krow][k0 * 8 + kcol]);
                ldsm2(ks0, ks1, &KsS[ni * 8 + krow][k0 * 8 + kcol]);
#define MMA_S(A0,A1,A2,A3,B0,B1) \
                asm volatile("mma.sync.aligned.m16n8k8.row.col.f32.tf32.tf32.f32 " \
                    "{%0,%1,%2,%3}, {%4,%5,%6,%7}, {%8,%9}, {%0,%1,%2,%3};" \
                    : "+f"(sacc[ni][0]), "+f"(sacc[ni][1]), "+f"(sacc[ni][2]), "+f"(sacc[ni][3]) \
                    : "r"(A0), "r"(A1), "r"(A2), "r"(A3), "r"(B0), "r"(B1))
                MMA_S(qbp[0], qbp[1], qbp[2], qbp[3], kb0, kb1);
                MMA_S(qbp[0], qbp[1], qbp[2], qbp[3], ks0, ks1);
#undef MMA_S
            }
        }

        // ---- online softmax ----
        float ml0 = -1e30f, ml1 = -1e30f;
#pragma unroll
        for (int ni = 0; ni < 4; ni++) {
            ml0 = fmaxf(ml0, fmaxf(sacc[ni][0], sacc[ni][1]));
            ml1 = fmaxf(ml1, fmaxf(sacc[ni][2], sacc[ni][3]));
        }
#pragma unroll
        for (int off = 1; off < 4; off <<= 1) {
            ml0 = fmaxf(ml0, __shfl_xor_sync(0xffffffffu, ml0, off));
            ml1 = fmaxf(ml1, __shfl_xor_sync(0xffffffffu, ml1, off));
        }
        float mn0 = fmaxf(mrow[0], ml0);
        float mn1 = fmaxf(mrow[1], ml1);
        float corr0 = fexp2((mrow[0] - mn0) * L2E);
        float corr1 = fexp2((mrow[1] - mn1) * L2E);
        mrow[0] = mn0; mrow[1] = mn1;

        float rs0 = 0.f, rs1 = 0.f;
#pragma unroll
        for (int ni = 0; ni < 4; ni++) {
            float p0 = fexp2((sacc[ni][0] - mn0) * L2E);
            float p1 = fexp2((sacc[ni][1] - mn0) * L2E);
            float p2 = fexp2((sacc[ni][2] - mn1) * L2E);
            float p3 = fexp2((sacc[ni][3] - mn1) * L2E);
            rs0 += p0 + p1;
            rs1 += p2 + p3;
            *reinterpret_cast<uint2*>(&Ps[wm + g][ni * 8 + 2 * t]) =
                make_uint2(f2tf32(p0), f2tf32(p1));
            *reinterpret_cast<uint2*>(&Ps[wm + g + 8][ni * 8 + 2 * t]) =
                make_uint2(f2tf32(p2), f2tf32(p3));
        }
#pragma unroll
        for (int off = 1; off < 4; off <<= 1) {
            rs0 += __shfl_xor_sync(0xffffffffu, rs0, off);
            rs1 += __shfl_xor_sync(0xffffffffu, rs1, off);
        }
        lrow[0] = lrow[0] * corr0 + rs0;
        lrow[1] = lrow[1] * corr1 + rs1;
#pragma unroll
        for (int ni = 0; ni < 8; ni++) {
            oacc[ni][0] *= corr0; oacc[ni][1] *= corr0;
            oacc[ni][2] *= corr1; oacc[ni][3] *= corr1;
        }
        __syncwarp();  // Ps warp-private

        // ---- O += P V ----
#pragma unroll
        for (int k0 = 0; k0 < 32; k0 += 8) {
            unsigned pa0 = Ps[wm + g][k0 + t];
            unsigned pa1 = Ps[wm + g + 8][k0 + t];
            unsigned pa2 = Ps[wm + g][k0 + t + 4];
            unsigned pa3 = Ps[wm + g + 8][k0 + t + 4];
#pragma unroll
            for (int ni = 0; ni < 8; ni++) {
                unsigned vb0 = Vs[k0 + t][ni * 8 + g];
                unsigned vb1 = Vs[k0 + t + 4][ni * 8 + g];
                asm volatile("mma.sync.aligned.m16n8k8.row.col.f32.tf32.tf32.f32 "
                    "{%0,%1,%2,%3}, {%4,%5,%6,%7}, {%8,%9}, {%0,%1,%2,%3};"
                    : "+f"(oacc[ni][0]), "+f"(oacc[ni][1]), "+f"(oacc[ni][2]), "+f"(oacc[ni][3])
                    : "r"(pa0), "r"(pa1), "r"(pa2), "r"(pa3), "r"(vb0), "r"(vb1));
            }
        }
        __syncwarp();
    }

    float inv0 = 1.0f / lrow[0];
    float inv1 = 1.0f / lrow[1];
    int row0 = b * L_SEQ + q0 + wm + g;
    int row1 = row0 + 8;
#pragma unroll
    for (int ni = 0; ni < 8; ni++) {
        int col = h * 64 + ni * 8 + 2 * t;
        float2 r0 = make_float2(oacc[ni][0] * inv0, oacc[ni][1] * inv0);
        float2 r1 = make_float2(oacc[ni][2] * inv1, oacc[ni][3] * inv1);
        *reinterpret_cast<float2*>(o + (size_t)row0 * DMODEL + col) = r0;
        *reinterpret_cast<float2*>(o + (size_t)row1 * DMODEL + col) = r1;
    }
}

// ---------------- SwiGLU ----------------
__global__ void __launch_bounds__(256) swiglu_kernel(const float* __restrict__ u,
                                                     float* __restrict__ h)
{
    int idx = blockIdx.x * blockDim.x + threadIdx.x;
    int m = idx / (DFF / 4);
    int j = idx % (DFF / 4);
    const float4* ur = reinterpret_cast<const float4*>(u) + (size_t)m * (2 * DFF / 4);
    float4 a = ur[j];
    float4 g = ur[DFF / 4 + j];
    float4 r;
    r.x = a.x * g.x / (1.f + fexp2(-g.x * L2E));
    r.y = a.y * g.y / (1.f + fexp2(-g.y * L2E));
    r.z = a.z * g.z / (1.f + fexp2(-g.z * L2E));
    r.w = a.w * g.w / (1.f + fexp2(-g.w * L2E));
    reinterpret_cast<float4*>(h)[idx] = r;
}

extern "C" void kernel_launch(void* const* d_in, const int* in_sizes, int n_in,
                              void* d_out, int out_size)
{
    const float* x          = (const float*)d_in[0];
    const float* norm_scale = (const float*)d_in[2];
    const float* w_qkv      = (const float*)d_in[3];
    const float* attn_scale = (const float*)d_in[4];
    const float* w_out      = (const float*)d_in[5];
    const float* ff_scale   = (const float*)d_in[6];
    const float* w_up       = (const float*)d_in[7];
    const float* w_down     = (const float*)d_in[8];
    float* out = (float*)d_out;

    float *xn, *qkvp, *op, *up, *hp;
    cudaGetSymbolAddress((void**)&xn, g_xn);
    cudaGetSymbolAddress((void**)&qkvp, g_qkv);
    cudaGetSymbolAddress((void**)&op, g_o);
    cudaGetSymbolAddress((void**)&up, g_u);
    cudaGetSymbolAddress((void**)&hp, g_h);

    rmsnorm_kernel<<<MTOT, 256>>>(x, norm_scale, xn);
    gemm_tf32_kernel<<<dim3(3 * DMODEL / 128, MTOT / 128), 256>>>(xn, w_qkv, nullptr, qkvp, 3 * DMODEL, DMODEL);
    qknorm_kernel<<<MTOT * 32 / 8, 256>>>(qkvp, attn_scale);
    attention_tc_kernel<<<dim3(L_SEQ / 64, NHEAD, BATCH), 128>>>(qkvp, op);
    gemm_tf32_kernel<<<dim3(DMODEL / 128, MTOT / 128), 256>>>(op, w_out, x, out, DMODEL, DMODEL);
    rmsnorm_kernel<<<MTOT, 256>>>(out, ff_scale, xn);
    gemm_tf32_kernel<<<dim3(2 * DFF / 128, MTOT / 128), 256>>>(xn, w_up, nullptr, up, 2 * DFF, DMODEL);
    swiglu_kernel<<<MTOT * DFF / 4 / 256, 256>>>(up, hp);
    gemm_tf32_kernel<<<dim3(DMODEL / 128, MTOT / 128), 256>>>(hp, w_down, out, out, DMODEL, DFF);
}

// round 12
// speedup vs baseline: 1.6311x; 1.2077x over previous
#include <cuda_runtime.h>
#include <cuda_fp16.h>
#include <cstdint>

#define L_SEQ 2048
#define BATCH 2
#define DMODEL 1024
#define NHEAD 16
#define DHEAD 64
#define DFF 3072
#define MTOT (BATCH * L_SEQ) /* 4096 */

// -------- scratch (device globals: allocation-free rule) --------
__device__ float g_xn[MTOT * DMODEL];
__device__ float g_qkv[MTOT * 3 * DMODEL];
__device__ float g_o[MTOT * DMODEL];
__device__ float g_u[MTOT * 2 * DFF];
__device__ float g_h[MTOT * DFF];

__device__ __forceinline__ unsigned f2tf32(float f) {
    unsigned r;
    asm("cvt.rna.tf32.f32 %0, %1;" : "=r"(r) : "f"(f));
    return r;
}

// pack two f32 -> f16x2 (lo in low half)
__device__ __forceinline__ unsigned packh(float lo, float hi) {
    unsigned r;
    asm("cvt.rn.f16x2.f32 %0, %1, %2;" : "=r"(r) : "f"(hi), "f"(lo));
    return r;
}

// FFMA-only 2^y (no MUFU).
__device__ __forceinline__ float fexp2(float y) {
    y = fmaxf(fminf(y, 120.f), -120.f);
    float z = y + 12582912.f;                 // 1.5*2^23
    int n = __float_as_int(z) - 0x4B400000;   // round(y)
    float f = y - (z - 12582912.f);           // y - n in [-0.5, 0.5]
    float p = 0.0013333558f;
    p = fmaf(p, f, 0.0096181291f);
    p = fmaf(p, f, 0.0555041087f);
    p = fmaf(p, f, 0.2402265070f);
    p = fmaf(p, f, 0.6931471806f);
    p = fmaf(p, f, 1.0f);
    return __int_as_float((n + 127) << 23) * p;
}
#define L2E 1.4426950408889634f

__device__ __forceinline__ void ldsm4(unsigned& r0, unsigned& r1, unsigned& r2, unsigned& r3,
                                      const void* p)
{
    unsigned a = (unsigned)__cvta_generic_to_shared(p);
    asm volatile("ldmatrix.sync.aligned.m8n8.x4.shared.b16 {%0,%1,%2,%3}, [%4];"
                 : "=r"(r0), "=r"(r1), "=r"(r2), "=r"(r3) : "r"(a));
}
__device__ __forceinline__ void ldsm2(unsigned& r0, unsigned& r1, const void* p)
{
    unsigned a = (unsigned)__cvta_generic_to_shared(p);
    asm volatile("ldmatrix.sync.aligned.m8n8.x2.shared.b16 {%0,%1}, [%2];"
                 : "=r"(r0), "=r"(r1) : "r"(a));
}

// ---------------- RMSNorm ----------------
__global__ void __launch_bounds__(256) rmsnorm_kernel(const float* __restrict__ x,
                                                      const float* __restrict__ scale,
                                                      float* __restrict__ out)
{
    int row = blockIdx.x;
    int t = threadIdx.x;
    const float4* xr = reinterpret_cast<const float4*>(x) + (size_t)row * (DMODEL / 4);
    float4 v = xr[t];
    float ss = v.x * v.x + v.y * v.y + v.z * v.z + v.w * v.w;
#pragma unroll
    for (int o = 16; o; o >>= 1) ss += __shfl_xor_sync(0xffffffffu, ss, o);
    __shared__ float ws[8];
    if ((t & 31) == 0) ws[t >> 5] = ss;
    __syncthreads();
    float tot = 0.f;
#pragma unroll
    for (int i = 0; i < 8; i++) tot += ws[i];
    float inv = rsqrtf(tot * (1.0f / DMODEL) + 1e-6f);
    float4 s = reinterpret_cast<const float4*>(scale)[t];
    float4 r;
    r.x = v.x * s.x * inv;
    r.y = v.y * s.y * inv;
    r.z = v.z * s.z * inv;
    r.w = v.w * s.w * inv;
    (reinterpret_cast<float4*>(out) + (size_t)row * (DMODEL / 4))[t] = r;
}

// ---------------- FP16 GEMM NT: m16n8k16 mma, ldmatrix, double-buffered ----------------
// C[m,n] = sum_k A[m,k]*B[n,k] (+resid). 128x128 tile, BK=16, 8 warps, 64x32 warp tile.
// fp16-rn has the same 11-bit mantissa as tf32 -> identical error model, 2x K per mma.
// Smem [row][k-halves], stride 24 halves (12 words): 8-row LDSM phases bank-disjoint.
#define BKH 16
#define LDH 24
__global__ void __launch_bounds__(256, 2) gemm_f16_kernel(const float* __restrict__ A,
                                                          const float* __restrict__ B,
                                                          const float* resid,
                                                          float* __restrict__ C,
                                                          int N, int K)
{
    __shared__ unsigned short As[2][128][LDH];
    __shared__ unsigned short Bs[2][128][LDH];
    int tid = threadIdx.x;
    int warp = tid >> 5, lane = tid & 31;
    int g = lane >> 2, t = lane & 3;
    int m0 = blockIdx.y * 128, n0 = blockIdx.x * 128;
    int wm = (warp >> 2) * 64;
    int wn = (warp & 3) * 32;

    // ldmatrix per-lane source coords (halves)
    int arow = wm + (lane & 15);            // + mi*16
    int acol = (lane >> 4) * 8;             // k halves 0 or 8
    int brow = wn + (lane & 7);             // + ni*8
    int bcol = ((lane >> 3) & 1) * 8;

    int lm = tid >> 1;                      // row 0..127
    int lk = (tid & 1) * 8;                 // k offset (floats = halves)
    const float* Ap = A + (size_t)(m0 + lm) * K + lk;
    const float* Bp = B + (size_t)(n0 + lm) * K + lk;

    float acc[4][4][4] = {};

    // prologue: tile 0 -> buffer 0
    {
        float4 a0 = *reinterpret_cast<const float4*>(Ap);
        float4 a1 = *reinterpret_cast<const float4*>(Ap + 4);
        float4 b0 = *reinterpret_cast<const float4*>(Bp);
        float4 b1 = *reinterpret_cast<const float4*>(Bp + 4);
        uint4 ua = make_uint4(packh(a0.x, a0.y), packh(a0.z, a0.w),
                              packh(a1.x, a1.y), packh(a1.z, a1.w));
        uint4 ub = make_uint4(packh(b0.x, b0.y), packh(b0.z, b0.w),
                              packh(b1.x, b1.y), packh(b1.z, b1.w));
        *reinterpret_cast<uint4*>(&As[0][lm][lk]) = ua;
        *reinterpret_cast<uint4*>(&Bs[0][lm][lk]) = ub;
    }
    __syncthreads();

    int cur = 0;
    for (int kt = 0; kt < K; kt += BKH) {
        bool has_next = (kt + BKH < K);
        float4 a0, a1, b0, b1;
        if (has_next) {
            a0 = *reinterpret_cast<const float4*>(Ap + kt + BKH);
            a1 = *reinterpret_cast<const float4*>(Ap + kt + BKH + 4);
            b0 = *reinterpret_cast<const float4*>(Bp + kt + BKH);
            b1 = *reinterpret_cast<const float4*>(Bp + kt + BKH + 4);
        }

        // compute: one k16 step per tile
        {
            unsigned af[4][4], bf[4][2];
#pragma unroll
            for (int mi = 0; mi < 4; mi++)
                ldsm4(af[mi][0], af[mi][1], af[mi][2], af[mi][3],
                      &As[cur][arow + mi * 16][acol]);
#pragma unroll
            for (int ni = 0; ni < 4; ni++)
                ldsm2(bf[ni][0], bf[ni][1], &Bs[cur][brow + ni * 8][bcol]);
#pragma unroll
            for (int mi = 0; mi < 4; mi++)
#pragma unroll
                for (int ni = 0; ni < 4; ni++) {
                    asm volatile(
                        "mma.sync.aligned.m16n8k16.row.col.f32.f16.f16.f32 "
                        "{%0,%1,%2,%3}, {%4,%5,%6,%7}, {%8,%9}, {%0,%1,%2,%3};"
                        : "+f"(acc[mi][ni][0]), "+f"(acc[mi][ni][1]),
                          "+f"(acc[mi][ni][2]), "+f"(acc[mi][ni][3])
                        : "r"(af[mi][0]), "r"(af[mi][1]), "r"(af[mi][2]), "r"(af[mi][3]),
                          "r"(bf[ni][0]), "r"(bf[ni][1]));
                }
        }

        if (has_next) {
            int nxt = cur ^ 1;
            uint4 ua = make_uint4(packh(a0.x, a0.y), packh(a0.z, a0.w),
                                  packh(a1.x, a1.y), packh(a1.z, a1.w));
            uint4 ub = make_uint4(packh(b0.x, b0.y), packh(b0.z, b0.w),
                                  packh(b1.x, b1.y), packh(b1.z, b1.w));
            *reinterpret_cast<uint4*>(&As[nxt][lm][lk]) = ua;
            *reinterpret_cast<uint4*>(&Bs[nxt][lm][lk]) = ub;
            __syncthreads();
            cur = nxt;
        }
    }

#pragma unroll
    for (int mi = 0; mi < 4; mi++) {
#pragma unroll
        for (int ni = 0; ni < 4; ni++) {
            int row0 = m0 + wm + mi * 16 + g;
            int col = n0 + wn + ni * 8 + 2 * t;
            size_t i0 = (size_t)row0 * N + col;
            size_t i1 = (size_t)(row0 + 8) * N + col;
            float2 v01 = make_float2(acc[mi][ni][0], acc[mi][ni][1]);
            float2 v23 = make_float2(acc[mi][ni][2], acc[mi][ni][3]);
            if (resid) {
                float2 r0 = *reinterpret_cast<const float2*>(resid + i0);
                float2 r1 = *reinterpret_cast<const float2*>(resid + i1);
                v01.x += r0.x; v01.y += r0.y;
                v23.x += r1.x; v23.y += r1.y;
            }
            *reinterpret_cast<float2*>(C + i0) = v01;
            *reinterpret_cast<float2*>(C + i1) = v23;
        }
    }
}

// ---------------- QK cosine norm ----------------
__global__ void __launch_bounds__(256) qknorm_kernel(float* __restrict__ qkv,
                                                     const float* __restrict__ attn_scale)
{
    int warp = blockIdx.x * (blockDim.x >> 5) + (threadIdx.x >> 5);
    int lane = threadIdx.x & 31;
    int m = warp >> 5;
    int rest = warp & 31;
    int part = rest >> 4;
    int h = rest & 15;
    size_t base = (size_t)m * 3072 + part * 1024 + h * 64;
    float2 v = *reinterpret_cast<float2*>(qkv + base + lane * 2);
    float ss = v.x * v.x + v.y * v.y;
#pragma unroll
    for (int o = 16; o; o >>= 1) ss += __shfl_xor_sync(0xffffffffu, ss, o);
    float f = sqrtf(attn_scale[h]) * rsqrtf(ss + 1e-6f);
    v.x *= f;
    v.y *= f;
    *reinterpret_cast<float2*>(qkv + base + lane * 2) = v;
}

// ---------------- Tensor-core flash attention (R9-proven version) ----------------
__global__ void __launch_bounds__(128, 3) attention_tc_kernel(const float* __restrict__ qkv,
                                                              float* __restrict__ o)
{
    __shared__ __align__(16) char qk_raw[64 * 68 * 4];
    float (*Qs)[68] = reinterpret_cast<float(*)[68]>(qk_raw);
    unsigned (*KsB)[68] = reinterpret_cast<unsigned(*)[68]>(qk_raw);
    unsigned (*KsS)[68] = reinterpret_cast<unsigned(*)[68]>(qk_raw + 32 * 68 * 4);
    __shared__ unsigned Vs[32][72];
    __shared__ unsigned Ps[64][36];

    int tid = threadIdx.x;
    int warp = tid >> 5, lane = tid & 31;
    int g = lane >> 2, t = lane & 3;
    int wm = warp * 16;
    int q0 = blockIdx.x * 64;
    int h = blockIdx.y, b = blockIdx.z;
    const float* qbase = qkv + (size_t)b * L_SEQ * 3072 + h * 64;
    const float* kbase = qbase + 1024;
    const float* vbase = qbase + 2048;

    int krow = lane & 7;
    int kcol = ((lane >> 3) & 1) * 4;

#pragma unroll
    for (int j = 0; j < 8; j++) {
        int idx = tid + 128 * j;
        int r = idx >> 4, seg = idx & 15;
        float4 v = *reinterpret_cast<const float4*>(qbase + (size_t)(q0 + r) * 3072 + seg * 4);
        *reinterpret_cast<float4*>(&Qs[r][seg * 4]) = v;
    }
    __syncthreads();

    unsigned qb[32];
#pragma unroll
    for (int k0 = 0; k0 < 8; k0++) {
        qb[k0 * 4 + 0] = f2tf32(Qs[wm + g][k0 * 8 + t]);
        qb[k0 * 4 + 1] = f2tf32(Qs[wm + g + 8][k0 * 8 + t]);
        qb[k0 * 4 + 2] = f2tf32(Qs[wm + g][k0 * 8 + t + 4]);
        qb[k0 * 4 + 3] = f2tf32(Qs[wm + g + 8][k0 * 8 + t + 4]);
    }

    float oacc[8][4] = {};
    float mrow[2] = {-1e30f, -1e30f};
    float lrow[2] = {0.f, 0.f};

    for (int kb = 0; kb < L_SEQ / 32; kb++) {
        __syncthreads();
#pragma unroll
        for (int j = 0; j < 4; j++) {
            int idx = tid + 128 * j;
            int r = idx >> 4, seg = idx & 15;
            size_t moff = (size_t)(kb * 32 + r) * 3072 + seg * 4;
            float4 k4 = *reinterpret_cast<const float4*>(kbase + moff);
            uint4 ukb = make_uint4(f2tf32(k4.x), f2tf32(k4.y), f2tf32(k4.z), f2tf32(k4.w));
            uint4 uks = make_uint4(f2tf32(k4.x - __uint_as_float(ukb.x)),
                                   f2tf32(k4.y - __uint_as_float(ukb.y)),
                                   f2tf32(k4.z - __uint_as_float(ukb.z)),
                                   f2tf32(k4.w - __uint_as_float(ukb.w)));
            *reinterpret_cast<uint4*>(&KsB[r][seg * 4]) = ukb;
            *reinterpret_cast<uint4*>(&KsS[r][seg * 4]) = uks;
            float4 v4 = *reinterpret_cast<const float4*>(vbase + moff);
            uint4 uv = make_uint4(f2tf32(v4.x), f2tf32(v4.y), f2tf32(v4.z), f2tf32(v4.w));
            *reinterpret_cast<uint4*>(&Vs[r][seg * 4]) = uv;
        }
        __syncthreads();

        float sacc[4][4] = {};
#pragma unroll
        for (int k0 = 0; k0 < 8; k0++) {
            const unsigned* qbp = qb + k0 * 4;
#pragma unroll
            for (int ni = 0; ni < 4; ni++) {
                unsigned kb0, kb1, ks0, ks1;
                ldsm2(kb0, kb1, &KsB[ni * 8 + krow][k0 * 8 + kcol]);
                ldsm2(ks0, ks1, &KsS[ni * 8 + krow][k0 * 8 + kcol]);
#define MMA_S(A0,A1,A2,A3,B0,B1) \
                asm volatile("mma.sync.aligned.m16n8k8.row.col.f32.tf32.tf32.f32 " \
                    "{%0,%1,%2,%3}, {%4,%5,%6,%7}, {%8,%9}, {%0,%1,%2,%3};" \
                    : "+f"(sacc[ni][0]), "+f"(sacc[ni][1]), "+f"(sacc[ni][2]), "+f"(sacc[ni][3]) \
                    : "r"(A0), "r"(A1), "r"(A2), "r"(A3), "r"(B0), "r"(B1))
                MMA_S(qbp[0], qbp[1], qbp[2], qbp[3], kb0, kb1);
                MMA_S(qbp[0], qbp[1], qbp[2], qbp[3], ks0, ks1);
#undef MMA_S
            }
        }

        float ml0 = -1e30f, ml1 = -1e30f;
#pragma unroll
        for (int ni = 0; ni < 4; ni++) {
            ml0 = fmaxf(ml0, fmaxf(sacc[ni][0], sacc[ni][1]));
            ml1 = fmaxf(ml1, fmaxf(sacc[ni][2], sacc[ni][3]));
        }
#pragma unroll
        for (int off = 1; off < 4; off <<= 1) {
            ml0 = fmaxf(ml0, __shfl_xor_sync(0xffffffffu, ml0, off));
            ml1 = fmaxf(ml1, __shfl_xor_sync(0xffffffffu, ml1, off));
        }
        float mn0 = fmaxf(mrow[0], ml0);
        float mn1 = fmaxf(mrow[1], ml1);
        float corr0 = fexp2((mrow[0] - mn0) * L2E);
        float corr1 = fexp2((mrow[1] - mn1) * L2E);
        mrow[0] = mn0; mrow[1] = mn1;

        float rs0 = 0.f, rs1 = 0.f;
#pragma unroll
        for (int ni = 0; ni < 4; ni++) {
            float p0 = fexp2((sacc[ni][0] - mn0) * L2E);
            float p1 = fexp2((sacc[ni][1] - mn0) * L2E);
            float p2 = fexp2((sacc[ni][2] - mn1) * L2E);
            float p3 = fexp2((sacc[ni][3] - mn1) * L2E);
            rs0 += p0 + p1;
            rs1 += p2 + p3;
            *reinterpret_cast<uint2*>(&Ps[wm + g][ni * 8 + 2 * t]) =
                make_uint2(f2tf32(p0), f2tf32(p1));
            *reinterpret_cast<uint2*>(&Ps[wm + g + 8][ni * 8 + 2 * t]) =
                make_uint2(f2tf32(p2), f2tf32(p3));
        }
#pragma unroll
        for (int off = 1; off < 4; off <<= 1) {
            rs0 += __shfl_xor_sync(0xffffffffu, rs0, off);
            rs1 += __shfl_xor_sync(0xffffffffu, rs1, off);
        }
        lrow[0] = lrow[0] * corr0 + rs0;
        lrow[1] = lrow[1] * corr1 + rs1;
#pragma unroll
        for (int ni = 0; ni < 8; ni++) {
            oacc[ni][0] *= corr0; oacc[ni][1] *= corr0;
            oacc[ni][2] *= corr1; oacc[ni][3] *= corr1;
        }
        __syncwarp();

#pragma unroll
        for (int k0 = 0; k0 < 32; k0 += 8) {
            unsigned pa0 = Ps[wm + g][k0 + t];
            unsigned pa1 = Ps[wm + g + 8][k0 + t];
            unsigned pa2 = Ps[wm + g][k0 + t + 4];
            unsigned pa3 = Ps[wm + g + 8][k0 + t + 4];
#pragma unroll
            for (int ni = 0; ni < 8; ni++) {
                unsigned vb0 = Vs[k0 + t][ni * 8 + g];
                unsigned vb1 = Vs[k0 + t + 4][ni * 8 + g];
                asm volatile("mma.sync.aligned.m16n8k8.row.col.f32.tf32.tf32.f32 "
                    "{%0,%1,%2,%3}, {%4,%5,%6,%7}, {%8,%9}, {%0,%1,%2,%3};"
                    : "+f"(oacc[ni][0]), "+f"(oacc[ni][1]), "+f"(oacc[ni][2]), "+f"(oacc[ni][3])
                    : "r"(pa0), "r"(pa1), "r"(pa2), "r"(pa3), "r"(vb0), "r"(vb1));
            }
        }
        __syncwarp();
    }

    float inv0 = 1.0f / lrow[0];
    float inv1 = 1.0f / lrow[1];
    int row0 = b * L_SEQ + q0 + wm + g;
    int row1 = row0 + 8;
#pragma unroll
    for (int ni = 0; ni < 8; ni++) {
        int col = h * 64 + ni * 8 + 2 * t;
        float2 r0 = make_float2(oacc[ni][0] * inv0, oacc[ni][1] * inv0);
        float2 r1 = make_float2(oacc[ni][2] * inv1, oacc[ni][3] * inv1);
        *reinterpret_cast<float2*>(o + (size_t)row0 * DMODEL + col) = r0;
        *reinterpret_cast<float2*>(o + (size_t)row1 * DMODEL + col) = r1;
    }
}

// ---------------- SwiGLU ----------------
__global__ void __launch_bounds__(256) swiglu_kernel(const float* __restrict__ u,
                                                     float* __restrict__ h)
{
    int idx = blockIdx.x * blockDim.x + threadIdx.x;
    int m = idx / (DFF / 4);
    int j = idx % (DFF / 4);
    const float4* ur = reinterpret_cast<const float4*>(u) + (size_t)m * (2 * DFF / 4);
    float4 a = ur[j];
    float4 g = ur[DFF / 4 + j];
    float4 r;
    r.x = a.x * g.x / (1.f + fexp2(-g.x * L2E));
    r.y = a.y * g.y / (1.f + fexp2(-g.y * L2E));
    r.z = a.z * g.z / (1.f + fexp2(-g.z * L2E));
    r.w = a.w * g.w / (1.f + fexp2(-g.w * L2E));
    reinterpret_cast<float4*>(h)[idx] = r;
}

extern "C" void kernel_launch(void* const* d_in, const int* in_sizes, int n_in,
                              void* d_out, int out_size)
{
    const float* x          = (const float*)d_in[0];
    const float* norm_scale = (const float*)d_in[2];
    const float* w_qkv      = (const float*)d_in[3];
    const float* attn_scale = (const float*)d_in[4];
    const float* w_out      = (const float*)d_in[5];
    const float* ff_scale   = (const float*)d_in[6];
    const float* w_up       = (const float*)d_in[7];
    const float* w_down     = (const float*)d_in[8];
    float* out = (float*)d_out;

    float *xn, *qkvp, *op, *up, *hp;
    cudaGetSymbolAddress((void**)&xn, g_xn);
    cudaGetSymbolAddress((void**)&qkvp, g_qkv);
    cudaGetSymbolAddress((void**)&op, g_o);
    cudaGetSymbolAddress((void**)&up, g_u);
    cudaGetSymbolAddress((void**)&hp, g_h);

    rmsnorm_kernel<<<MTOT, 256>>>(x, norm_scale, xn);
    gemm_f16_kernel<<<dim3(3 * DMODEL / 128, MTOT / 128), 256>>>(xn, w_qkv, nullptr, qkvp, 3 * DMODEL, DMODEL);
    qknorm_kernel<<<MTOT * 32 / 8, 256>>>(qkvp, attn_scale);
    attention_tc_kernel<<<dim3(L_SEQ / 64, NHEAD, BATCH), 128>>>(qkvp, op);
    gemm_f16_kernel<<<dim3(DMODEL / 128, MTOT / 128), 256>>>(op, w_out, x, out, DMODEL, DMODEL);
    rmsnorm_kernel<<<MTOT, 256>>>(out, ff_scale, xn);
    gemm_f16_kernel<<<dim3(2 * DFF / 128, MTOT / 128), 256>>>(xn, w_up, nullptr, up, 2 * DFF, DMODEL);
    swiglu_kernel<<<MTOT * DFF / 4 / 256, 256>>>(up, hp);
    gemm_f16_kernel<<<dim3(DMODEL / 128, MTOT / 128), 256>>>(hp, w_down, out, out, DMODEL, DFF);
}

// round 13
// speedup vs baseline: 1.7688x; 1.0845x over previous
#include <cuda_runtime.h>
#include <cuda_fp16.h>
#include <cstdint>

#define L_SEQ 2048
#define BATCH 2
#define DMODEL 1024
#define NHEAD 16
#define DHEAD 64
#define DFF 3072
#define MTOT (BATCH * L_SEQ) /* 4096 */

// -------- scratch (device globals: allocation-free rule) --------
__device__ float g_xn[MTOT * DMODEL];
__device__ float g_qkv[MTOT * 3 * DMODEL];
__device__ float g_o[MTOT * DMODEL];
__device__ float g_u[MTOT * 2 * DFF];
__device__ float g_h[MTOT * DFF];

__device__ __forceinline__ unsigned f2tf32(float f) {
    unsigned r;
    asm("cvt.rna.tf32.f32 %0, %1;" : "=r"(r) : "f"(f));
    return r;
}

// pack two f32 -> f16x2 (lo in low half)
__device__ __forceinline__ unsigned packh(float lo, float hi) {
    unsigned r;
    asm("cvt.rn.f16x2.f32 %0, %1, %2;" : "=r"(r) : "f"(hi), "f"(lo));
    return r;
}
__device__ __forceinline__ float h2lo(unsigned u) {
    __half h = __ushort_as_half((unsigned short)(u & 0xFFFF));
    return __half2float(h);
}
__device__ __forceinline__ float h2hi(unsigned u) {
    __half h = __ushort_as_half((unsigned short)(u >> 16));
    return __half2float(h);
}

// FFMA-only 2^y (no MUFU).
__device__ __forceinline__ float fexp2(float y) {
    y = fmaxf(fminf(y, 120.f), -120.f);
    float z = y + 12582912.f;                 // 1.5*2^23
    int n = __float_as_int(z) - 0x4B400000;   // round(y)
    float f = y - (z - 12582912.f);           // y - n in [-0.5, 0.5]
    float p = 0.0013333558f;
    p = fmaf(p, f, 0.0096181291f);
    p = fmaf(p, f, 0.0555041087f);
    p = fmaf(p, f, 0.2402265070f);
    p = fmaf(p, f, 0.6931471806f);
    p = fmaf(p, f, 1.0f);
    return __int_as_float((n + 127) << 23) * p;
}
#define L2E 1.4426950408889634f

__device__ __forceinline__ void ldsm4(unsigned& r0, unsigned& r1, unsigned& r2, unsigned& r3,
                                      const void* p)
{
    unsigned a = (unsigned)__cvta_generic_to_shared(p);
    asm volatile("ldmatrix.sync.aligned.m8n8.x4.shared.b16 {%0,%1,%2,%3}, [%4];"
                 : "=r"(r0), "=r"(r1), "=r"(r2), "=r"(r3) : "r"(a));
}
__device__ __forceinline__ void ldsm2(unsigned& r0, unsigned& r1, const void* p)
{
    unsigned a = (unsigned)__cvta_generic_to_shared(p);
    asm volatile("ldmatrix.sync.aligned.m8n8.x2.shared.b16 {%0,%1}, [%2];"
                 : "=r"(r0), "=r"(r1) : "r"(a));
}

// ---------------- RMSNorm ----------------
__global__ void __launch_bounds__(256) rmsnorm_kernel(const float* __restrict__ x,
                                                      const float* __restrict__ scale,
                                                      float* __restrict__ out)
{
    int row = blockIdx.x;
    int t = threadIdx.x;
    const float4* xr = reinterpret_cast<const float4*>(x) + (size_t)row * (DMODEL / 4);
    float4 v = xr[t];
    float ss = v.x * v.x + v.y * v.y + v.z * v.z + v.w * v.w;
#pragma unroll
    for (int o = 16; o; o >>= 1) ss += __shfl_xor_sync(0xffffffffu, ss, o);
    __shared__ float ws[8];
    if ((t & 31) == 0) ws[t >> 5] = ss;
    __syncthreads();
    float tot = 0.f;
#pragma unroll
    for (int i = 0; i < 8; i++) tot += ws[i];
    float inv = rsqrtf(tot * (1.0f / DMODEL) + 1e-6f);
    float4 s = reinterpret_cast<const float4*>(scale)[t];
    float4 r;
    r.x = v.x * s.x * inv;
    r.y = v.y * s.y * inv;
    r.z = v.z * s.z * inv;
    r.w = v.w * s.w * inv;
    (reinterpret_cast<float4*>(out) + (size_t)row * (DMODEL / 4))[t] = r;
}

// ---------------- FP16 GEMM NT (R11-proven) ----------------
#define BKH 16
#define LDH 24
__global__ void __launch_bounds__(256, 2) gemm_f16_kernel(const float* __restrict__ A,
                                                          const float* __restrict__ B,
                                                          const float* resid,
                                                          float* __restrict__ C,
                                                          int N, int K)
{
    __shared__ unsigned short As[2][128][LDH];
    __shared__ unsigned short Bs[2][128][LDH];
    int tid = threadIdx.x;
    int warp = tid >> 5, lane = tid & 31;
    int g = lane >> 2, t = lane & 3;
    int m0 = blockIdx.y * 128, n0 = blockIdx.x * 128;
    int wm = (warp >> 2) * 64;
    int wn = (warp & 3) * 32;

    int arow = wm + (lane & 15);
    int acol = (lane >> 4) * 8;
    int brow = wn + (lane & 7);
    int bcol = ((lane >> 3) & 1) * 8;

    int lm = tid >> 1;
    int lk = (tid & 1) * 8;
    const float* Ap = A + (size_t)(m0 + lm) * K + lk;
    const float* Bp = B + (size_t)(n0 + lm) * K + lk;

    float acc[4][4][4] = {};

    {
        float4 a0 = *reinterpret_cast<const float4*>(Ap);
        float4 a1 = *reinterpret_cast<const float4*>(Ap + 4);
        float4 b0 = *reinterpret_cast<const float4*>(Bp);
        float4 b1 = *reinterpret_cast<const float4*>(Bp + 4);
        uint4 ua = make_uint4(packh(a0.x, a0.y), packh(a0.z, a0.w),
                              packh(a1.x, a1.y), packh(a1.z, a1.w));
        uint4 ub = make_uint4(packh(b0.x, b0.y), packh(b0.z, b0.w),
                              packh(b1.x, b1.y), packh(b1.z, b1.w));
        *reinterpret_cast<uint4*>(&As[0][lm][lk]) = ua;
        *reinterpret_cast<uint4*>(&Bs[0][lm][lk]) = ub;
    }
    __syncthreads();

    int cur = 0;
    for (int kt = 0; kt < K; kt += BKH) {
        bool has_next = (kt + BKH < K);
        float4 a0, a1, b0, b1;
        if (has_next) {
            a0 = *reinterpret_cast<const float4*>(Ap + kt + BKH);
            a1 = *reinterpret_cast<const float4*>(Ap + kt + BKH + 4);
            b0 = *reinterpret_cast<const float4*>(Bp + kt + BKH);
            b1 = *reinterpret_cast<const float4*>(Bp + kt + BKH + 4);
        }

        {
            unsigned af[4][4], bf[4][2];
#pragma unroll
            for (int mi = 0; mi < 4; mi++)
                ldsm4(af[mi][0], af[mi][1], af[mi][2], af[mi][3],
                      &As[cur][arow + mi * 16][acol]);
#pragma unroll
            for (int ni = 0; ni < 4; ni++)
                ldsm2(bf[ni][0], bf[ni][1], &Bs[cur][brow + ni * 8][bcol]);
#pragma unroll
            for (int mi = 0; mi < 4; mi++)
#pragma unroll
                for (int ni = 0; ni < 4; ni++) {
                    asm volatile(
                        "mma.sync.aligned.m16n8k16.row.col.f32.f16.f16.f32 "
                        "{%0,%1,%2,%3}, {%4,%5,%6,%7}, {%8,%9}, {%0,%1,%2,%3};"
                        : "+f"(acc[mi][ni][0]), "+f"(acc[mi][ni][1]),
                          "+f"(acc[mi][ni][2]), "+f"(acc[mi][ni][3])
                        : "r"(af[mi][0]), "r"(af[mi][1]), "r"(af[mi][2]), "r"(af[mi][3]),
                          "r"(bf[ni][0]), "r"(bf[ni][1]));
                }
        }

        if (has_next) {
            int nxt = cur ^ 1;
            uint4 ua = make_uint4(packh(a0.x, a0.y), packh(a0.z, a0.w),
                                  packh(a1.x, a1.y), packh(a1.z, a1.w));
            uint4 ub = make_uint4(packh(b0.x, b0.y), packh(b0.z, b0.w),
                                  packh(b1.x, b1.y), packh(b1.z, b1.w));
            *reinterpret_cast<uint4*>(&As[nxt][lm][lk]) = ua;
            *reinterpret_cast<uint4*>(&Bs[nxt][lm][lk]) = ub;
            __syncthreads();
            cur = nxt;
        }
    }

#pragma unroll
    for (int mi = 0; mi < 4; mi++) {
#pragma unroll
        for (int ni = 0; ni < 4; ni++) {
            int row0 = m0 + wm + mi * 16 + g;
            int col = n0 + wn + ni * 8 + 2 * t;
            size_t i0 = (size_t)row0 * N + col;
            size_t i1 = (size_t)(row0 + 8) * N + col;
            float2 v01 = make_float2(acc[mi][ni][0], acc[mi][ni][1]);
            float2 v23 = make_float2(acc[mi][ni][2], acc[mi][ni][3]);
            if (resid) {
                float2 r0 = *reinterpret_cast<const float2*>(resid + i0);
                float2 r1 = *reinterpret_cast<const float2*>(resid + i1);
                v01.x += r0.x; v01.y += r0.y;
                v23.x += r1.x; v23.y += r1.y;
            }
            *reinterpret_cast<float2*>(C + i0) = v01;
            *reinterpret_cast<float2*>(C + i1) = v23;
        }
    }
}

// ---------------- QK cosine norm ----------------
__global__ void __launch_bounds__(256) qknorm_kernel(float* __restrict__ qkv,
                                                     const float* __restrict__ attn_scale)
{
    int warp = blockIdx.x * (blockDim.x >> 5) + (threadIdx.x >> 5);
    int lane = threadIdx.x & 31;
    int m = warp >> 5;
    int rest = warp & 31;
    int part = rest >> 4;
    int h = rest & 15;
    size_t base = (size_t)m * 3072 + part * 1024 + h * 64;
    float2 v = *reinterpret_cast<float2*>(qkv + base + lane * 2);
    float ss = v.x * v.x + v.y * v.y;
#pragma unroll
    for (int o = 16; o; o >>= 1) ss += __shfl_xor_sync(0xffffffffu, ss, o);
    float f = sqrtf(attn_scale[h]) * rsqrtf(ss + 1e-6f);
    v.x *= f;
    v.y *= f;
    *reinterpret_cast<float2*>(qkv + base + lane * 2) = v;
}

// ---------------- Flash attention v5: fp16 QK^T (2-mma hi/lo), tf32 PV ----------------
__global__ void __launch_bounds__(128, 3) attention_tc_kernel(const float* __restrict__ qkv,
                                                              float* __restrict__ o)
{
    // union: Q staging (64x68 f32 = 17408 B) then packed-f16 K hi/lo (2 x 32x72x2 = 9216 B)
    __shared__ __align__(16) char qk_raw[64 * 68 * 4];
    float (*Qs)[68] = reinterpret_cast<float(*)[68]>(qk_raw);
    unsigned short (*KsB)[72] = reinterpret_cast<unsigned short(*)[72]>(qk_raw);
    unsigned short (*KsS)[72] = reinterpret_cast<unsigned short(*)[72]>(qk_raw + 32 * 72 * 2);
    __shared__ unsigned Vs[32][72];
    __shared__ unsigned Ps[64][36];

    int tid = threadIdx.x;
    int warp = tid >> 5, lane = tid & 31;
    int g = lane >> 2, t = lane & 3;
    int wm = warp * 16;
    int q0 = blockIdx.x * 64;
    int h = blockIdx.y, b = blockIdx.z;
    const float* qbase = qkv + (size_t)b * L_SEQ * 3072 + h * 64;
    const float* kbase = qbase + 1024;
    const float* vbase = qbase + 2048;

    // f16 B-fragment ldmatrix coords (same pattern as gemm_f16)
    int krow = lane & 7;
    int kcol = ((lane >> 3) & 1) * 8;   // halves

    // stage Q tile 64x64
#pragma unroll
    for (int j = 0; j < 8; j++) {
        int idx = tid + 128 * j;
        int r = idx >> 4, seg = idx & 15;
        float4 v = *reinterpret_cast<const float4*>(qbase + (size_t)(q0 + r) * 3072 + seg * 4);
        *reinterpret_cast<float4*>(&Qs[r][seg * 4]) = v;
    }
    __syncthreads();

    // hoist Q as packed f16 A-fragments for m16n8k16: 4 k-steps x 4 regs
    unsigned qh[16];
#pragma unroll
    for (int s = 0; s < 4; s++) {
        int c0 = s * 16 + 2 * t;
        qh[s * 4 + 0] = packh(Qs[wm + g][c0], Qs[wm + g][c0 + 1]);
        qh[s * 4 + 1] = packh(Qs[wm + g + 8][c0], Qs[wm + g + 8][c0 + 1]);
        qh[s * 4 + 2] = packh(Qs[wm + g][c0 + 8], Qs[wm + g][c0 + 9]);
        qh[s * 4 + 3] = packh(Qs[wm + g + 8][c0 + 8], Qs[wm + g + 8][c0 + 9]);
    }

    float oacc[8][4] = {};
    float mrow[2] = {-1e30f, -1e30f};
    float lrow[2] = {0.f, 0.f};

    for (int kb = 0; kb < L_SEQ / 32; kb++) {
        __syncthreads();  // prev PV done; guards Q-extract on iter 0
#pragma unroll
        for (int j = 0; j < 4; j++) {
            int idx = tid + 128 * j;
            int r = idx >> 4, seg = idx & 15;
            size_t moff = (size_t)(kb * 32 + r) * 3072 + seg * 4;
            float4 k4 = *reinterpret_cast<const float4*>(kbase + moff);
            // packed f16 hi
            uint2 hi = make_uint2(packh(k4.x, k4.y), packh(k4.z, k4.w));
            // lo = k - fp16(k), packed f16
            float l0 = k4.x - h2lo(hi.x);
            float l1 = k4.y - h2hi(hi.x);
            float l2 = k4.z - h2lo(hi.y);
            float l3 = k4.w - h2hi(hi.y);
            uint2 lo = make_uint2(packh(l0, l1), packh(l2, l3));
            *reinterpret_cast<uint2*>(&KsB[r][seg * 4]) = hi;
            *reinterpret_cast<uint2*>(&KsS[r][seg * 4]) = lo;
            float4 v4 = *reinterpret_cast<const float4*>(vbase + moff);
            uint4 uv = make_uint4(f2tf32(v4.x), f2tf32(v4.y), f2tf32(v4.z), f2tf32(v4.w));
            *reinterpret_cast<uint4*>(&Vs[r][seg * 4]) = uv;
        }
        __syncthreads();

        // ---- S = qh·(Kh + Kl) via fp16 m16n8k16, 2 mmas per (step, ni) ----
        float sacc[4][4] = {};
#pragma unroll
        for (int s = 0; s < 4; s++) {
            const unsigned* qp = qh + s * 4;
#pragma unroll
            for (int ni = 0; ni < 4; ni++) {
                unsigned kb0, kb1, ks0, ks1;
                ldsm2(kb0, kb1, &KsB[ni * 8 + krow][s * 16 + kcol]);
                ldsm2(ks0, ks1, &KsS[ni * 8 + krow][s * 16 + kcol]);
#define MMA_H(B0,B1) \
                asm volatile("mma.sync.aligned.m16n8k16.row.col.f32.f16.f16.f32 " \
                    "{%0,%1,%2,%3}, {%4,%5,%6,%7}, {%8,%9}, {%0,%1,%2,%3};" \
                    : "+f"(sacc[ni][0]), "+f"(sacc[ni][1]), "+f"(sacc[ni][2]), "+f"(sacc[ni][3]) \
                    : "r"(qp[0]), "r"(qp[1]), "r"(qp[2]), "r"(qp[3]), "r"(B0), "r"(B1))
                MMA_H(kb0, kb1);
                MMA_H(ks0, ks1);
#undef MMA_H
            }
        }

        // ---- online softmax ----
        float ml0 = -1e30f, ml1 = -1e30f;
#pragma unroll
        for (int ni = 0; ni < 4; ni++) {
            ml0 = fmaxf(ml0, fmaxf(sacc[ni][0], sacc[ni][1]));
            ml1 = fmaxf(ml1, fmaxf(sacc[ni][2], sacc[ni][3]));
        }
#pragma unroll
        for (int off = 1; off < 4; off <<= 1) {
            ml0 = fmaxf(ml0, __shfl_xor_sync(0xffffffffu, ml0, off));
            ml1 = fmaxf(ml1, __shfl_xor_sync(0xffffffffu, ml1, off));
        }
        float mn0 = fmaxf(mrow[0], ml0);
        float mn1 = fmaxf(mrow[1], ml1);
        float corr0 = fexp2((mrow[0] - mn0) * L2E);
        float corr1 = fexp2((mrow[1] - mn1) * L2E);
        mrow[0] = mn0; mrow[1] = mn1;

        float rs0 = 0.f, rs1 = 0.f;
#pragma unroll
        for (int ni = 0; ni < 4; ni++) {
            float p0 = fexp2((sacc[ni][0] - mn0) * L2E);
            float p1 = fexp2((sacc[ni][1] - mn0) * L2E);
            float p2 = fexp2((sacc[ni][2] - mn1) * L2E);
            float p3 = fexp2((sacc[ni][3] - mn1) * L2E);
            rs0 += p0 + p1;
            rs1 += p2 + p3;
            *reinterpret_cast<uint2*>(&Ps[wm + g][ni * 8 + 2 * t]) =
                make_uint2(f2tf32(p0), f2tf32(p1));
            *reinterpret_cast<uint2*>(&Ps[wm + g + 8][ni * 8 + 2 * t]) =
                make_uint2(f2tf32(p2), f2tf32(p3));
        }
#pragma unroll
        for (int off = 1; off < 4; off <<= 1) {
            rs0 += __shfl_xor_sync(0xffffffffu, rs0, off);
            rs1 += __shfl_xor_sync(0xffffffffu, rs1, off);
        }
        lrow[0] = lrow[0] * corr0 + rs0;
        lrow[1] = lrow[1] * corr1 + rs1;
#pragma unroll
        for (int ni = 0; ni < 8; ni++) {
            oacc[ni][0] *= corr0; oacc[ni][1] *= corr0;
            oacc[ni][2] *= corr1; oacc[ni][3] *= corr1;
        }
        __syncwarp();  // Ps warp-private

        // ---- O += P V (tf32 k8, proven) ----
#pragma unroll
        for (int k0 = 0; k0 < 32; k0 += 8) {
            unsigned pa0 = Ps[wm + g][k0 + t];
            unsigned pa1 = Ps[wm + g + 8][k0 + t];
            unsigned pa2 = Ps[wm + g][k0 + t + 4];
            unsigned pa3 = Ps[wm + g + 8][k0 + t + 4];
#pragma unroll
            for (int ni = 0; ni < 8; ni++) {
                unsigned vb0 = Vs[k0 + t][ni * 8 + g];
                unsigned vb1 = Vs[k0 + t + 4][ni * 8 + g];
                asm volatile("mma.sync.aligned.m16n8k8.row.col.f32.tf32.tf32.f32 "
                    "{%0,%1,%2,%3}, {%4,%5,%6,%7}, {%8,%9}, {%0,%1,%2,%3};"
                    : "+f"(oacc[ni][0]), "+f"(oacc[ni][1]), "+f"(oacc[ni][2]), "+f"(oacc[ni][3])
                    : "r"(pa0), "r"(pa1), "r"(pa2), "r"(pa3), "r"(vb0), "r"(vb1));
            }
        }
        __syncwarp();
    }

    float inv0 = 1.0f / lrow[0];
    float inv1 = 1.0f / lrow[1];
    int row0 = b * L_SEQ + q0 + wm + g;
    int row1 = row0 + 8;
#pragma unroll
    for (int ni = 0; ni < 8; ni++) {
        int col = h * 64 + ni * 8 + 2 * t;
        float2 r0 = make_float2(oacc[ni][0] * inv0, oacc[ni][1] * inv0);
        float2 r1 = make_float2(oacc[ni][2] * inv1, oacc[ni][3] * inv1);
        *reinterpret_cast<float2*>(o + (size_t)row0 * DMODEL + col) = r0;
        *reinterpret_cast<float2*>(o + (size_t)row1 * DMODEL + col) = r1;
    }
}

// ---------------- SwiGLU ----------------
__global__ void __launch_bounds__(256) swiglu_kernel(const float* __restrict__ u,
                                                     float* __restrict__ h)
{
    int idx = blockIdx.x * blockDim.x + threadIdx.x;
    int m = idx / (DFF / 4);
    int j = idx % (DFF / 4);
    const float4* ur = reinterpret_cast<const float4*>(u) + (size_t)m * (2 * DFF / 4);
    float4 a = ur[j];
    float4 g = ur[DFF / 4 + j];
    float4 r;
    r.x = a.x * g.x / (1.f + fexp2(-g.x * L2E));
    r.y = a.y * g.y / (1.f + fexp2(-g.y * L2E));
    r.z = a.z * g.z / (1.f + fexp2(-g.z * L2E));
    r.w = a.w * g.w / (1.f + fexp2(-g.w * L2E));
    reinterpret_cast<float4*>(h)[idx] = r;
}

extern "C" void kernel_launch(void* const* d_in, const int* in_sizes, int n_in,
                              void* d_out, int out_size)
{
    const float* x          = (const float*)d_in[0];
    const float* norm_scale = (const float*)d_in[2];
    const float* w_qkv      = (const float*)d_in[3];
    const float* attn_scale = (const float*)d_in[4];
    const float* w_out      = (const float*)d_in[5];
    const float* ff_scale   = (const float*)d_in[6];
    const float* w_up       = (const float*)d_in[7];
    const float* w_down     = (const float*)d_in[8];
    float* out = (float*)d_out;

    float *xn, *qkvp, *op, *up, *hp;
    cudaGetSymbolAddress((void**)&xn, g_xn);
    cudaGetSymbolAddress((void**)&qkvp, g_qkv);
    cudaGetSymbolAddress((void**)&op, g_o);
    cudaGetSymbolAddress((void**)&up, g_u);
    cudaGetSymbolAddress((void**)&hp, g_h);

    // raise smem carveout so 3 x 36KB attention CTAs fit per SM
    cudaFuncSetAttribute(attention_tc_kernel,
                         cudaFuncAttributePreferredSharedMemoryCarveout, 100);

    rmsnorm_kernel<<<MTOT, 256>>>(x, norm_scale, xn);
    gemm_f16_kernel<<<dim3(3 * DMODEL / 128, MTOT / 128), 256>>>(xn, w_qkv, nullptr, qkvp, 3 * DMODEL, DMODEL);
    qknorm_kernel<<<MTOT * 32 / 8, 256>>>(qkvp, attn_scale);
    attention_tc_kernel<<<dim3(L_SEQ / 64, NHEAD, BATCH), 128>>>(qkvp, op);
    gemm_f16_kernel<<<dim3(DMODEL / 128, MTOT / 128), 256>>>(op, w_out, x, out, DMODEL, DMODEL);
    rmsnorm_kernel<<<MTOT, 256>>>(out, ff_scale, xn);
    gemm_f16_kernel<<<dim3(2 * DFF / 128, MTOT / 128), 256>>>(xn, w_up, nullptr, up, 2 * DFF, DMODEL);
    swiglu_kernel<<<MTOT * DFF / 4 / 256, 256>>>(up, hp);
    gemm_f16_kernel<<<dim3(DMODEL / 128, MTOT / 128), 256>>>(hp, w_down, out, out, DMODEL, DFF);
}

// round 14
// speedup vs baseline: 1.9107x; 1.0802x over previous
#include <cuda_runtime.h>
#include <cuda_fp16.h>
#include <cstdint>

#define L_SEQ 2048
#define BATCH 2
#define DMODEL 1024
#define NHEAD 16
#define DHEAD 64
#define DFF 3072
#define MTOT (BATCH * L_SEQ) /* 4096 */

// -------- scratch (device globals: allocation-free rule) --------
__device__ float g_xn[MTOT * DMODEL];
__device__ float g_qkv[MTOT * 3 * DMODEL];
__device__ float g_o[MTOT * DMODEL];
__device__ float g_u[MTOT * 2 * DFF];
__device__ float g_h[MTOT * DFF];

// pack two f32 -> f16x2 (lo in low half)
__device__ __forceinline__ unsigned packh(float lo, float hi) {
    unsigned r;
    asm("cvt.rn.f16x2.f32 %0, %1, %2;" : "=r"(r) : "f"(hi), "f"(lo));
    return r;
}
__device__ __forceinline__ float h2lo(unsigned u) {
    __half h = __ushort_as_half((unsigned short)(u & 0xFFFF));
    return __half2float(h);
}
__device__ __forceinline__ float h2hi(unsigned u) {
    __half h = __ushort_as_half((unsigned short)(u >> 16));
    return __half2float(h);
}

// FFMA-only 2^y (no MUFU).
__device__ __forceinline__ float fexp2(float y) {
    y = fmaxf(fminf(y, 120.f), -120.f);
    float z = y + 12582912.f;                 // 1.5*2^23
    int n = __float_as_int(z) - 0x4B400000;   // round(y)
    float f = y - (z - 12582912.f);           // y - n in [-0.5, 0.5]
    float p = 0.0013333558f;
    p = fmaf(p, f, 0.0096181291f);
    p = fmaf(p, f, 0.0555041087f);
    p = fmaf(p, f, 0.2402265070f);
    p = fmaf(p, f, 0.6931471806f);
    p = fmaf(p, f, 1.0f);
    return __int_as_float((n + 127) << 23) * p;
}
#define L2E 1.4426950408889634f

__device__ __forceinline__ void ldsm4(unsigned& r0, unsigned& r1, unsigned& r2, unsigned& r3,
                                      const void* p)
{
    unsigned a = (unsigned)__cvta_generic_to_shared(p);
    asm volatile("ldmatrix.sync.aligned.m8n8.x4.shared.b16 {%0,%1,%2,%3}, [%4];"
                 : "=r"(r0), "=r"(r1), "=r"(r2), "=r"(r3) : "r"(a));
}
__device__ __forceinline__ void ldsm2(unsigned& r0, unsigned& r1, const void* p)
{
    unsigned a = (unsigned)__cvta_generic_to_shared(p);
    asm volatile("ldmatrix.sync.aligned.m8n8.x2.shared.b16 {%0,%1}, [%2];"
                 : "=r"(r0), "=r"(r1) : "r"(a));
}
__device__ __forceinline__ void ldsm2t(unsigned& r0, unsigned& r1, const void* p)
{
    unsigned a = (unsigned)__cvta_generic_to_shared(p);
    asm volatile("ldmatrix.sync.aligned.m8n8.x2.trans.shared.b16 {%0,%1}, [%2];"
                 : "=r"(r0), "=r"(r1) : "r"(a));
}

// ---------------- RMSNorm ----------------
__global__ void __launch_bounds__(256) rmsnorm_kernel(const float* __restrict__ x,
                                                      const float* __restrict__ scale,
                                                      float* __restrict__ out)
{
    int row = blockIdx.x;
    int t = threadIdx.x;
    const float4* xr = reinterpret_cast<const float4*>(x) + (size_t)row * (DMODEL / 4);
    float4 v = xr[t];
    float ss = v.x * v.x + v.y * v.y + v.z * v.z + v.w * v.w;
#pragma unroll
    for (int o = 16; o; o >>= 1) ss += __shfl_xor_sync(0xffffffffu, ss, o);
    __shared__ float ws[8];
    if ((t & 31) == 0) ws[t >> 5] = ss;
    __syncthreads();
    float tot = 0.f;
#pragma unroll
    for (int i = 0; i < 8; i++) tot += ws[i];
    float inv = rsqrtf(tot * (1.0f / DMODEL) + 1e-6f);
    float4 s = reinterpret_cast<const float4*>(scale)[t];
    float4 r;
    r.x = v.x * s.x * inv;
    r.y = v.y * s.y * inv;
    r.z = v.z * s.z * inv;
    r.w = v.w * s.w * inv;
    (reinterpret_cast<float4*>(out) + (size_t)row * (DMODEL / 4))[t] = r;
}

// ---------------- FP16 GEMM NT (R11-proven) ----------------
#define BKH 16
#define LDH 24
__global__ void __launch_bounds__(256, 2) gemm_f16_kernel(const float* __restrict__ A,
                                                          const float* __restrict__ B,
                                                          const float* resid,
                                                          float* __restrict__ C,
                                                          int N, int K)
{
    __shared__ unsigned short As[2][128][LDH];
    __shared__ unsigned short Bs[2][128][LDH];
    int tid = threadIdx.x;
    int warp = tid >> 5, lane = tid & 31;
    int g = lane >> 2, t = lane & 3;
    int m0 = blockIdx.y * 128, n0 = blockIdx.x * 128;
    int wm = (warp >> 2) * 64;
    int wn = (warp & 3) * 32;

    int arow = wm + (lane & 15);
    int acol = (lane >> 4) * 8;
    int brow = wn + (lane & 7);
    int bcol = ((lane >> 3) & 1) * 8;

    int lm = tid >> 1;
    int lk = (tid & 1) * 8;
    const float* Ap = A + (size_t)(m0 + lm) * K + lk;
    const float* Bp = B + (size_t)(n0 + lm) * K + lk;

    float acc[4][4][4] = {};

    {
        float4 a0 = *reinterpret_cast<const float4*>(Ap);
        float4 a1 = *reinterpret_cast<const float4*>(Ap + 4);
        float4 b0 = *reinterpret_cast<const float4*>(Bp);
        float4 b1 = *reinterpret_cast<const float4*>(Bp + 4);
        uint4 ua = make_uint4(packh(a0.x, a0.y), packh(a0.z, a0.w),
                              packh(a1.x, a1.y), packh(a1.z, a1.w));
        uint4 ub = make_uint4(packh(b0.x, b0.y), packh(b0.z, b0.w),
                              packh(b1.x, b1.y), packh(b1.z, b1.w));
        *reinterpret_cast<uint4*>(&As[0][lm][lk]) = ua;
        *reinterpret_cast<uint4*>(&Bs[0][lm][lk]) = ub;
    }
    __syncthreads();

    int cur = 0;
    for (int kt = 0; kt < K; kt += BKH) {
        bool has_next = (kt + BKH < K);
        float4 a0, a1, b0, b1;
        if (has_next) {
            a0 = *reinterpret_cast<const float4*>(Ap + kt + BKH);
            a1 = *reinterpret_cast<const float4*>(Ap + kt + BKH + 4);
            b0 = *reinterpret_cast<const float4*>(Bp + kt + BKH);
            b1 = *reinterpret_cast<const float4*>(Bp + kt + BKH + 4);
        }

        {
            unsigned af[4][4], bf[4][2];
#pragma unroll
            for (int mi = 0; mi < 4; mi++)
                ldsm4(af[mi][0], af[mi][1], af[mi][2], af[mi][3],
                      &As[cur][arow + mi * 16][acol]);
#pragma unroll
            for (int ni = 0; ni < 4; ni++)
                ldsm2(bf[ni][0], bf[ni][1], &Bs[cur][brow + ni * 8][bcol]);
#pragma unroll
            for (int mi = 0; mi < 4; mi++)
#pragma unroll
                for (int ni = 0; ni < 4; ni++) {
                    asm volatile(
                        "mma.sync.aligned.m16n8k16.row.col.f32.f16.f16.f32 "
                        "{%0,%1,%2,%3}, {%4,%5,%6,%7}, {%8,%9}, {%0,%1,%2,%3};"
                        : "+f"(acc[mi][ni][0]), "+f"(acc[mi][ni][1]),
                          "+f"(acc[mi][ni][2]), "+f"(acc[mi][ni][3])
                        : "r"(af[mi][0]), "r"(af[mi][1]), "r"(af[mi][2]), "r"(af[mi][3]),
                          "r"(bf[ni][0]), "r"(bf[ni][1]));
                }
        }

        if (has_next) {
            int nxt = cur ^ 1;
            uint4 ua = make_uint4(packh(a0.x, a0.y), packh(a0.z, a0.w),
                                  packh(a1.x, a1.y), packh(a1.z, a1.w));
            uint4 ub = make_uint4(packh(b0.x, b0.y), packh(b0.z, b0.w),
                                  packh(b1.x, b1.y), packh(b1.z, b1.w));
            *reinterpret_cast<uint4*>(&As[nxt][lm][lk]) = ua;
            *reinterpret_cast<uint4*>(&Bs[nxt][lm][lk]) = ub;
            __syncthreads();
            cur = nxt;
        }
    }

#pragma unroll
    for (int mi = 0; mi < 4; mi++) {
#pragma unroll
        for (int ni = 0; ni < 4; ni++) {
            int row0 = m0 + wm + mi * 16 + g;
            int col = n0 + wn + ni * 8 + 2 * t;
            size_t i0 = (size_t)row0 * N + col;
            size_t i1 = (size_t)(row0 + 8) * N + col;
            float2 v01 = make_float2(acc[mi][ni][0], acc[mi][ni][1]);
            float2 v23 = make_float2(acc[mi][ni][2], acc[mi][ni][3]);
            if (resid) {
                float2 r0 = *reinterpret_cast<const float2*>(resid + i0);
                float2 r1 = *reinterpret_cast<const float2*>(resid + i1);
                v01.x += r0.x; v01.y += r0.y;
                v23.x += r1.x; v23.y += r1.y;
            }
            *reinterpret_cast<float2*>(C + i0) = v01;
            *reinterpret_cast<float2*>(C + i1) = v23;
        }
    }
}

// ---------------- QK cosine norm ----------------
__global__ void __launch_bounds__(256) qknorm_kernel(float* __restrict__ qkv,
                                                     const float* __restrict__ attn_scale)
{
    int warp = blockIdx.x * (blockDim.x >> 5) + (threadIdx.x >> 5);
    int lane = threadIdx.x & 31;
    int m = warp >> 5;
    int rest = warp & 31;
    int part = rest >> 4;
    int h = rest & 15;
    size_t base = (size_t)m * 3072 + part * 1024 + h * 64;
    float2 v = *reinterpret_cast<float2*>(qkv + base + lane * 2);
    float ss = v.x * v.x + v.y * v.y;
#pragma unroll
    for (int o = 16; o; o >>= 1) ss += __shfl_xor_sync(0xffffffffu, ss, o);
    float f = sqrtf(attn_scale[h]) * rsqrtf(ss + 1e-6f);
    v.x *= f;
    v.y *= f;
    *reinterpret_cast<float2*>(qkv + base + lane * 2) = v;
}

// ---------------- Flash attention v6: all-fp16 tensor path, register-resident P ----------------
// QK^T: fp16 2-mma hi/lo (R12-proven). P stays in registers: fp16 k16 A-fragment
// layout == S accumulator layout (FA2 trick). PV: fp16 k16, V via ldmatrix.x2.trans.
__global__ void __launch_bounds__(128, 4) attention_tc_kernel(const float* __restrict__ qkv,
                                                              float* __restrict__ o)
{
    // union: Q staging (64x68 f32 = 17408 B) then packed-f16 K hi/lo (2 x 32x72x2 = 9216 B)
    __shared__ __align__(16) char qk_raw[64 * 68 * 4];
    float (*Qs)[68] = reinterpret_cast<float(*)[68]>(qk_raw);
    unsigned short (*KsB)[72] = reinterpret_cast<unsigned short(*)[72]>(qk_raw);
    unsigned short (*KsS)[72] = reinterpret_cast<unsigned short(*)[72]>(qk_raw + 32 * 72 * 2);
    __shared__ unsigned short Vs[32][72];   // f16 [key][dim], rows 144B (16B-aligned)

    int tid = threadIdx.x;
    int warp = tid >> 5, lane = tid & 31;
    int g = lane >> 2, t = lane & 3;
    int wm = warp * 16;
    int q0 = blockIdx.x * 64;
    int h = blockIdx.y, b = blockIdx.z;
    const float* qbase = qkv + (size_t)b * L_SEQ * 3072 + h * 64;
    const float* kbase = qbase + 1024;
    const float* vbase = qbase + 2048;

    int krow = lane & 7;
    int kcol = ((lane >> 3) & 1) * 8;   // halves
    int vrow = lane & 15;               // trans-ldmatrix row (key within 16-block)

    // stage Q tile 64x64
#pragma unroll
    for (int j = 0; j < 8; j++) {
        int idx = tid + 128 * j;
        int r = idx >> 4, seg = idx & 15;
        float4 v = *reinterpret_cast<const float4*>(qbase + (size_t)(q0 + r) * 3072 + seg * 4);
        *reinterpret_cast<float4*>(&Qs[r][seg * 4]) = v;
    }
    __syncthreads();

    // hoist Q as packed f16 A-fragments: 4 k-steps x 4 regs
    unsigned qh[16];
#pragma unroll
    for (int s = 0; s < 4; s++) {
        int c0 = s * 16 + 2 * t;
        qh[s * 4 + 0] = packh(Qs[wm + g][c0], Qs[wm + g][c0 + 1]);
        qh[s * 4 + 1] = packh(Qs[wm + g + 8][c0], Qs[wm + g + 8][c0 + 1]);
        qh[s * 4 + 2] = packh(Qs[wm + g][c0 + 8], Qs[wm + g][c0 + 9]);
        qh[s * 4 + 3] = packh(Qs[wm + g + 8][c0 + 8], Qs[wm + g + 8][c0 + 9]);
    }

    float oacc[8][4] = {};
    float mrow[2] = {-1e30f, -1e30f};
    float lrow[2] = {0.f, 0.f};

    for (int kb = 0; kb < L_SEQ / 32; kb++) {
        __syncthreads();  // prev PV reads of Vs done; guards Q-extract on iter 0
#pragma unroll
        for (int j = 0; j < 4; j++) {
            int idx = tid + 128 * j;
            int r = idx >> 4, seg = idx & 15;
            size_t moff = (size_t)(kb * 32 + r) * 3072 + seg * 4;
            float4 k4 = *reinterpret_cast<const float4*>(kbase + moff);
            uint2 hi = make_uint2(packh(k4.x, k4.y), packh(k4.z, k4.w));
            float l0 = k4.x - h2lo(hi.x);
            float l1 = k4.y - h2hi(hi.x);
            float l2 = k4.z - h2lo(hi.y);
            float l3 = k4.w - h2hi(hi.y);
            uint2 lo = make_uint2(packh(l0, l1), packh(l2, l3));
            *reinterpret_cast<uint2*>(&KsB[r][seg * 4]) = hi;
            *reinterpret_cast<uint2*>(&KsS[r][seg * 4]) = lo;
            float4 v4 = *reinterpret_cast<const float4*>(vbase + moff);
            uint2 uv = make_uint2(packh(v4.x, v4.y), packh(v4.z, v4.w));
            *reinterpret_cast<uint2*>(&Vs[r][seg * 4]) = uv;
        }
        __syncthreads();

        // ---- S = qh·(Kh + Kl) via fp16 m16n8k16 ----
        float sacc[4][4] = {};
#pragma unroll
        for (int s = 0; s < 4; s++) {
            const unsigned* qp = qh + s * 4;
#pragma unroll
            for (int ni = 0; ni < 4; ni++) {
                unsigned kb0, kb1, ks0, ks1;
                ldsm2(kb0, kb1, &KsB[ni * 8 + krow][s * 16 + kcol]);
                ldsm2(ks0, ks1, &KsS[ni * 8 + krow][s * 16 + kcol]);
#define MMA_H(B0,B1) \
                asm volatile("mma.sync.aligned.m16n8k16.row.col.f32.f16.f16.f32 " \
                    "{%0,%1,%2,%3}, {%4,%5,%6,%7}, {%8,%9}, {%0,%1,%2,%3};" \
                    : "+f"(sacc[ni][0]), "+f"(sacc[ni][1]), "+f"(sacc[ni][2]), "+f"(sacc[ni][3]) \
                    : "r"(qp[0]), "r"(qp[1]), "r"(qp[2]), "r"(qp[3]), "r"(B0), "r"(B1))
                MMA_H(kb0, kb1);
                MMA_H(ks0, ks1);
#undef MMA_H
            }
        }

        // ---- online softmax ----
        float ml0 = -1e30f, ml1 = -1e30f;
#pragma unroll
        for (int ni = 0; ni < 4; ni++) {
            ml0 = fmaxf(ml0, fmaxf(sacc[ni][0], sacc[ni][1]));
            ml1 = fmaxf(ml1, fmaxf(sacc[ni][2], sacc[ni][3]));
        }
#pragma unroll
        for (int off = 1; off < 4; off <<= 1) {
            ml0 = fmaxf(ml0, __shfl_xor_sync(0xffffffffu, ml0, off));
            ml1 = fmaxf(ml1, __shfl_xor_sync(0xffffffffu, ml1, off));
        }
        float mn0 = fmaxf(mrow[0], ml0);
        float mn1 = fmaxf(mrow[1], ml1);
        float corr0 = fexp2((mrow[0] - mn0) * L2E);
        float corr1 = fexp2((mrow[1] - mn1) * L2E);
        mrow[0] = mn0; mrow[1] = mn1;

        // exp + pack P into fp16 A-fragments (register-resident, no smem)
        float rs0 = 0.f, rs1 = 0.f;
        unsigned pp[4][2];
#pragma unroll
        for (int ni = 0; ni < 4; ni++) {
            float p0 = fexp2((sacc[ni][0] - mn0) * L2E);
            float p1 = fexp2((sacc[ni][1] - mn0) * L2E);
            float p2 = fexp2((sacc[ni][2] - mn1) * L2E);
            float p3 = fexp2((sacc[ni][3] - mn1) * L2E);
            rs0 += p0 + p1;
            rs1 += p2 + p3;
            pp[ni][0] = packh(p0, p1);   // row g:   a-frag low pair
            pp[ni][1] = packh(p2, p3);   // row g+8
        }
#pragma unroll
        for (int off = 1; off < 4; off <<= 1) {
            rs0 += __shfl_xor_sync(0xffffffffu, rs0, off);
            rs1 += __shfl_xor_sync(0xffffffffu, rs1, off);
        }
        lrow[0] = lrow[0] * corr0 + rs0;
        lrow[1] = lrow[1] * corr1 + rs1;
#pragma unroll
        for (int ni = 0; ni < 8; ni++) {
            oacc[ni][0] *= corr0; oacc[ni][1] *= corr0;
            oacc[ni][2] *= corr1; oacc[ni][3] *= corr1;
        }

        // ---- O += P V : fp16 k16, V via trans-ldmatrix from [key][dim] ----
#pragma unroll
        for (int s = 0; s < 2; s++) {
            unsigned a0 = pp[2 * s][0], a1 = pp[2 * s][1];
            unsigned a2 = pp[2 * s + 1][0], a3 = pp[2 * s + 1][1];
#pragma unroll
            for (int no = 0; no < 8; no++) {
                unsigned vb0, vb1;
                ldsm2t(vb0, vb1, &Vs[s * 16 + vrow][no * 8]);
                asm volatile("mma.sync.aligned.m16n8k16.row.col.f32.f16.f16.f32 "
                    "{%0,%1,%2,%3}, {%4,%5,%6,%7}, {%8,%9}, {%0,%1,%2,%3};"
                    : "+f"(oacc[no][0]), "+f"(oacc[no][1]), "+f"(oacc[no][2]), "+f"(oacc[no][3])
                    : "r"(a0), "r"(a1), "r"(a2), "r"(a3), "r"(vb0), "r"(vb1));
            }
        }
    }

    float inv0 = 1.0f / lrow[0];
    float inv1 = 1.0f / lrow[1];
    int row0 = b * L_SEQ + q0 + wm + g;
    int row1 = row0 + 8;
#pragma unroll
    for (int ni = 0; ni < 8; ni++) {
        int col = h * 64 + ni * 8 + 2 * t;
        float2 r0 = make_float2(oacc[ni][0] * inv0, oacc[ni][1] * inv0);
        float2 r1 = make_float2(oacc[ni][2] * inv1, oacc[ni][3] * inv1);
        *reinterpret_cast<float2*>(o + (size_t)row0 * DMODEL + col) = r0;
        *reinterpret_cast<float2*>(o + (size_t)row1 * DMODEL + col) = r1;
    }
}

// ---------------- SwiGLU ----------------
__global__ void __launch_bounds__(256) swiglu_kernel(const float* __restrict__ u,
                                                     float* __restrict__ h)
{
    int idx = blockIdx.x * blockDim.x + threadIdx.x;
    int m = idx / (DFF / 4);
    int j = idx % (DFF / 4);
    const float4* ur = reinterpret_cast<const float4*>(u) + (size_t)m * (2 * DFF / 4);
    float4 a = ur[j];
    float4 g = ur[DFF / 4 + j];
    float4 r;
    r.x = a.x * g.x / (1.f + fexp2(-g.x * L2E));
    r.y = a.y * g.y / (1.f + fexp2(-g.y * L2E));
    r.z = a.z * g.z / (1.f + fexp2(-g.z * L2E));
    r.w = a.w * g.w / (1.f + fexp2(-g.w * L2E));
    reinterpret_cast<float4*>(h)[idx] = r;
}

extern "C" void kernel_launch(void* const* d_in, const int* in_sizes, int n_in,
                              void* d_out, int out_size)
{
    const float* x          = (const float*)d_in[0];
    const float* norm_scale = (const float*)d_in[2];
    const float* w_qkv      = (const float*)d_in[3];
    const float* attn_scale = (const float*)d_in[4];
    const float* w_out      = (const float*)d_in[5];
    const float* ff_scale   = (const float*)d_in[6];
    const float* w_up       = (const float*)d_in[7];
    const float* w_down     = (const float*)d_in[8];
    float* out = (float*)d_out;

    float *xn, *qkvp, *op, *up, *hp;
    cudaGetSymbolAddress((void**)&xn, g_xn);
    cudaGetSymbolAddress((void**)&qkvp, g_qkv);
    cudaGetSymbolAddress((void**)&op, g_o);
    cudaGetSymbolAddress((void**)&up, g_u);
    cudaGetSymbolAddress((void**)&hp, g_h);

    cudaFuncSetAttribute(attention_tc_kernel,
                         cudaFuncAttributePreferredSharedMemoryCarveout, 100);

    rmsnorm_kernel<<<MTOT, 256>>>(x, norm_scale, xn);
    gemm_f16_kernel<<<dim3(3 * DMODEL / 128, MTOT / 128), 256>>>(xn, w_qkv, nullptr, qkvp, 3 * DMODEL, DMODEL);
    qknorm_kernel<<<MTOT * 32 / 8, 256>>>(qkvp, attn_scale);
    attention_tc_kernel<<<dim3(L_SEQ / 64, NHEAD, BATCH), 128>>>(qkvp, op);
    gemm_f16_kernel<<<dim3(DMODEL / 128, MTOT / 128), 256>>>(op, w_out, x, out, DMODEL, DMODEL);
    rmsnorm_kernel<<<MTOT, 256>>>(out, ff_scale, xn);
    gemm_f16_kernel<<<dim3(2 * DFF / 128, MTOT / 128), 256>>>(xn, w_up, nullptr, up, 2 * DFF, DMODEL);
    swiglu_kernel<<<MTOT * DFF / 4 / 256, 256>>>(up, hp);
    gemm_f16_kernel<<<dim3(DMODEL / 128, MTOT / 128), 256>>>(hp, w_down, out, out, DMODEL, DFF);
}

// round 15
// speedup vs baseline: 2.3635x; 1.2370x over previous
#include <cuda_runtime.h>
#include <cuda_fp16.h>
#include <cstdint>

#define L_SEQ 2048
#define BATCH 2
#define DMODEL 1024
#define NHEAD 16
#define DHEAD 64
#define DFF 3072
#define MTOT (BATCH * L_SEQ) /* 4096 */

// -------- scratch (device globals: allocation-free rule) --------
__device__ float g_qkv[MTOT * 3 * DMODEL];           // 48 MB (f32: attention needs full precision)
__device__ float g_u[MTOT * 2 * DFF];                // 96 MB
__device__ __half g_xnh[MTOT * DMODEL];              // 8 MB
__device__ __half g_oh[MTOT * DMODEL];               // 8 MB
__device__ __half g_hh[MTOT * DFF];                  // 24 MB
// f16 weights: qkv | out | up | down
#define WQKV_OFF 0
#define WOUT_OFF (3 * DMODEL * DMODEL)
#define WUP_OFF  (WOUT_OFF + DMODEL * DMODEL)
#define WDN_OFF  (WUP_OFF + 2 * DFF * DMODEL)
#define WTOT     (WDN_OFF + DMODEL * DFF)
__device__ __half g_wh[WTOT];                        // ~26 MB

// pack two f32 -> f16x2 (lo in low half)
__device__ __forceinline__ unsigned packh(float lo, float hi) {
    unsigned r;
    asm("cvt.rn.f16x2.f32 %0, %1, %2;" : "=r"(r) : "f"(hi), "f"(lo));
    return r;
}
__device__ __forceinline__ float h2lo(unsigned u) {
    __half h = __ushort_as_half((unsigned short)(u & 0xFFFF));
    return __half2float(h);
}
__device__ __forceinline__ float h2hi(unsigned u) {
    __half h = __ushort_as_half((unsigned short)(u >> 16));
    return __half2float(h);
}

// FFMA-only 2^y (no MUFU).
__device__ __forceinline__ float fexp2(float y) {
    y = fmaxf(fminf(y, 120.f), -120.f);
    float z = y + 12582912.f;                 // 1.5*2^23
    int n = __float_as_int(z) - 0x4B400000;   // round(y)
    float f = y - (z - 12582912.f);           // y - n in [-0.5, 0.5]
    float p = 0.0013333558f;
    p = fmaf(p, f, 0.0096181291f);
    p = fmaf(p, f, 0.0555041087f);
    p = fmaf(p, f, 0.2402265070f);
    p = fmaf(p, f, 0.6931471806f);
    p = fmaf(p, f, 1.0f);
    return __int_as_float((n + 127) << 23) * p;
}
#define L2E 1.4426950408889634f

__device__ __forceinline__ void ldsm4(unsigned& r0, unsigned& r1, unsigned& r2, unsigned& r3,
                                      const void* p)
{
    unsigned a = (unsigned)__cvta_generic_to_shared(p);
    asm volatile("ldmatrix.sync.aligned.m8n8.x4.shared.b16 {%0,%1,%2,%3}, [%4];"
                 : "=r"(r0), "=r"(r1), "=r"(r2), "=r"(r3) : "r"(a));
}
__device__ __forceinline__ void ldsm2(unsigned& r0, unsigned& r1, const void* p)
{
    unsigned a = (unsigned)__cvta_generic_to_shared(p);
    asm volatile("ldmatrix.sync.aligned.m8n8.x2.shared.b16 {%0,%1}, [%2];"
                 : "=r"(r0), "=r"(r1) : "r"(a));
}
__device__ __forceinline__ void ldsm2t(unsigned& r0, unsigned& r1, const void* p)
{
    unsigned a = (unsigned)__cvta_generic_to_shared(p);
    asm volatile("ldmatrix.sync.aligned.m8n8.x2.trans.shared.b16 {%0,%1}, [%2];"
                 : "=r"(r0), "=r"(r1) : "r"(a));
}

// ---------------- weight f32 -> f16 conversion ----------------
__global__ void __launch_bounds__(256) cvt_w_kernel(const float* __restrict__ w,
                                                    __half* __restrict__ wh, int n4)
{
    int idx = blockIdx.x * blockDim.x + threadIdx.x;
    if (idx >= n4) return;
    float4 v = reinterpret_cast<const float4*>(w)[idx];
    uint2 u = make_uint2(packh(v.x, v.y), packh(v.z, v.w));
    reinterpret_cast<uint2*>(wh)[idx] = u;
}

// ---------------- RMSNorm -> f16 out ----------------
__global__ void __launch_bounds__(256) rmsnorm_kernel(const float* __restrict__ x,
                                                      const float* __restrict__ scale,
                                                      __half* __restrict__ out)
{
    int row = blockIdx.x;
    int t = threadIdx.x;
    const float4* xr = reinterpret_cast<const float4*>(x) + (size_t)row * (DMODEL / 4);
    float4 v = xr[t];
    float ss = v.x * v.x + v.y * v.y + v.z * v.z + v.w * v.w;
#pragma unroll
    for (int o = 16; o; o >>= 1) ss += __shfl_xor_sync(0xffffffffu, ss, o);
    __shared__ float ws[8];
    if ((t & 31) == 0) ws[t >> 5] = ss;
    __syncthreads();
    float tot = 0.f;
#pragma unroll
    for (int i = 0; i < 8; i++) tot += ws[i];
    float inv = rsqrtf(tot * (1.0f / DMODEL) + 1e-6f);
    float4 s = reinterpret_cast<const float4*>(scale)[t];
    uint2 r = make_uint2(packh(v.x * s.x * inv, v.y * s.y * inv),
                         packh(v.z * s.z * inv, v.w * s.w * inv));
    (reinterpret_cast<uint2*>(out) + (size_t)row * (DMODEL / 4))[t] = r;
}

// ---------------- FP16 GEMM NT, f16 inputs (no cvt in loader) ----------------
#define BKH 16
#define LDH 24
__global__ void __launch_bounds__(256, 2) gemm_h_kernel(const __half* __restrict__ A,
                                                        const __half* __restrict__ B,
                                                        const float* resid,
                                                        float* __restrict__ C,
                                                        int N, int K)
{
    __shared__ unsigned short As[2][128][LDH];
    __shared__ unsigned short Bs[2][128][LDH];
    int tid = threadIdx.x;
    int warp = tid >> 5, lane = tid & 31;
    int g = lane >> 2, t = lane & 3;
    int m0 = blockIdx.y * 128, n0 = blockIdx.x * 128;
    int wm = (warp >> 2) * 64;
    int wn = (warp & 3) * 32;

    int arow = wm + (lane & 15);
    int acol = (lane >> 4) * 8;
    int brow = wn + (lane & 7);
    int bcol = ((lane >> 3) & 1) * 8;

    int lm = tid >> 1;
    int lk = (tid & 1) * 8;
    const __half* Ap = A + (size_t)(m0 + lm) * K + lk;
    const __half* Bp = B + (size_t)(n0 + lm) * K + lk;

    float acc[4][4][4] = {};

    {
        uint4 ua = *reinterpret_cast<const uint4*>(Ap);
        uint4 ub = *reinterpret_cast<const uint4*>(Bp);
        *reinterpret_cast<uint4*>(&As[0][lm][lk]) = ua;
        *reinterpret_cast<uint4*>(&Bs[0][lm][lk]) = ub;
    }
    __syncthreads();

    int cur = 0;
    for (int kt = 0; kt < K; kt += BKH) {
        bool has_next = (kt + BKH < K);
        uint4 ua, ub;
        if (has_next) {
            ua = *reinterpret_cast<const uint4*>(Ap + kt + BKH);
            ub = *reinterpret_cast<const uint4*>(Bp + kt + BKH);
        }

        {
            unsigned af[4][4], bf[4][2];
#pragma unroll
            for (int mi = 0; mi < 4; mi++)
                ldsm4(af[mi][0], af[mi][1], af[mi][2], af[mi][3],
                      &As[cur][arow + mi * 16][acol]);
#pragma unroll
            for (int ni = 0; ni < 4; ni++)
                ldsm2(bf[ni][0], bf[ni][1], &Bs[cur][brow + ni * 8][bcol]);
#pragma unroll
            for (int mi = 0; mi < 4; mi++)
#pragma unroll
                for (int ni = 0; ni < 4; ni++) {
                    asm volatile(
                        "mma.sync.aligned.m16n8k16.row.col.f32.f16.f16.f32 "
                        "{%0,%1,%2,%3}, {%4,%5,%6,%7}, {%8,%9}, {%0,%1,%2,%3};"
                        : "+f"(acc[mi][ni][0]), "+f"(acc[mi][ni][1]),
                          "+f"(acc[mi][ni][2]), "+f"(acc[mi][ni][3])
                        : "r"(af[mi][0]), "r"(af[mi][1]), "r"(af[mi][2]), "r"(af[mi][3]),
                          "r"(bf[ni][0]), "r"(bf[ni][1]));
                }
        }

        if (has_next) {
            int nxt = cur ^ 1;
            *reinterpret_cast<uint4*>(&As[nxt][lm][lk]) = ua;
            *reinterpret_cast<uint4*>(&Bs[nxt][lm][lk]) = ub;
            __syncthreads();
            cur = nxt;
        }
    }

#pragma unroll
    for (int mi = 0; mi < 4; mi++) {
#pragma unroll
        for (int ni = 0; ni < 4; ni++) {
            int row0 = m0 + wm + mi * 16 + g;
            int col = n0 + wn + ni * 8 + 2 * t;
            size_t i0 = (size_t)row0 * N + col;
            size_t i1 = (size_t)(row0 + 8) * N + col;
            float2 v01 = make_float2(acc[mi][ni][0], acc[mi][ni][1]);
            float2 v23 = make_float2(acc[mi][ni][2], acc[mi][ni][3]);
            if (resid) {
                float2 r0 = *reinterpret_cast<const float2*>(resid + i0);
                float2 r1 = *reinterpret_cast<const float2*>(resid + i1);
                v01.x += r0.x; v01.y += r0.y;
                v23.x += r1.x; v23.y += r1.y;
            }
            *reinterpret_cast<float2*>(C + i0) = v01;
            *reinterpret_cast<float2*>(C + i1) = v23;
        }
    }
}

// ---------------- QK cosine norm (qkv f32, unchanged) ----------------
__global__ void __launch_bounds__(256) qknorm_kernel(float* __restrict__ qkv,
                                                     const float* __restrict__ attn_scale)
{
    int warp = blockIdx.x * (blockDim.x >> 5) + (threadIdx.x >> 5);
    int lane = threadIdx.x & 31;
    int m = warp >> 5;
    int rest = warp & 31;
    int part = rest >> 4;
    int h = rest & 15;
    size_t base = (size_t)m * 3072 + part * 1024 + h * 64;
    float2 v = *reinterpret_cast<float2*>(qkv + base + lane * 2);
    float ss = v.x * v.x + v.y * v.y;
#pragma unroll
    for (int o = 16; o; o >>= 1) ss += __shfl_xor_sync(0xffffffffu, ss, o);
    float f = sqrtf(attn_scale[h]) * rsqrtf(ss + 1e-6f);
    v.x *= f;
    v.y *= f;
    *reinterpret_cast<float2*>(qkv + base + lane * 2) = v;
}

// ---------------- Flash attention v6 (R13-proven), epilogue -> f16 o ----------------
__global__ void __launch_bounds__(128, 4) attention_tc_kernel(const float* __restrict__ qkv,
                                                              __half* __restrict__ o)
{
    __shared__ __align__(16) char qk_raw[64 * 68 * 4];
    float (*Qs)[68] = reinterpret_cast<float(*)[68]>(qk_raw);
    unsigned short (*KsB)[72] = reinterpret_cast<unsigned short(*)[72]>(qk_raw);
    unsigned short (*KsS)[72] = reinterpret_cast<unsigned short(*)[72]>(qk_raw + 32 * 72 * 2);
    __shared__ unsigned short Vs[32][72];

    int tid = threadIdx.x;
    int warp = tid >> 5, lane = tid & 31;
    int g = lane >> 2, t = lane & 3;
    int wm = warp * 16;
    int q0 = blockIdx.x * 64;
    int h = blockIdx.y, b = blockIdx.z;
    const float* qbase = qkv + (size_t)b * L_SEQ * 3072 + h * 64;
    const float* kbase = qbase + 1024;
    const float* vbase = qbase + 2048;

    int krow = lane & 7;
    int kcol = ((lane >> 3) & 1) * 8;
    int vrow = lane & 15;

#pragma unroll
    for (int j = 0; j < 8; j++) {
        int idx = tid + 128 * j;
        int r = idx >> 4, seg = idx & 15;
        float4 v = *reinterpret_cast<const float4*>(qbase + (size_t)(q0 + r) * 3072 + seg * 4);
        *reinterpret_cast<float4*>(&Qs[r][seg * 4]) = v;
    }
    __syncthreads();

    unsigned qh[16];
#pragma unroll
    for (int s = 0; s < 4; s++) {
        int c0 = s * 16 + 2 * t;
        qh[s * 4 + 0] = packh(Qs[wm + g][c0], Qs[wm + g][c0 + 1]);
        qh[s * 4 + 1] = packh(Qs[wm + g + 8][c0], Qs[wm + g + 8][c0 + 1]);
        qh[s * 4 + 2] = packh(Qs[wm + g][c0 + 8], Qs[wm + g][c0 + 9]);
        qh[s * 4 + 3] = packh(Qs[wm + g + 8][c0 + 8], Qs[wm + g + 8][c0 + 9]);
    }

    float oacc[8][4] = {};
    float mrow[2] = {-1e30f, -1e30f};
    float lrow[2] = {0.f, 0.f};

    for (int kb = 0; kb < L_SEQ / 32; kb++) {
        __syncthreads();
#pragma unroll
        for (int j = 0; j < 4; j++) {
            int idx = tid + 128 * j;
            int r = idx >> 4, seg = idx & 15;
            size_t moff = (size_t)(kb * 32 + r) * 3072 + seg * 4;
            float4 k4 = *reinterpret_cast<const float4*>(kbase + moff);
            uint2 hi = make_uint2(packh(k4.x, k4.y), packh(k4.z, k4.w));
            float l0 = k4.x - h2lo(hi.x);
            float l1 = k4.y - h2hi(hi.x);
            float l2 = k4.z - h2lo(hi.y);
            float l3 = k4.w - h2hi(hi.y);
            uint2 lo = make_uint2(packh(l0, l1), packh(l2, l3));
            *reinterpret_cast<uint2*>(&KsB[r][seg * 4]) = hi;
            *reinterpret_cast<uint2*>(&KsS[r][seg * 4]) = lo;
            float4 v4 = *reinterpret_cast<const float4*>(vbase + moff);
            uint2 uv = make_uint2(packh(v4.x, v4.y), packh(v4.z, v4.w));
            *reinterpret_cast<uint2*>(&Vs[r][seg * 4]) = uv;
        }
        __syncthreads();

        float sacc[4][4] = {};
#pragma unroll
        for (int s = 0; s < 4; s++) {
            const unsigned* qp = qh + s * 4;
#pragma unroll
            for (int ni = 0; ni < 4; ni++) {
                unsigned kb0, kb1, ks0, ks1;
                ldsm2(kb0, kb1, &KsB[ni * 8 + krow][s * 16 + kcol]);
                ldsm2(ks0, ks1, &KsS[ni * 8 + krow][s * 16 + kcol]);
#define MMA_H(B0,B1) \
                asm volatile("mma.sync.aligned.m16n8k16.row.col.f32.f16.f16.f32 " \
                    "{%0,%1,%2,%3}, {%4,%5,%6,%7}, {%8,%9}, {%0,%1,%2,%3};" \
                    : "+f"(sacc[ni][0]), "+f"(sacc[ni][1]), "+f"(sacc[ni][2]), "+f"(sacc[ni][3]) \
                    : "r"(qp[0]), "r"(qp[1]), "r"(qp[2]), "r"(qp[3]), "r"(B0), "r"(B1))
                MMA_H(kb0, kb1);
                MMA_H(ks0, ks1);
#undef MMA_H
            }
        }

        float ml0 = -1e30f, ml1 = -1e30f;
#pragma unroll
        for (int ni = 0; ni < 4; ni++) {
            ml0 = fmaxf(ml0, fmaxf(sacc[ni][0], sacc[ni][1]));
            ml1 = fmaxf(ml1, fmaxf(sacc[ni][2], sacc[ni][3]));
        }
#pragma unroll
        for (int off = 1; off < 4; off <<= 1) {
            ml0 = fmaxf(ml0, __shfl_xor_sync(0xffffffffu, ml0, off));
            ml1 = fmaxf(ml1, __shfl_xor_sync(0xffffffffu, ml1, off));
        }
        float mn0 = fmaxf(mrow[0], ml0);
        float mn1 = fmaxf(mrow[1], ml1);
        float corr0 = fexp2((mrow[0] - mn0) * L2E);
        float corr1 = fexp2((mrow[1] - mn1) * L2E);
        mrow[0] = mn0; mrow[1] = mn1;

        float rs0 = 0.f, rs1 = 0.f;
        unsigned pp[4][2];
#pragma unroll
        for (int ni = 0; ni < 4; ni++) {
            float p0 = fexp2((sacc[ni][0] - mn0) * L2E);
            float p1 = fexp2((sacc[ni][1] - mn0) * L2E);
            float p2 = fexp2((sacc[ni][2] - mn1) * L2E);
            float p3 = fexp2((sacc[ni][3] - mn1) * L2E);
            rs0 += p0 + p1;
            rs1 += p2 + p3;
            pp[ni][0] = packh(p0, p1);
            pp[ni][1] = packh(p2, p3);
        }
#pragma unroll
        for (int off = 1; off < 4; off <<= 1) {
            rs0 += __shfl_xor_sync(0xffffffffu, rs0, off);
            rs1 += __shfl_xor_sync(0xffffffffu, rs1, off);
        }
        lrow[0] = lrow[0] * corr0 + rs0;
        lrow[1] = lrow[1] * corr1 + rs1;
#pragma unroll
        for (int ni = 0; ni < 8; ni++) {
            oacc[ni][0] *= corr0; oacc[ni][1] *= corr0;
            oacc[ni][2] *= corr1; oacc[ni][3] *= corr1;
        }

#pragma unroll
        for (int s = 0; s < 2; s++) {
            unsigned a0 = pp[2 * s][0], a1 = pp[2 * s][1];
            unsigned a2 = pp[2 * s + 1][0], a3 = pp[2 * s + 1][1];
#pragma unroll
            for (int no = 0; no < 8; no++) {
                unsigned vb0, vb1;
                ldsm2t(vb0, vb1, &Vs[s * 16 + vrow][no * 8]);
                asm volatile("mma.sync.aligned.m16n8k16.row.col.f32.f16.f16.f32 "
                    "{%0,%1,%2,%3}, {%4,%5,%6,%7}, {%8,%9}, {%0,%1,%2,%3};"
                    : "+f"(oacc[no][0]), "+f"(oacc[no][1]), "+f"(oacc[no][2]), "+f"(oacc[no][3])
                    : "r"(a0), "r"(a1), "r"(a2), "r"(a3), "r"(vb0), "r"(vb1));
            }
        }
    }

    float inv0 = 1.0f / lrow[0];
    float inv1 = 1.0f / lrow[1];
    int row0 = b * L_SEQ + q0 + wm + g;
    int row1 = row0 + 8;
#pragma unroll
    for (int ni = 0; ni < 8; ni++) {
        int col = h * 64 + ni * 8 + 2 * t;
        unsigned u0 = packh(oacc[ni][0] * inv0, oacc[ni][1] * inv0);
        unsigned u1 = packh(oacc[ni][2] * inv1, oacc[ni][3] * inv1);
        *reinterpret_cast<unsigned*>(o + (size_t)row0 * DMODEL + col) = u0;
        *reinterpret_cast<unsigned*>(o + (size_t)row1 * DMODEL + col) = u1;
    }
}

// ---------------- SwiGLU -> f16 h ----------------
__global__ void __launch_bounds__(256) swiglu_kernel(const float* __restrict__ u,
                                                     __half* __restrict__ h)
{
    int idx = blockIdx.x * blockDim.x + threadIdx.x;
    int m = idx / (DFF / 4);
    int j = idx % (DFF / 4);
    const float4* ur = reinterpret_cast<const float4*>(u) + (size_t)m * (2 * DFF / 4);
    float4 a = ur[j];
    float4 g = ur[DFF / 4 + j];
    float r0 = a.x * g.x / (1.f + fexp2(-g.x * L2E));
    float r1 = a.y * g.y / (1.f + fexp2(-g.y * L2E));
    float r2 = a.z * g.z / (1.f + fexp2(-g.z * L2E));
    float r3 = a.w * g.w / (1.f + fexp2(-g.w * L2E));
    uint2 r = make_uint2(packh(r0, r1), packh(r2, r3));
    reinterpret_cast<uint2*>(h)[idx] = r;
}

extern "C" void kernel_launch(void* const* d_in, const int* in_sizes, int n_in,
                              void* d_out, int out_size)
{
    const float* x          = (const float*)d_in[0];
    const float* norm_scale = (const float*)d_in[2];
    const float* w_qkv      = (const float*)d_in[3];
    const float* attn_scale = (const float*)d_in[4];
    const float* w_out      = (const float*)d_in[5];
    const float* ff_scale   = (const float*)d_in[6];
    const float* w_up       = (const float*)d_in[7];
    const float* w_down     = (const float*)d_in[8];
    float* out = (float*)d_out;

    float *qkvp, *up;
    __half *xnh, *oh, *hh, *wh;
    cudaGetSymbolAddress((void**)&qkvp, g_qkv);
    cudaGetSymbolAddress((void**)&up, g_u);
    cudaGetSymbolAddress((void**)&xnh, g_xnh);
    cudaGetSymbolAddress((void**)&oh, g_oh);
    cudaGetSymbolAddress((void**)&hh, g_hh);
    cudaGetSymbolAddress((void**)&wh, g_wh);

    cudaFuncSetAttribute(attention_tc_kernel,
                         cudaFuncAttributePreferredSharedMemoryCarveout, 100);

    // 0) weights -> f16 (bit-identical to the per-tile cvt the loader used to do)
    cvt_w_kernel<<<(3 * DMODEL * DMODEL / 4 + 255) / 256, 256>>>(w_qkv, wh + WQKV_OFF, 3 * DMODEL * DMODEL / 4);
    cvt_w_kernel<<<(DMODEL * DMODEL / 4 + 255) / 256, 256>>>(w_out, wh + WOUT_OFF, DMODEL * DMODEL / 4);
    cvt_w_kernel<<<(2 * DFF * DMODEL / 4 + 255) / 256, 256>>>(w_up, wh + WUP_OFF, 2 * DFF * DMODEL / 4);
    cvt_w_kernel<<<(DMODEL * DFF / 4 + 255) / 256, 256>>>(w_down, wh + WDN_OFF, DMODEL * DFF / 4);

    // 1) xn = rmsnorm(x) -> f16
    rmsnorm_kernel<<<MTOT, 256>>>(x, norm_scale, xnh);
    // 2) qkv = xn @ w_qkv^T (f32 out)
    gemm_h_kernel<<<dim3(3 * DMODEL / 128, MTOT / 128), 256>>>(xnh, wh + WQKV_OFF, nullptr, qkvp, 3 * DMODEL, DMODEL);
    // 3) q,k cosine norm
    qknorm_kernel<<<MTOT * 32 / 8, 256>>>(qkvp, attn_scale);
    // 4) attention -> o (f16)
    attention_tc_kernel<<<dim3(L_SEQ / 64, NHEAD, BATCH), 128>>>(qkvp, oh);
    // 5) x1 = o @ w_out^T + x -> d_out (f32)
    gemm_h_kernel<<<dim3(DMODEL / 128, MTOT / 128), 256>>>(oh, wh + WOUT_OFF, x, out, DMODEL, DMODEL);
    // 6) xn = rmsnorm(x1) -> f16
    rmsnorm_kernel<<<MTOT, 256>>>(out, ff_scale, xnh);
    // 7) u = xn @ w_up^T (f32 out)
    gemm_h_kernel<<<dim3(2 * DFF / 128, MTOT / 128), 256>>>(xnh, wh + WUP_OFF, nullptr, up, 2 * DFF, DMODEL);
    // 8) h = a * silu(g) -> f16
    swiglu_kernel<<<MTOT * DFF / 4 / 256, 256>>>(up, hh);
    // 9) out = h @ w_down^T + x1
    gemm_h_kernel<<<dim3(DMODEL / 128, MTOT / 128), 256>>>(hh, wh + WDN_OFF, out, out, DMODEL, DFF);
}

// round 16
// speedup vs baseline: 2.4764x; 1.0478x over previous
#include <cuda_runtime.h>
#include <cuda_fp16.h>
#include <cstdint>

#define L_SEQ 2048
#define BATCH 2
#define DMODEL 1024
#define NHEAD 16
#define DHEAD 64
#define DFF 3072
#define MTOT (BATCH * L_SEQ) /* 4096 */

// -------- scratch (device globals: allocation-free rule) --------
__device__ float g_qkv[MTOT * 3 * DMODEL];           // f32: attention needs full-precision K
__device__ __half g_uh[MTOT * 2 * DFF];              // 48 MB (f16 up-proj output)
__device__ __half g_xnh[MTOT * DMODEL];
__device__ __half g_oh[MTOT * DMODEL];
__device__ __half g_hh[MTOT * DFF];
#define WQKV_OFF 0
#define WOUT_OFF (3 * DMODEL * DMODEL)
#define WUP_OFF  (WOUT_OFF + DMODEL * DMODEL)
#define WDN_OFF  (WUP_OFF + 2 * DFF * DMODEL)
#define WTOT     (WDN_OFF + DMODEL * DFF)
__device__ __half g_wh[WTOT];

__device__ __forceinline__ unsigned packh(float lo, float hi) {
    unsigned r;
    asm("cvt.rn.f16x2.f32 %0, %1, %2;" : "=r"(r) : "f"(hi), "f"(lo));
    return r;
}
__device__ __forceinline__ float h2lo(unsigned u) {
    __half h = __ushort_as_half((unsigned short)(u & 0xFFFF));
    return __half2float(h);
}
__device__ __forceinline__ float h2hi(unsigned u) {
    __half h = __ushort_as_half((unsigned short)(u >> 16));
    return __half2float(h);
}

// FFMA-only 2^y (no MUFU).
__device__ __forceinline__ float fexp2(float y) {
    y = fmaxf(fminf(y, 120.f), -120.f);
    float z = y + 12582912.f;
    int n = __float_as_int(z) - 0x4B400000;
    float f = y - (z - 12582912.f);
    float p = 0.0013333558f;
    p = fmaf(p, f, 0.0096181291f);
    p = fmaf(p, f, 0.0555041087f);
    p = fmaf(p, f, 0.2402265070f);
    p = fmaf(p, f, 0.6931471806f);
    p = fmaf(p, f, 1.0f);
    return __int_as_float((n + 127) << 23) * p;
}
#define L2E 1.4426950408889634f

__device__ __forceinline__ void ldsm4(unsigned& r0, unsigned& r1, unsigned& r2, unsigned& r3,
                                      const void* p)
{
    unsigned a = (unsigned)__cvta_generic_to_shared(p);
    asm volatile("ldmatrix.sync.aligned.m8n8.x4.shared.b16 {%0,%1,%2,%3}, [%4];"
                 : "=r"(r0), "=r"(r1), "=r"(r2), "=r"(r3) : "r"(a));
}
__device__ __forceinline__ void ldsm2(unsigned& r0, unsigned& r1, const void* p)
{
    unsigned a = (unsigned)__cvta_generic_to_shared(p);
    asm volatile("ldmatrix.sync.aligned.m8n8.x2.shared.b16 {%0,%1}, [%2];"
                 : "=r"(r0), "=r"(r1) : "r"(a));
}
__device__ __forceinline__ void ldsm2t(unsigned& r0, unsigned& r1, const void* p)
{
    unsigned a = (unsigned)__cvta_generic_to_shared(p);
    asm volatile("ldmatrix.sync.aligned.m8n8.x2.trans.shared.b16 {%0,%1}, [%2];"
                 : "=r"(r0), "=r"(r1) : "r"(a));
}

// ---------------- weight f32 -> f16 conversion ----------------
__global__ void __launch_bounds__(256) cvt_w_kernel(const float* __restrict__ w,
                                                    __half* __restrict__ wh, int n4)
{
    int idx = blockIdx.x * blockDim.x + threadIdx.x;
    if (idx >= n4) return;
    float4 v = reinterpret_cast<const float4*>(w)[idx];
    uint2 u = make_uint2(packh(v.x, v.y), packh(v.z, v.w));
    reinterpret_cast<uint2*>(wh)[idx] = u;
}

// ---------------- RMSNorm -> f16 out ----------------
__global__ void __launch_bounds__(256) rmsnorm_kernel(const float* __restrict__ x,
                                                      const float* __restrict__ scale,
                                                      __half* __restrict__ out)
{
    int row = blockIdx.x;
    int t = threadIdx.x;
    const float4* xr = reinterpret_cast<const float4*>(x) + (size_t)row * (DMODEL / 4);
    float4 v = xr[t];
    float ss = v.x * v.x + v.y * v.y + v.z * v.z + v.w * v.w;
#pragma unroll
    for (int o = 16; o; o >>= 1) ss += __shfl_xor_sync(0xffffffffu, ss, o);
    __shared__ float ws[8];
    if ((t & 31) == 0) ws[t >> 5] = ss;
    __syncthreads();
    float tot = 0.f;
#pragma unroll
    for (int i = 0; i < 8; i++) tot += ws[i];
    float inv = rsqrtf(tot * (1.0f / DMODEL) + 1e-6f);
    float4 s = reinterpret_cast<const float4*>(scale)[t];
    uint2 r = make_uint2(packh(v.x * s.x * inv, v.y * s.y * inv),
                         packh(v.z * s.z * inv, v.w * s.w * inv));
    (reinterpret_cast<uint2*>(out) + (size_t)row * (DMODEL / 4))[t] = r;
}

// ---------------- FP16 GEMM NT, f16 in, f32 or f16 out ----------------
#define BKH 16
#define LDH 24
template<bool HOUT>
__global__ void __launch_bounds__(256, 2) gemm_h_kernel(const __half* __restrict__ A,
                                                        const __half* __restrict__ B,
                                                        const float* resid,
                                                        void* __restrict__ Cv,
                                                        int N, int K)
{
    __shared__ unsigned short As[2][128][LDH];
    __shared__ unsigned short Bs[2][128][LDH];
    int tid = threadIdx.x;
    int warp = tid >> 5, lane = tid & 31;
    int g = lane >> 2, t = lane & 3;
    int m0 = blockIdx.y * 128, n0 = blockIdx.x * 128;
    int wm = (warp >> 2) * 64;
    int wn = (warp & 3) * 32;

    int arow = wm + (lane & 15);
    int acol = (lane >> 4) * 8;
    int brow = wn + (lane & 7);
    int bcol = ((lane >> 3) & 1) * 8;

    int lm = tid >> 1;
    int lk = (tid & 1) * 8;
    const __half* Ap = A + (size_t)(m0 + lm) * K + lk;
    const __half* Bp = B + (size_t)(n0 + lm) * K + lk;

    float acc[4][4][4] = {};

    {
        uint4 ua = *reinterpret_cast<const uint4*>(Ap);
        uint4 ub = *reinterpret_cast<const uint4*>(Bp);
        *reinterpret_cast<uint4*>(&As[0][lm][lk]) = ua;
        *reinterpret_cast<uint4*>(&Bs[0][lm][lk]) = ub;
    }
    __syncthreads();

    int cur = 0;
    for (int kt = 0; kt < K; kt += BKH) {
        bool has_next = (kt + BKH < K);
        uint4 ua, ub;
        if (has_next) {
            ua = *reinterpret_cast<const uint4*>(Ap + kt + BKH);
            ub = *reinterpret_cast<const uint4*>(Bp + kt + BKH);
        }

        {
            unsigned af[4][4], bf[4][2];
#pragma unroll
            for (int mi = 0; mi < 4; mi++)
                ldsm4(af[mi][0], af[mi][1], af[mi][2], af[mi][3],
                      &As[cur][arow + mi * 16][acol]);
#pragma unroll
            for (int ni = 0; ni < 4; ni++)
                ldsm2(bf[ni][0], bf[ni][1], &Bs[cur][brow + ni * 8][bcol]);
#pragma unroll
            for (int mi = 0; mi < 4; mi++)
#pragma unroll
                for (int ni = 0; ni < 4; ni++) {
                    asm volatile(
                        "mma.sync.aligned.m16n8k16.row.col.f32.f16.f16.f32 "
                        "{%0,%1,%2,%3}, {%4,%5,%6,%7}, {%8,%9}, {%0,%1,%2,%3};"
                        : "+f"(acc[mi][ni][0]), "+f"(acc[mi][ni][1]),
                          "+f"(acc[mi][ni][2]), "+f"(acc[mi][ni][3])
                        : "r"(af[mi][0]), "r"(af[mi][1]), "r"(af[mi][2]), "r"(af[mi][3]),
                          "r"(bf[ni][0]), "r"(bf[ni][1]));
                }
        }

        if (has_next) {
            int nxt = cur ^ 1;
            *reinterpret_cast<uint4*>(&As[nxt][lm][lk]) = ua;
            *reinterpret_cast<uint4*>(&Bs[nxt][lm][lk]) = ub;
            __syncthreads();
            cur = nxt;
        }
    }

#pragma unroll
    for (int mi = 0; mi < 4; mi++) {
#pragma unroll
        for (int ni = 0; ni < 4; ni++) {
            int row0 = m0 + wm + mi * 16 + g;
            int col = n0 + wn + ni * 8 + 2 * t;
            size_t i0 = (size_t)row0 * N + col;
            size_t i1 = (size_t)(row0 + 8) * N + col;
            if (HOUT) {
                __half* C = (__half*)Cv;
                *reinterpret_cast<unsigned*>(C + i0) = packh(acc[mi][ni][0], acc[mi][ni][1]);
                *reinterpret_cast<unsigned*>(C + i1) = packh(acc[mi][ni][2], acc[mi][ni][3]);
            } else {
                float* C = (float*)Cv;
                float2 v01 = make_float2(acc[mi][ni][0], acc[mi][ni][1]);
                float2 v23 = make_float2(acc[mi][ni][2], acc[mi][ni][3]);
                if (resid) {
                    float2 r0 = *reinterpret_cast<const float2*>(resid + i0);
                    float2 r1 = *reinterpret_cast<const float2*>(resid + i1);
                    v01.x += r0.x; v01.y += r0.y;
                    v23.x += r1.x; v23.y += r1.y;
                }
                *reinterpret_cast<float2*>(C + i0) = v01;
                *reinterpret_cast<float2*>(C + i1) = v23;
            }
        }
    }
}

// ---------------- QK cosine norm ----------------
__global__ void __launch_bounds__(256) qknorm_kernel(float* __restrict__ qkv,
                                                     const float* __restrict__ attn_scale)
{
    int warp = blockIdx.x * (blockDim.x >> 5) + (threadIdx.x >> 5);
    int lane = threadIdx.x & 31;
    int m = warp >> 5;
    int rest = warp & 31;
    int part = rest >> 4;
    int h = rest & 15;
    size_t base = (size_t)m * 3072 + part * 1024 + h * 64;
    float2 v = *reinterpret_cast<float2*>(qkv + base + lane * 2);
    float ss = v.x * v.x + v.y * v.y;
#pragma unroll
    for (int o = 16; o; o >>= 1) ss += __shfl_xor_sync(0xffffffffu, ss, o);
    float f = sqrtf(attn_scale[h]) * rsqrtf(ss + 1e-6f);
    v.x *= f;
    v.y *= f;
    *reinterpret_cast<float2*>(qkv + base + lane * 2) = v;
}

// ---------------- Flash attention v7: STATIC-MAX softmax ----------------
// After qknorm, |s| <= attn_scale[h] exactly -> softmax with fixed max = attn_scale[h]
// is mathematically exact. Online-softmax machinery (running max, corrections,
// rescaling) deleted. P packed as 2^8 * exp(s - smax) for fp16 dynamic range;
// the 2^8 cancels in o = sum(p'v)/sum(p').
__global__ void __launch_bounds__(128, 4) attention_tc_kernel(const float* __restrict__ qkv,
                                                              const float* __restrict__ attn_scale,
                                                              __half* __restrict__ o)
{
    __shared__ __align__(16) char qk_raw[64 * 68 * 4];
    float (*Qs)[68] = reinterpret_cast<float(*)[68]>(qk_raw);
    unsigned short (*KsB)[72] = reinterpret_cast<unsigned short(*)[72]>(qk_raw);
    unsigned short (*KsS)[72] = reinterpret_cast<unsigned short(*)[72]>(qk_raw + 32 * 72 * 2);
    __shared__ unsigned short Vs[32][72];

    int tid = threadIdx.x;
    int warp = tid >> 5, lane = tid & 31;
    int g = lane >> 2, t = lane & 3;
    int wm = warp * 16;
    int q0 = blockIdx.x * 64;
    int h = blockIdx.y, b = blockIdx.z;
    const float* qbase = qkv + (size_t)b * L_SEQ * 3072 + h * 64;
    const float* kbase = qbase + 1024;
    const float* vbase = qbase + 2048;
    // exp2 bias: (s - smax)*L2E + 8
    float soft_b = 8.0f - attn_scale[h] * L2E;

    int krow = lane & 7;
    int kcol = ((lane >> 3) & 1) * 8;
    int vrow = lane & 15;

#pragma unroll
    for (int j = 0; j < 8; j++) {
        int idx = tid + 128 * j;
        int r = idx >> 4, seg = idx & 15;
        float4 v = *reinterpret_cast<const float4*>(qbase + (size_t)(q0 + r) * 3072 + seg * 4);
        *reinterpret_cast<float4*>(&Qs[r][seg * 4]) = v;
    }
    __syncthreads();

    unsigned qh[16];
#pragma unroll
    for (int s = 0; s < 4; s++) {
        int c0 = s * 16 + 2 * t;
        qh[s * 4 + 0] = packh(Qs[wm + g][c0], Qs[wm + g][c0 + 1]);
        qh[s * 4 + 1] = packh(Qs[wm + g + 8][c0], Qs[wm + g + 8][c0 + 1]);
        qh[s * 4 + 2] = packh(Qs[wm + g][c0 + 8], Qs[wm + g][c0 + 9]);
        qh[s * 4 + 3] = packh(Qs[wm + g + 8][c0 + 8], Qs[wm + g + 8][c0 + 9]);
    }

    float oacc[8][4] = {};
    float rs0 = 0.f, rs1 = 0.f;   // running sums (reduced once at end)

    for (int kb = 0; kb < L_SEQ / 32; kb++) {
        __syncthreads();
#pragma unroll
        for (int j = 0; j < 4; j++) {
            int idx = tid + 128 * j;
            int r = idx >> 4, seg = idx & 15;
            size_t moff = (size_t)(kb * 32 + r) * 3072 + seg * 4;
            float4 k4 = *reinterpret_cast<const float4*>(kbase + moff);
            uint2 hi = make_uint2(packh(k4.x, k4.y), packh(k4.z, k4.w));
            float l0 = k4.x - h2lo(hi.x);
            float l1 = k4.y - h2hi(hi.x);
            float l2 = k4.z - h2lo(hi.y);
            float l3 = k4.w - h2hi(hi.y);
            uint2 lo = make_uint2(packh(l0, l1), packh(l2, l3));
            *reinterpret_cast<uint2*>(&KsB[r][seg * 4]) = hi;
            *reinterpret_cast<uint2*>(&KsS[r][seg * 4]) = lo;
            float4 v4 = *reinterpret_cast<const float4*>(vbase + moff);
            uint2 uv = make_uint2(packh(v4.x, v4.y), packh(v4.z, v4.w));
            *reinterpret_cast<uint2*>(&Vs[r][seg * 4]) = uv;
        }
        __syncthreads();

        // ---- S = qh·(Kh + Kl) ----
        float sacc[4][4] = {};
#pragma unroll
        for (int s = 0; s < 4; s++) {
            const unsigned* qp = qh + s * 4;
#pragma unroll
            for (int ni = 0; ni < 4; ni++) {
                unsigned kb0, kb1, ks0, ks1;
                ldsm2(kb0, kb1, &KsB[ni * 8 + krow][s * 16 + kcol]);
                ldsm2(ks0, ks1, &KsS[ni * 8 + krow][s * 16 + kcol]);
#define MMA_H(B0,B1) \
                asm volatile("mma.sync.aligned.m16n8k16.row.col.f32.f16.f16.f32 " \
                    "{%0,%1,%2,%3}, {%4,%5,%6,%7}, {%8,%9}, {%0,%1,%2,%3};" \
                    : "+f"(sacc[ni][0]), "+f"(sacc[ni][1]), "+f"(sacc[ni][2]), "+f"(sacc[ni][3]) \
                    : "r"(qp[0]), "r"(qp[1]), "r"(qp[2]), "r"(qp[3]), "r"(B0), "r"(B1))
                MMA_H(kb0, kb1);
                MMA_H(ks0, ks1);
#undef MMA_H
            }
        }

        // ---- static-max softmax: p' = 2^8 * exp(s - smax); no corrections ----
        unsigned pp[4][2];
#pragma unroll
        for (int ni = 0; ni < 4; ni++) {
            float p0 = fexp2(fmaf(sacc[ni][0], L2E, soft_b));
            float p1 = fexp2(fmaf(sacc[ni][1], L2E, soft_b));
            float p2 = fexp2(fmaf(sacc[ni][2], L2E, soft_b));
            float p3 = fexp2(fmaf(sacc[ni][3], L2E, soft_b));
            rs0 += p0 + p1;
            rs1 += p2 + p3;
            pp[ni][0] = packh(p0, p1);
            pp[ni][1] = packh(p2, p3);
        }

        // ---- O += P' V ----
#pragma unroll
        for (int s = 0; s < 2; s++) {
            unsigned a0 = pp[2 * s][0], a1 = pp[2 * s][1];
            unsigned a2 = pp[2 * s + 1][0], a3 = pp[2 * s + 1][1];
#pragma unroll
            for (int no = 0; no < 8; no++) {
                unsigned vb0, vb1;
                ldsm2t(vb0, vb1, &Vs[s * 16 + vrow][no * 8]);
                asm volatile("mma.sync.aligned.m16n8k16.row.col.f32.f16.f16.f32 "
                    "{%0,%1,%2,%3}, {%4,%5,%6,%7}, {%8,%9}, {%0,%1,%2,%3};"
                    : "+f"(oacc[no][0]), "+f"(oacc[no][1]), "+f"(oacc[no][2]), "+f"(oacc[no][3])
                    : "r"(a0), "r"(a1), "r"(a2), "r"(a3), "r"(vb0), "r"(vb1));
            }
        }
    }

    // reduce row sums across the quad once
#pragma unroll
    for (int off = 1; off < 4; off <<= 1) {
        rs0 += __shfl_xor_sync(0xffffffffu, rs0, off);
        rs1 += __shfl_xor_sync(0xffffffffu, rs1, off);
    }
    // P was packed in f16: account for f16 rounding bias is symmetric; divide by f32 sum
    float inv0 = 1.0f / rs0;
    float inv1 = 1.0f / rs1;
    int row0 = b * L_SEQ + q0 + wm + g;
    int row1 = row0 + 8;
#pragma unroll
    for (int ni = 0; ni < 8; ni++) {
        int col = h * 64 + ni * 8 + 2 * t;
        unsigned u0 = packh(oacc[ni][0] * inv0, oacc[ni][1] * inv0);
        unsigned u1 = packh(oacc[ni][2] * inv1, oacc[ni][3] * inv1);
        *reinterpret_cast<unsigned*>(o + (size_t)row0 * DMODEL + col) = u0;
        *reinterpret_cast<unsigned*>(o + (size_t)row1 * DMODEL + col) = u1;
    }
}

// ---------------- SwiGLU: f16 in -> f16 out ----------------
__global__ void __launch_bounds__(256) swiglu_kernel(const __half* __restrict__ u,
                                                     __half* __restrict__ h)
{
    int idx = blockIdx.x * blockDim.x + threadIdx.x;  // over MTOT*DFF/4
    int m = idx / (DFF / 4);
    int j = idx % (DFF / 4);
    const uint2* ur = reinterpret_cast<const uint2*>(u) + (size_t)m * (2 * DFF / 4);
    uint2 ua = ur[j];
    uint2 ug = ur[DFF / 4 + j];
    float a0 = h2lo(ua.x), a1 = h2hi(ua.x), a2 = h2lo(ua.y), a3 = h2hi(ua.y);
    float g0 = h2lo(ug.x), g1 = h2hi(ug.x), g2 = h2lo(ug.y), g3 = h2hi(ug.y);
    float r0 = a0 * g0 / (1.f + fexp2(-g0 * L2E));
    float r1 = a1 * g1 / (1.f + fexp2(-g1 * L2E));
    float r2 = a2 * g2 / (1.f + fexp2(-g2 * L2E));
    float r3 = a3 * g3 / (1.f + fexp2(-g3 * L2E));
    uint2 r = make_uint2(packh(r0, r1), packh(r2, r3));
    reinterpret_cast<uint2*>(h)[idx] = r;
}

extern "C" void kernel_launch(void* const* d_in, const int* in_sizes, int n_in,
                              void* d_out, int out_size)
{
    const float* x          = (const float*)d_in[0];
    const float* norm_scale = (const float*)d_in[2];
    const float* w_qkv      = (const float*)d_in[3];
    const float* attn_scale = (const float*)d_in[4];
    const float* w_out      = (const float*)d_in[5];
    const float* ff_scale   = (const float*)d_in[6];
    const float* w_up       = (const float*)d_in[7];
    const float* w_down     = (const float*)d_in[8];
    float* out = (float*)d_out;

    float *qkvp;
    __half *uh, *xnh, *oh, *hh, *wh;
    cudaGetSymbolAddress((void**)&qkvp, g_qkv);
    cudaGetSymbolAddress((void**)&uh, g_uh);
    cudaGetSymbolAddress((void**)&xnh, g_xnh);
    cudaGetSymbolAddress((void**)&oh, g_oh);
    cudaGetSymbolAddress((void**)&hh, g_hh);
    cudaGetSymbolAddress((void**)&wh, g_wh);

    cudaFuncSetAttribute(attention_tc_kernel,
                         cudaFuncAttributePreferredSharedMemoryCarveout, 100);

    // 0) weights -> f16
    cvt_w_kernel<<<(3 * DMODEL * DMODEL / 4 + 255) / 256, 256>>>(w_qkv, wh + WQKV_OFF, 3 * DMODEL * DMODEL / 4);
    cvt_w_kernel<<<(DMODEL * DMODEL / 4 + 255) / 256, 256>>>(w_out, wh + WOUT_OFF, DMODEL * DMODEL / 4);
    cvt_w_kernel<<<(2 * DFF * DMODEL / 4 + 255) / 256, 256>>>(w_up, wh + WUP_OFF, 2 * DFF * DMODEL / 4);
    cvt_w_kernel<<<(DMODEL * DFF / 4 + 255) / 256, 256>>>(w_down, wh + WDN_OFF, DMODEL * DFF / 4);

    // 1) xn = rmsnorm(x) -> f16
    rmsnorm_kernel<<<MTOT, 256>>>(x, norm_scale, xnh);
    // 2) qkv = xn @ w_qkv^T (f32)
    gemm_h_kernel<false><<<dim3(3 * DMODEL / 128, MTOT / 128), 256>>>(xnh, wh + WQKV_OFF, nullptr, qkvp, 3 * DMODEL, DMODEL);
    // 3) q,k cosine norm
    qknorm_kernel<<<MTOT * 32 / 8, 256>>>(qkvp, attn_scale);
    // 4) attention -> o (f16), static-max softmax
    attention_tc_kernel<<<dim3(L_SEQ / 64, NHEAD, BATCH), 128>>>(qkvp, attn_scale, oh);
    // 5) x1 = o @ w_out^T + x -> d_out (f32)
    gemm_h_kernel<false><<<dim3(DMODEL / 128, MTOT / 128), 256>>>(oh, wh + WOUT_OFF, x, out, DMODEL, DMODEL);
    // 6) xn = rmsnorm(x1) -> f16
    rmsnorm_kernel<<<MTOT, 256>>>(out, ff_scale, xnh);
    // 7) u = xn @ w_up^T -> f16
    gemm_h_kernel<true><<<dim3(2 * DFF / 128, MTOT / 128), 256>>>(xnh, wh + WUP_OFF, nullptr, uh, 2 * DFF, DMODEL);
    // 8) h = a * silu(g) -> f16
    swiglu_kernel<<<MTOT * DFF / 4 / 256, 256>>>(uh, hh);
    // 9) out = h @ w_down^T + x1
    gemm_h_kernel<false><<<dim3(DMODEL / 128, MTOT / 128), 256>>>(hh, wh + WDN_OFF, out, out, DMODEL, DFF);
}

// round 17
// speedup vs baseline: 2.6763x; 1.0807x over previous
#include <cuda_runtime.h>
#include <cuda_fp16.h>
#include <cstdint>

#define L_SEQ 2048
#define BATCH 2
#define DMODEL 1024
#define NHEAD 16
#define DHEAD 64
#define DFF 3072
#define MTOT (BATCH * L_SEQ) /* 4096 */

// -------- scratch (device globals: allocation-free rule) --------
__device__ __half g_qkvh[MTOT * 3 * DMODEL];         // 24 MB (f16 qkv)
__device__ __half g_uh[MTOT * 2 * DFF];
__device__ __half g_xnh[MTOT * DMODEL];
__device__ __half g_oh[MTOT * DMODEL];
__device__ __half g_hh[MTOT * DFF];
#define WQKV_OFF 0
#define WOUT_OFF (3 * DMODEL * DMODEL)
#define WUP_OFF  (WOUT_OFF + DMODEL * DMODEL)
#define WDN_OFF  (WUP_OFF + 2 * DFF * DMODEL)
#define WTOT     (WDN_OFF + DMODEL * DFF)
__device__ __half g_wh[WTOT];

__device__ __forceinline__ unsigned packh(float lo, float hi) {
    unsigned r;
    asm("cvt.rn.f16x2.f32 %0, %1, %2;" : "=r"(r) : "f"(hi), "f"(lo));
    return r;
}
__device__ __forceinline__ float h2lo(unsigned u) {
    __half h = __ushort_as_half((unsigned short)(u & 0xFFFF));
    return __half2float(h);
}
__device__ __forceinline__ float h2hi(unsigned u) {
    __half h = __ushort_as_half((unsigned short)(u >> 16));
    return __half2float(h);
}

// FFMA-only 2^y (no MUFU).
__device__ __forceinline__ float fexp2(float y) {
    y = fmaxf(fminf(y, 120.f), -120.f);
    float z = y + 12582912.f;
    int n = __float_as_int(z) - 0x4B400000;
    float f = y - (z - 12582912.f);
    float p = 0.0013333558f;
    p = fmaf(p, f, 0.0096181291f);
    p = fmaf(p, f, 0.0555041087f);
    p = fmaf(p, f, 0.2402265070f);
    p = fmaf(p, f, 0.6931471806f);
    p = fmaf(p, f, 1.0f);
    return __int_as_float((n + 127) << 23) * p;
}
#define L2E 1.4426950408889634f

__device__ __forceinline__ void ldsm4(unsigned& r0, unsigned& r1, unsigned& r2, unsigned& r3,
                                      const void* p)
{
    unsigned a = (unsigned)__cvta_generic_to_shared(p);
    asm volatile("ldmatrix.sync.aligned.m8n8.x4.shared.b16 {%0,%1,%2,%3}, [%4];"
                 : "=r"(r0), "=r"(r1), "=r"(r2), "=r"(r3) : "r"(a));
}
__device__ __forceinline__ void ldsm2(unsigned& r0, unsigned& r1, const void* p)
{
    unsigned a = (unsigned)__cvta_generic_to_shared(p);
    asm volatile("ldmatrix.sync.aligned.m8n8.x2.shared.b16 {%0,%1}, [%2];"
                 : "=r"(r0), "=r"(r1) : "r"(a));
}
__device__ __forceinline__ void ldsm2t(unsigned& r0, unsigned& r1, const void* p)
{
    unsigned a = (unsigned)__cvta_generic_to_shared(p);
    asm volatile("ldmatrix.sync.aligned.m8n8.x2.trans.shared.b16 {%0,%1}, [%2];"
                 : "=r"(r0), "=r"(r1) : "r"(a));
}

// ---------------- weight f32 -> f16 conversion ----------------
__global__ void __launch_bounds__(256) cvt_w_kernel(const float* __restrict__ w,
                                                    __half* __restrict__ wh, int n4)
{
    int idx = blockIdx.x * blockDim.x + threadIdx.x;
    if (idx >= n4) return;
    float4 v = reinterpret_cast<const float4*>(w)[idx];
    uint2 u = make_uint2(packh(v.x, v.y), packh(v.z, v.w));
    reinterpret_cast<uint2*>(wh)[idx] = u;
}

// ---------------- RMSNorm -> f16 out ----------------
__global__ void __launch_bounds__(256) rmsnorm_kernel(const float* __restrict__ x,
                                                      const float* __restrict__ scale,
                                                      __half* __restrict__ out)
{
    int row = blockIdx.x;
    int t = threadIdx.x;
    const float4* xr = reinterpret_cast<const float4*>(x) + (size_t)row * (DMODEL / 4);
    float4 v = xr[t];
    float ss = v.x * v.x + v.y * v.y + v.z * v.z + v.w * v.w;
#pragma unroll
    for (int o = 16; o; o >>= 1) ss += __shfl_xor_sync(0xffffffffu, ss, o);
    __shared__ float ws[8];
    if ((t & 31) == 0) ws[t >> 5] = ss;
    __syncthreads();
    float tot = 0.f;
#pragma unroll
    for (int i = 0; i < 8; i++) tot += ws[i];
    float inv = rsqrtf(tot * (1.0f / DMODEL) + 1e-6f);
    float4 s = reinterpret_cast<const float4*>(scale)[t];
    uint2 r = make_uint2(packh(v.x * s.x * inv, v.y * s.y * inv),
                         packh(v.z * s.z * inv, v.w * s.w * inv));
    (reinterpret_cast<uint2*>(out) + (size_t)row * (DMODEL / 4))[t] = r;
}

// ---------------- FP16 GEMM NT, f16 in, f32 or f16 out ----------------
#define BKH 16
#define LDH 24
template<bool HOUT>
__global__ void __launch_bounds__(256, 2) gemm_h_kernel(const __half* __restrict__ A,
                                                        const __half* __restrict__ B,
                                                        const float* resid,
                                                        void* __restrict__ Cv,
                                                        int N, int K)
{
    __shared__ unsigned short As[2][128][LDH];
    __shared__ unsigned short Bs[2][128][LDH];
    int tid = threadIdx.x;
    int warp = tid >> 5, lane = tid & 31;
    int g = lane >> 2, t = lane & 3;
    int m0 = blockIdx.y * 128, n0 = blockIdx.x * 128;
    int wm = (warp >> 2) * 64;
    int wn = (warp & 3) * 32;

    int arow = wm + (lane & 15);
    int acol = (lane >> 4) * 8;
    int brow = wn + (lane & 7);
    int bcol = ((lane >> 3) & 1) * 8;

    int lm = tid >> 1;
    int lk = (tid & 1) * 8;
    const __half* Ap = A + (size_t)(m0 + lm) * K + lk;
    const __half* Bp = B + (size_t)(n0 + lm) * K + lk;

    float acc[4][4][4] = {};

    {
        uint4 ua = *reinterpret_cast<const uint4*>(Ap);
        uint4 ub = *reinterpret_cast<const uint4*>(Bp);
        *reinterpret_cast<uint4*>(&As[0][lm][lk]) = ua;
        *reinterpret_cast<uint4*>(&Bs[0][lm][lk]) = ub;
    }
    __syncthreads();

    int cur = 0;
    for (int kt = 0; kt < K; kt += BKH) {
        bool has_next = (kt + BKH < K);
        uint4 ua, ub;
        if (has_next) {
            ua = *reinterpret_cast<const uint4*>(Ap + kt + BKH);
            ub = *reinterpret_cast<const uint4*>(Bp + kt + BKH);
        }

        {
            unsigned af[4][4], bf[4][2];
#pragma unroll
            for (int mi = 0; mi < 4; mi++)
                ldsm4(af[mi][0], af[mi][1], af[mi][2], af[mi][3],
                      &As[cur][arow + mi * 16][acol]);
#pragma unroll
            for (int ni = 0; ni < 4; ni++)
                ldsm2(bf[ni][0], bf[ni][1], &Bs[cur][brow + ni * 8][bcol]);
#pragma unroll
            for (int mi = 0; mi < 4; mi++)
#pragma unroll
                for (int ni = 0; ni < 4; ni++) {
                    asm volatile(
                        "mma.sync.aligned.m16n8k16.row.col.f32.f16.f16.f32 "
                        "{%0,%1,%2,%3}, {%4,%5,%6,%7}, {%8,%9}, {%0,%1,%2,%3};"
                        : "+f"(acc[mi][ni][0]), "+f"(acc[mi][ni][1]),
                          "+f"(acc[mi][ni][2]), "+f"(acc[mi][ni][3])
                        : "r"(af[mi][0]), "r"(af[mi][1]), "r"(af[mi][2]), "r"(af[mi][3]),
                          "r"(bf[ni][0]), "r"(bf[ni][1]));
                }
        }

        if (has_next) {
            int nxt = cur ^ 1;
            *reinterpret_cast<uint4*>(&As[nxt][lm][lk]) = ua;
            *reinterpret_cast<uint4*>(&Bs[nxt][lm][lk]) = ub;
            __syncthreads();
            cur = nxt;
        }
    }

#pragma unroll
    for (int mi = 0; mi < 4; mi++) {
#pragma unroll
        for (int ni = 0; ni < 4; ni++) {
            int row0 = m0 + wm + mi * 16 + g;
            int col = n0 + wn + ni * 8 + 2 * t;
            size_t i0 = (size_t)row0 * N + col;
            size_t i1 = (size_t)(row0 + 8) * N + col;
            if (HOUT) {
                __half* C = (__half*)Cv;
                *reinterpret_cast<unsigned*>(C + i0) = packh(acc[mi][ni][0], acc[mi][ni][1]);
                *reinterpret_cast<unsigned*>(C + i1) = packh(acc[mi][ni][2], acc[mi][ni][3]);
            } else {
                float* C = (float*)Cv;
                float2 v01 = make_float2(acc[mi][ni][0], acc[mi][ni][1]);
                float2 v23 = make_float2(acc[mi][ni][2], acc[mi][ni][3]);
                if (resid) {
                    float2 r0 = *reinterpret_cast<const float2*>(resid + i0);
                    float2 r1 = *reinterpret_cast<const float2*>(resid + i1);
                    v01.x += r0.x; v01.y += r0.y;
                    v23.x += r1.x; v23.y += r1.y;
                }
                *reinterpret_cast<float2*>(C + i0) = v01;
                *reinterpret_cast<float2*>(C + i1) = v23;
            }
        }
    }
}

// ---------------- QK cosine norm: f16 in/out, f32 math ----------------
__global__ void __launch_bounds__(256) qknorm_kernel(__half* __restrict__ qkv,
                                                     const float* __restrict__ attn_scale)
{
    int warp = blockIdx.x * (blockDim.x >> 5) + (threadIdx.x >> 5);
    int lane = threadIdx.x & 31;
    int m = warp >> 5;
    int rest = warp & 31;
    int part = rest >> 4;
    int h = rest & 15;
    size_t base = (size_t)m * 3072 + part * 1024 + h * 64;
    unsigned u = *reinterpret_cast<unsigned*>(qkv + base + lane * 2);
    float f0 = h2lo(u), f1 = h2hi(u);
    float ss = f0 * f0 + f1 * f1;
#pragma unroll
    for (int o = 16; o; o >>= 1) ss += __shfl_xor_sync(0xffffffffu, ss, o);
    float f = sqrtf(attn_scale[h]) * rsqrtf(ss + 1e-6f);
    *reinterpret_cast<unsigned*>(qkv + base + lane * 2) = packh(f0 * f, f1 * f);
}

// ---------------- Flash attention v8: full-fp16 path, single-mma QK ----------------
// q,k,v stored f16; no hi/lo split (measured dilution: logit errors ~1e-3 move
// final rel_err by <1e-5). Static-max softmax (|s| <= attn_scale exactly).
__global__ void __launch_bounds__(128, 4) attention_tc_kernel(const __half* __restrict__ qkv,
                                                              const float* __restrict__ attn_scale,
                                                              __half* __restrict__ o)
{
    // union: Q staging [64][72] halves (9216 B) reused as K [32][72] (4608 B)
    __shared__ __align__(16) unsigned short QK_raw[64][72];
    unsigned short (*Qs)[72] = QK_raw;
    unsigned short (*Ks)[72] = QK_raw;
    __shared__ unsigned short Vs[32][72];

    int tid = threadIdx.x;
    int warp = tid >> 5, lane = tid & 31;
    int g = lane >> 2, t = lane & 3;
    int wm = warp * 16;
    int q0 = blockIdx.x * 64;
    int h = blockIdx.y, b = blockIdx.z;
    const __half* qbase = qkv + (size_t)b * L_SEQ * 3072 + h * 64;
    const __half* kbase = qbase + 1024;
    const __half* vbase = qbase + 2048;
    float soft_b = 8.0f - attn_scale[h] * L2E;   // exp2 bias: s*L2E + soft_b

    int krow = lane & 7;
    int kcol = ((lane >> 3) & 1) * 8;
    int vrow = lane & 15;

    // stage Q tile 64x64 halves (uint2 = 4 halves per chunk; 1024 chunks)
#pragma unroll
    for (int j = 0; j < 8; j++) {
        int idx = tid + 128 * j;
        int r = idx >> 4, seg = idx & 15;
        uint2 v = *reinterpret_cast<const uint2*>(qbase + (size_t)(q0 + r) * 3072 + seg * 4);
        *reinterpret_cast<uint2*>(&Qs[r][seg * 4]) = v;
    }
    __syncthreads();

    // extract Q fragments: packed f16 pair = one 32-bit smem read
    unsigned qh[16];
#pragma unroll
    for (int s = 0; s < 4; s++) {
        int c0 = s * 16 + 2 * t;
        qh[s * 4 + 0] = *reinterpret_cast<unsigned*>(&Qs[wm + g][c0]);
        qh[s * 4 + 1] = *reinterpret_cast<unsigned*>(&Qs[wm + g + 8][c0]);
        qh[s * 4 + 2] = *reinterpret_cast<unsigned*>(&Qs[wm + g][c0 + 8]);
        qh[s * 4 + 3] = *reinterpret_cast<unsigned*>(&Qs[wm + g + 8][c0 + 8]);
    }

    float oacc[8][4] = {};
    float rs0 = 0.f, rs1 = 0.f;

    for (int kb = 0; kb < L_SEQ / 32; kb++) {
        __syncthreads();  // prev PV done + (iter 0) Q extraction done before K overwrites
#pragma unroll
        for (int j = 0; j < 4; j++) {
            int idx = tid + 128 * j;
            int r = idx >> 4, seg = idx & 15;
            size_t moff = (size_t)(kb * 32 + r) * 3072 + seg * 4;
            uint2 kk = *reinterpret_cast<const uint2*>(kbase + moff);
            *reinterpret_cast<uint2*>(&Ks[r][seg * 4]) = kk;
            uint2 vv = *reinterpret_cast<const uint2*>(vbase + moff);
            *reinterpret_cast<uint2*>(&Vs[r][seg * 4]) = vv;
        }
        __syncthreads();

        // ---- S = q·k : single fp16 mma per (s, ni) ----
        float sacc[4][4] = {};
#pragma unroll
        for (int s = 0; s < 4; s++) {
            const unsigned* qp = qh + s * 4;
#pragma unroll
            for (int ni = 0; ni < 4; ni++) {
                unsigned kb0, kb1;
                ldsm2(kb0, kb1, &Ks[ni * 8 + krow][s * 16 + kcol]);
                asm volatile("mma.sync.aligned.m16n8k16.row.col.f32.f16.f16.f32 "
                    "{%0,%1,%2,%3}, {%4,%5,%6,%7}, {%8,%9}, {%0,%1,%2,%3};"
                    : "+f"(sacc[ni][0]), "+f"(sacc[ni][1]), "+f"(sacc[ni][2]), "+f"(sacc[ni][3])
                    : "r"(qp[0]), "r"(qp[1]), "r"(qp[2]), "r"(qp[3]), "r"(kb0), "r"(kb1));
            }
        }

        // ---- static-max softmax: p' = 2^8 * exp(s - smax) ----
        unsigned pp[4][2];
#pragma unroll
        for (int ni = 0; ni < 4; ni++) {
            float p0 = fexp2(fmaf(sacc[ni][0], L2E, soft_b));
            float p1 = fexp2(fmaf(sacc[ni][1], L2E, soft_b));
            float p2 = fexp2(fmaf(sacc[ni][2], L2E, soft_b));
            float p3 = fexp2(fmaf(sacc[ni][3], L2E, soft_b));
            rs0 += p0 + p1;
            rs1 += p2 + p3;
            pp[ni][0] = packh(p0, p1);
            pp[ni][1] = packh(p2, p3);
        }

        // ---- O += P' V ----
#pragma unroll
        for (int s = 0; s < 2; s++) {
            unsigned a0 = pp[2 * s][0], a1 = pp[2 * s][1];
            unsigned a2 = pp[2 * s + 1][0], a3 = pp[2 * s + 1][1];
#pragma unroll
            for (int no = 0; no < 8; no++) {
                unsigned vb0, vb1;
                ldsm2t(vb0, vb1, &Vs[s * 16 + vrow][no * 8]);
                asm volatile("mma.sync.aligned.m16n8k16.row.col.f32.f16.f16.f32 "
                    "{%0,%1,%2,%3}, {%4,%5,%6,%7}, {%8,%9}, {%0,%1,%2,%3};"
                    : "+f"(oacc[no][0]), "+f"(oacc[no][1]), "+f"(oacc[no][2]), "+f"(oacc[no][3])
                    : "r"(a0), "r"(a1), "r"(a2), "r"(a3), "r"(vb0), "r"(vb1));
            }
        }
    }

#pragma unroll
    for (int off = 1; off < 4; off <<= 1) {
        rs0 += __shfl_xor_sync(0xffffffffu, rs0, off);
        rs1 += __shfl_xor_sync(0xffffffffu, rs1, off);
    }
    float inv0 = 1.0f / rs0;
    float inv1 = 1.0f / rs1;
    int row0 = b * L_SEQ + q0 + wm + g;
    int row1 = row0 + 8;
#pragma unroll
    for (int ni = 0; ni < 8; ni++) {
        int col = h * 64 + ni * 8 + 2 * t;
        unsigned u0 = packh(oacc[ni][0] * inv0, oacc[ni][1] * inv0);
        unsigned u1 = packh(oacc[ni][2] * inv1, oacc[ni][3] * inv1);
        *reinterpret_cast<unsigned*>(o + (size_t)row0 * DMODEL + col) = u0;
        *reinterpret_cast<unsigned*>(o + (size_t)row1 * DMODEL + col) = u1;
    }
}

// ---------------- SwiGLU: f16 in -> f16 out ----------------
__global__ void __launch_bounds__(256) swiglu_kernel(const __half* __restrict__ u,
                                                     __half* __restrict__ h)
{
    int idx = blockIdx.x * blockDim.x + threadIdx.x;
    int m = idx / (DFF / 4);
    int j = idx % (DFF / 4);
    const uint2* ur = reinterpret_cast<const uint2*>(u) + (size_t)m * (2 * DFF / 4);
    uint2 ua = ur[j];
    uint2 ug = ur[DFF / 4 + j];
    float a0 = h2lo(ua.x), a1 = h2hi(ua.x), a2 = h2lo(ua.y), a3 = h2hi(ua.y);
    float g0 = h2lo(ug.x), g1 = h2hi(ug.x), g2 = h2lo(ug.y), g3 = h2hi(ug.y);
    float r0 = a0 * g0 / (1.f + fexp2(-g0 * L2E));
    float r1 = a1 * g1 / (1.f + fexp2(-g1 * L2E));
    float r2 = a2 * g2 / (1.f + fexp2(-g2 * L2E));
    float r3 = a3 * g3 / (1.f + fexp2(-g3 * L2E));
    uint2 r = make_uint2(packh(r0, r1), packh(r2, r3));
    reinterpret_cast<uint2*>(h)[idx] = r;
}

extern "C" void kernel_launch(void* const* d_in, const int* in_sizes, int n_in,
                              void* d_out, int out_size)
{
    const float* x          = (const float*)d_in[0];
    const float* norm_scale = (const float*)d_in[2];
    const float* w_qkv      = (const float*)d_in[3];
    const float* attn_scale = (const float*)d_in[4];
    const float* w_out      = (const float*)d_in[5];
    const float* ff_scale   = (const float*)d_in[6];
    const float* w_up       = (const float*)d_in[7];
    const float* w_down     = (const float*)d_in[8];
    float* out = (float*)d_out;

    __half *qkvh, *uh, *xnh, *oh, *hh, *wh;
    cudaGetSymbolAddress((void**)&qkvh, g_qkvh);
    cudaGetSymbolAddress((void**)&uh, g_uh);
    cudaGetSymbolAddress((void**)&xnh, g_xnh);
    cudaGetSymbolAddress((void**)&oh, g_oh);
    cudaGetSymbolAddress((void**)&hh, g_hh);
    cudaGetSymbolAddress((void**)&wh, g_wh);

    cudaFuncSetAttribute(attention_tc_kernel,
                         cudaFuncAttributePreferredSharedMemoryCarveout, 100);

    // 0) weights -> f16
    cvt_w_kernel<<<(3 * DMODEL * DMODEL / 4 + 255) / 256, 256>>>(w_qkv, wh + WQKV_OFF, 3 * DMODEL * DMODEL / 4);
    cvt_w_kernel<<<(DMODEL * DMODEL / 4 + 255) / 256, 256>>>(w_out, wh + WOUT_OFF, DMODEL * DMODEL / 4);
    cvt_w_kernel<<<(2 * DFF * DMODEL / 4 + 255) / 256, 256>>>(w_up, wh + WUP_OFF, 2 * DFF * DMODEL / 4);
    cvt_w_kernel<<<(DMODEL * DFF / 4 + 255) / 256, 256>>>(w_down, wh + WDN_OFF, DMODEL * DFF / 4);

    // 1) xn = rmsnorm(x) -> f16
    rmsnorm_kernel<<<MTOT, 256>>>(x, norm_scale, xnh);
    // 2) qkv = xn @ w_qkv^T -> f16
    gemm_h_kernel<true><<<dim3(3 * DMODEL / 128, MTOT / 128), 256>>>(xnh, wh + WQKV_OFF, nullptr, qkvh, 3 * DMODEL, DMODEL);
    // 3) q,k cosine norm (f16 in/out)
    qknorm_kernel<<<MTOT * 32 / 8, 256>>>(qkvh, attn_scale);
    // 4) attention -> o (f16), full-fp16 datapath
    attention_tc_kernel<<<dim3(L_SEQ / 64, NHEAD, BATCH), 128>>>(qkvh, attn_scale, oh);
    // 5) x1 = o @ w_out^T + x -> d_out (f32)
    gemm_h_kernel<false><<<dim3(DMODEL / 128, MTOT / 128), 256>>>(oh, wh + WOUT_OFF, x, out, DMODEL, DMODEL);
    // 6) xn = rmsnorm(x1) -> f16
    rmsnorm_kernel<<<MTOT, 256>>>(out, ff_scale, xnh);
    // 7) u = xn @ w_up^T -> f16
    gemm_h_kernel<true><<<dim3(2 * DFF / 128, MTOT / 128), 256>>>(xnh, wh + WUP_OFF, nullptr, uh, 2 * DFF, DMODEL);
    // 8) h = a * silu(g) -> f16
    swiglu_kernel<<<MTOT * DFF / 4 / 256, 256>>>(uh, hh);
    // 9) out = h @ w_down^T + x1
    gemm_h_kernel<false><<<dim3(DMODEL / 128, MTOT / 128), 256>>>(hh, wh + WDN_OFF, out, out, DMODEL, DFF);
}